// round 10
// baseline (speedup 1.0000x reference)
#include <cuda_runtime.h>
#include <cuda_bf16.h>
#include <math.h>
#include <stdint.h>

#define NROI 32768
#define DIM  1024
#define NH   8
#define HDIM 128
#define KSEL 2048
#define PCAP 32768

// ======================= PTX helpers (family-compatible) ====================
__device__ __forceinline__ uint32_t smem_u32(const void* p) {
    uint32_t a;
    asm("{ .reg .u64 t; cvta.to.shared.u64 t, %1; cvt.u32.u64 %0, t; }"
        : "=r"(a) : "l"(p));
    return a;
}
__device__ __forceinline__ void ldmatrix_x4(uint32_t* r, uint32_t addr) {
    asm volatile("ldmatrix.sync.aligned.m8n8.x4.shared.b16 {%0,%1,%2,%3}, [%4];"
        : "=r"(r[0]), "=r"(r[1]), "=r"(r[2]), "=r"(r[3]) : "r"(addr));
}
__device__ __forceinline__ void ldmatrix_x2(uint32_t* r, uint32_t addr) {
    asm volatile("ldmatrix.sync.aligned.m8n8.x2.shared.b16 {%0,%1}, [%2];"
        : "=r"(r[0]), "=r"(r[1]) : "r"(addr));
}
__device__ __forceinline__ void mma16816(float* d, const uint32_t* a,
                                         const uint32_t* b) {
    asm volatile(
        "mma.sync.aligned.m16n8k16.row.col.f32.bf16.bf16.f32 "
        "{%0,%1,%2,%3}, {%4,%5,%6,%7}, {%8,%9}, {%0,%1,%2,%3};"
        : "+f"(d[0]), "+f"(d[1]), "+f"(d[2]), "+f"(d[3])
        : "r"(a[0]), "r"(a[1]), "r"(a[2]), "r"(a[3]), "r"(b[0]), "r"(b[1]));
}
__device__ __forceinline__ void cp_async16(uint32_t smem_addr, const void* g) {
    asm volatile("cp.async.cg.shared.global [%0], [%1], 16;"
        :: "r"(smem_addr), "l"(g) : "memory");
}
#define CP_COMMIT() asm volatile("cp.async.commit_group;" ::: "memory")
#define CP_WAIT(n)  asm volatile("cp.async.wait_group %0;" :: "n"(n) : "memory")

// ======================= scratch device globals ==============================
__device__ unsigned int g_keys[NROI];
__device__ int          g_topk[KSEL];
__device__ int          g_eq[NROI];
__device__ int          g_anyvalid;
__device__ int          g_npairs;
__device__ int          g_pairs[PCAP];

__device__ float g_S[KSEL * DIM];
__device__ float g_Q[KSEL * DIM];
__device__ float g_K[KSEL * DIM];
__device__ float g_V[KSEL * DIM];
__device__ float g_AGG[KSEL * DIM];
__device__ float g_FUSED[KSEL * DIM];
__device__ float g_qn[NH * KSEL];   // |q| per head-row
__device__ float g_kn[NH * KSEL];
__device__ float g_pq[NH * KSEL];   // partial norm^2 of qn over first 64 dims
__device__ float g_pk[NH * KSEL];

__device__ __nv_bfloat16 g_Sh[KSEL * DIM];
__device__ __nv_bfloat16 g_Sl[KSEL * DIM];
__device__ __nv_bfloat16 g_Qb[KSEL * DIM];   // NORMALIZED qn (bf16)
__device__ __nv_bfloat16 g_Kb[KSEL * DIM];   // NORMALIZED kn (bf16)
__device__ __nv_bfloat16 g_Wqb[DIM * DIM];
__device__ __nv_bfloat16 g_Wkb[DIM * DIM];
__device__ __nv_bfloat16 g_Wo2h[DIM * DIM];
__device__ __nv_bfloat16 g_Wo2l[DIM * DIM];

// ======================= scores only ========================================
__global__ void k_score(const float* __restrict__ roi,
                        const float* __restrict__ w,
                        const float* __restrict__ b) {
    int gw = (blockIdx.x * blockDim.x + threadIdx.x) >> 5;
    int lane = threadIdx.x & 31;
    if (gw >= NROI) return;
    const float4* r4 = (const float4*)(roi + (size_t)gw * DIM);
    const float4* w4 = (const float4*)w;
    float acc = 0.f;
#pragma unroll
    for (int i = 0; i < 8; i++) {
        float4 rv = r4[lane + i * 32];
        float4 wv = w4[lane + i * 32];
        acc += rv.x * wv.x + rv.y * wv.y + rv.z * wv.z + rv.w * wv.w;
    }
#pragma unroll
    for (int o = 16; o; o >>= 1) acc += __shfl_xor_sync(0xffffffffu, acc, o);
    if (lane == 0) {
        float s = acc + b[0];
        unsigned int kk = __float_as_uint(s);
        kk = (kk & 0x80000000u) ? ~kk : (kk | 0x80000000u);
        g_keys[gw] = kk;
    }
}

// ======================= flat copy roi -> out (side stream) =================
__global__ void k_copy(const float4* __restrict__ roi, float4* __restrict__ out) {
    int i = blockIdx.x * blockDim.x + threadIdx.x;
    out[i] = roi[i];
    out[i + (NROI * DIM / 8)] = roi[i + (NROI * DIM / 8)];
}

// ======================= single-kernel exact top-K ==========================
__global__ void __launch_bounds__(1024) k_topk() {
    extern __shared__ unsigned int sk[];
    __shared__ unsigned int hist[256];
    __shared__ unsigned int sprefix;
    __shared__ int skrem, scnt_gt, scnt_eq;
    int t = threadIdx.x;
    for (int i = t; i < NROI; i += 1024) sk[i] = g_keys[i];
    if (t == 0) {
        sprefix = 0; skrem = KSEL; scnt_gt = 0; scnt_eq = 0;
        g_anyvalid = 0; g_npairs = 0;
    }
    __syncthreads();

    for (int pass = 0; pass < 4; pass++) {
        if (t < 256) hist[t] = 0;
        __syncthreads();
        unsigned int pref = sprefix;
        unsigned int krem = (unsigned int)skrem;
        int shift = 24 - 8 * pass;
        for (int i = t; i < NROI; i += 1024) {
            unsigned int key = sk[i];
            if (pass == 0 || (key >> (shift + 8)) == pref)
                atomicAdd(&hist[(key >> shift) & 0xFFu], 1u);
        }
        __syncthreads();
#pragma unroll
        for (int o = 1; o < 256; o <<= 1) {
            unsigned int v = 0;
            if (t < 256 && t + o < 256) v = hist[t + o];
            __syncthreads();
            if (t < 256) hist[t] += v;
            __syncthreads();
        }
        if (t < 256) {
            unsigned int St = hist[t];
            unsigned int Sn = (t < 255) ? hist[t + 1] : 0u;
            if (St >= krem && Sn < krem) {
                sprefix = (pref << 8) | (unsigned int)t;
                skrem = (int)(krem - Sn);
            }
        }
        __syncthreads();
    }

    unsigned int thresh = sprefix;
    for (int i = t; i < NROI; i += 1024) {
        unsigned int key = sk[i];
        if (key > thresh) { int p = atomicAdd(&scnt_gt, 1); g_topk[p] = i; }
        else if (key == thresh) { int e = atomicAdd(&scnt_eq, 1); g_eq[e] = i; }
    }
    __syncthreads();
    int n = scnt_eq, need = skrem, base = scnt_gt;
    for (int i = t; i < n; i += 1024) {
        int idx = g_eq[i];
        int rank = 0;
        for (int j = 0; j < n; j++) rank += (g_eq[j] < idx);
        if (rank < need) g_topk[base + rank] = idx;
    }
}

// ======================= gather (+ bf16 split of S) =========================
__global__ void k_gather(const float* __restrict__ roi) {
    int r = blockIdx.x;
    int idx = g_topk[r];
    float4 v = ((const float4*)(roi + (size_t)idx * DIM))[threadIdx.x];
    ((float4*)(g_S + (size_t)r * DIM))[threadIdx.x] = v;
    int base = r * DIM + threadIdx.x * 4;
    float e[4] = {v.x, v.y, v.z, v.w};
    __nv_bfloat162 h01, h23, l01, l23;
    h01.x = __float2bfloat16(e[0]); h01.y = __float2bfloat16(e[1]);
    h23.x = __float2bfloat16(e[2]); h23.y = __float2bfloat16(e[3]);
    l01.x = __float2bfloat16(e[0] - __bfloat162float(h01.x));
    l01.y = __float2bfloat16(e[1] - __bfloat162float(h01.y));
    l23.x = __float2bfloat16(e[2] - __bfloat162float(h23.x));
    l23.y = __float2bfloat16(e[3] - __bfloat162float(h23.y));
    *(__nv_bfloat162*)(g_Sh + base) = h01;
    *(__nv_bfloat162*)(g_Sh + base + 2) = h23;
    *(__nv_bfloat162*)(g_Sl + base) = l01;
    *(__nv_bfloat162*)(g_Sl + base + 2) = l23;
}

// ======================= fused weight conversions (vectorized) ==============
__device__ __forceinline__ uint4 pack8(const float* e) {
    __nv_bfloat162 p[4];
#pragma unroll
    for (int c = 0; c < 4; c++) {
        p[c].x = __float2bfloat16(e[2 * c]);
        p[c].y = __float2bfloat16(e[2 * c + 1]);
    }
    uint4 u;
    u.x = *(uint32_t*)&p[0]; u.y = *(uint32_t*)&p[1];
    u.z = *(uint32_t*)&p[2]; u.w = *(uint32_t*)&p[3];
    return u;
}

__global__ void k_cvt_all(const float* __restrict__ wq,
                          const float* __restrict__ wk,
                          const float* __restrict__ wo) {
    int i = 8 * (blockIdx.x * blockDim.x + threadIdx.x);
    int which = blockIdx.y;
    if (which == 0) {
        float e[8];
        *(float4*)&e[0] = *(const float4*)(wq + i);
        *(float4*)&e[4] = *(const float4*)(wq + i + 4);
        *(uint4*)(g_Wqb + i) = pack8(e);
    } else if (which == 1) {
        float e[8];
        *(float4*)&e[0] = *(const float4*)(wk + i);
        *(float4*)&e[4] = *(const float4*)(wk + i + 4);
        *(uint4*)(g_Wkb + i) = pack8(e);
    } else {
        int j = i >> 10, k = i & 1023;
        float e[8];
        *(float4*)&e[0] = *(const float4*)(wo + (size_t)j * 2 * DIM + DIM + k);
        *(float4*)&e[4] = *(const float4*)(wo + (size_t)j * 2 * DIM + DIM + k + 4);
        uint4 h = pack8(e);
        *(uint4*)(g_Wo2h + i) = h;
        float r[8];
        const __nv_bfloat16* hb = (const __nv_bfloat16*)&h;
#pragma unroll
        for (int c = 0; c < 8; c++) r[c] = e[c] - __bfloat162float(hb[c]);
        *(uint4*)(g_Wo2l + i) = pack8(r);
    }
}

// ======================= pipelined bf16 HMMA GEMM ===========================
#define LDSROW 72
#define ASTAGE (128 * LDSROW)
#define STAGEB (2 * ASTAGE)
#define PIPE_SMEM (2 * STAGEB * 2)
#define MASK_SMEM (STAGEB * 2)

__device__ __forceinline__ void warp_mma_block(
    uint32_t a_base, uint32_t b_base, int wr, int wc, int lane,
    float acc[4][4][4]) {
#pragma unroll
    for (int ks = 0; ks < 4; ks++) {
        uint32_t af[4][4], bf[4][2];
#pragma unroll
        for (int mi = 0; mi < 4; mi++) {
            uint32_t addr = a_base +
                ((wr * 64 + mi * 16 + (lane & 15)) * LDSROW + ks * 16 + (lane >> 4) * 8) * 2;
            ldmatrix_x4(af[mi], addr);
        }
#pragma unroll
        for (int ni = 0; ni < 4; ni++) {
            uint32_t addr = b_base +
                ((wc * 32 + ni * 8 + (lane & 7)) * LDSROW + ks * 16 + ((lane >> 3) & 1) * 8) * 2;
            ldmatrix_x2(bf[ni], addr);
        }
#pragma unroll
        for (int mi = 0; mi < 4; mi++)
#pragma unroll
            for (int ni = 0; ni < 4; ni++)
                mma16816(acc[mi][ni], af[mi], bf[ni]);
    }
}

__device__ __forceinline__ void issue_stage(
    const __nv_bfloat16* __restrict__ A, int lda,
    const __nv_bfloat16* __restrict__ B, int ldb,
    uint32_t smem_stage_addr, int tid) {
#pragma unroll
    for (int i = 0; i < 4; i++) {
        int idx = tid + i * 256;
        int row = idx >> 3;
        int cg = idx & 7;
        uint32_t off = (uint32_t)(row * LDSROW + cg * 8) * 2;
        cp_async16(smem_stage_addr + off, A + (size_t)row * lda + cg * 8);
        cp_async16(smem_stage_addr + ASTAGE * 2 + off, B + (size_t)row * ldb + cg * 8);
    }
    CP_COMMIT();
}

// ----- Q/K projections: fp32 out + NORMALIZED bf16 + norms + partial norms --
__global__ void __launch_bounds__(256, 2) k_gemm3(
    const float* __restrict__ bq, const float* __restrict__ bk)
{
    extern __shared__ __nv_bfloat16 smp[];
    __shared__ float snorm[128];
    __shared__ float snorm64[128];
    int tid = threadIdx.x, wid = tid >> 5, lane = tid & 31;
    int bm = blockIdx.y * 128, bn = blockIdx.x * 128;
    int z = blockIdx.z;
    int wr = wid & 1, wc = wid >> 1;
    uint32_t s_base = smem_u32(smp);

    const __nv_bfloat16* B = z ? g_Wkb : g_Wqb;
    const float* bias = z ? bk : bq;
    float* C = z ? g_K : g_Q;
    __nv_bfloat16* Cb = z ? g_Kb : g_Qb;
    float* normOut = z ? g_kn : g_qn;
    float* pOut = z ? g_pk : g_pq;

    float acc[4][4][4];
#pragma unroll
    for (int mi = 0; mi < 4; mi++)
#pragma unroll
        for (int ni = 0; ni < 4; ni++)
#pragma unroll
            for (int c = 0; c < 4; c++) acc[mi][ni][c] = 0.f;

    const int nch = DIM >> 6;

    issue_stage(g_Sh + (size_t)bm * DIM, DIM, B + (size_t)bn * DIM, DIM,
                s_base, tid);

    for (int ch = 0; ch < nch; ch++) {
        int st = ch & 1;
        if (ch + 1 < nch) {
            int kc = (ch + 1) << 6;
            issue_stage(g_Sh + (size_t)bm * DIM + kc, DIM,
                        B + (size_t)bn * DIM + kc, DIM,
                        s_base + (st ^ 1) * STAGEB * 2, tid);
            CP_WAIT(1);
        } else {
            CP_WAIT(0);
        }
        __syncthreads();
        uint32_t a_b = s_base + st * STAGEB * 2;
        warp_mma_block(a_b, a_b + ASTAGE * 2, wr, wc, lane, acc);
        __syncthreads();
    }

    if (tid < 128) { snorm[tid] = 0.f; snorm64[tid] = 0.f; }
    __syncthreads();

    // pass 1: fp32 store + norm accumulation (full and first-64-dims partial)
#pragma unroll
    for (int mi = 0; mi < 4; mi++) {
        int row0 = bm + wr * 64 + mi * 16 + (lane >> 2);
        float ns0 = 0.f, ns1 = 0.f;
#pragma unroll
        for (int ni = 0; ni < 4; ni++) {
            int col = bn + wc * 32 + ni * 8 + (lane & 3) * 2;
            float b0 = bias[col], b1 = bias[col + 1];
            float v00 = acc[mi][ni][0] + b0, v01 = acc[mi][ni][1] + b1;
            float v10 = acc[mi][ni][2] + b0, v11 = acc[mi][ni][3] + b1;
            *(float2*)(C + (size_t)row0 * DIM + col) = make_float2(v00, v01);
            *(float2*)(C + (size_t)(row0 + 8) * DIM + col) = make_float2(v10, v11);
            ns0 += v00 * v00 + v01 * v01;
            ns1 += v10 * v10 + v11 * v11;
        }
        ns0 += __shfl_xor_sync(0xffffffffu, ns0, 1);
        ns0 += __shfl_xor_sync(0xffffffffu, ns0, 2);
        ns1 += __shfl_xor_sync(0xffffffffu, ns1, 1);
        ns1 += __shfl_xor_sync(0xffffffffu, ns1, 2);
        if ((lane & 3) == 0) {
            atomicAdd(&snorm[row0 - bm], ns0);
            atomicAdd(&snorm[row0 - bm + 8], ns1);
            if (wc < 2) {  // cols [bn, bn+64) = first 64 dims of this head
                atomicAdd(&snorm64[row0 - bm], ns0);
                atomicAdd(&snorm64[row0 - bm + 8], ns1);
            }
        }
    }
    __syncthreads();

    // pass 2: normalized bf16 store
#pragma unroll
    for (int mi = 0; mi < 4; mi++) {
        int row0 = bm + wr * 64 + mi * 16 + (lane >> 2);
        float rinv0 = __fdividef(1.f, sqrtf(snorm[row0 - bm]) + 1e-6f);
        float rinv1 = __fdividef(1.f, sqrtf(snorm[row0 - bm + 8]) + 1e-6f);
#pragma unroll
        for (int ni = 0; ni < 4; ni++) {
            int col = bn + wc * 32 + ni * 8 + (lane & 3) * 2;
            float b0 = bias[col], b1 = bias[col + 1];
            float v00 = acc[mi][ni][0] + b0, v01 = acc[mi][ni][1] + b1;
            float v10 = acc[mi][ni][2] + b0, v11 = acc[mi][ni][3] + b1;
            __nv_bfloat162 h0, h1;
            h0.x = __float2bfloat16(v00 * rinv0); h0.y = __float2bfloat16(v01 * rinv0);
            h1.x = __float2bfloat16(v10 * rinv1); h1.y = __float2bfloat16(v11 * rinv1);
            *(__nv_bfloat162*)(Cb + (size_t)row0 * DIM + col) = h0;
            *(__nv_bfloat162*)(Cb + (size_t)(row0 + 8) * DIM + col) = h1;
        }
    }
    if (tid < 128) {
        float ns = snorm[tid];
        float nrm = sqrtf(ns);
        float rinv = __fdividef(1.f, nrm + 1e-6f);
        normOut[blockIdx.x * KSEL + bm + tid] = nrm;
        pOut[blockIdx.x * KSEL + bm + tid] = snorm64[tid] * rinv * rinv;
    }
}

// ----- FUSED projection (3-segment split bf16) with direct output write -----
__global__ void __launch_bounds__(256, 2) k_gemm_fused(
    const float* __restrict__ bo, float* __restrict__ out)
{
    extern __shared__ __nv_bfloat16 smp[];
    int tid = threadIdx.x, wid = tid >> 5, lane = tid & 31;
    int bm = blockIdx.y * 128, bn = blockIdx.x * 128;
    int wr = wid & 1, wc = wid >> 1;
    uint32_t s_base = smem_u32(smp);

    const __nv_bfloat16* Aseg[3] = {g_Sh, g_Sh, g_Sl};
    const __nv_bfloat16* Bseg[3] = {g_Wo2h, g_Wo2l, g_Wo2h};

    float acc[4][4][4];
#pragma unroll
    for (int mi = 0; mi < 4; mi++)
#pragma unroll
        for (int ni = 0; ni < 4; ni++)
#pragma unroll
            for (int c = 0; c < 4; c++) acc[mi][ni][c] = 0.f;

    const int cps = DIM >> 6;
    const int nch = 3 * cps;

    issue_stage(Aseg[0] + (size_t)bm * DIM, DIM, Bseg[0] + (size_t)bn * DIM, DIM,
                s_base, tid);

    for (int ch = 0; ch < nch; ch++) {
        int st = ch & 1;
        if (ch + 1 < nch) {
            int seg = (ch + 1) / cps;
            int kc = ((ch + 1) - seg * cps) << 6;
            issue_stage(Aseg[seg] + (size_t)bm * DIM + kc, DIM,
                        Bseg[seg] + (size_t)bn * DIM + kc, DIM,
                        s_base + (st ^ 1) * STAGEB * 2, tid);
            CP_WAIT(1);
        } else {
            CP_WAIT(0);
        }
        __syncthreads();
        uint32_t a_b = s_base + st * STAGEB * 2;
        warp_mma_block(a_b, a_b + ASTAGE * 2, wr, wc, lane, acc);
        __syncthreads();
    }

#pragma unroll
    for (int mi = 0; mi < 4; mi++) {
        int r0 = bm + wr * 64 + mi * 16 + (lane >> 2);
        int r1 = r0 + 8;
        int t0 = g_topk[r0], t1 = g_topk[r1];
#pragma unroll
        for (int ni = 0; ni < 4; ni++) {
            int col = bn + wc * 32 + ni * 8 + (lane & 3) * 2;
            float b0 = bo[col], b1 = bo[col + 1];
            float v00 = acc[mi][ni][0] + b0, v01 = acc[mi][ni][1] + b1;
            float v10 = acc[mi][ni][2] + b0, v11 = acc[mi][ni][3] + b1;
            *(float2*)(g_FUSED + (size_t)r0 * DIM + col) = make_float2(v00, v01);
            *(float2*)(g_FUSED + (size_t)r1 * DIM + col) = make_float2(v10, v11);
            float2 s0 = *(const float2*)(g_S + (size_t)r0 * DIM + col);
            float2 s1 = *(const float2*)(g_S + (size_t)r1 * DIM + col);
            *(float2*)(out + (size_t)t0 * DIM + col) =
                make_float2(0.5f * (s0.x + v00), 0.5f * (s0.y + v01));
            *(float2*)(out + (size_t)t1 * DIM + col) =
                make_float2(0.5f * (s1.x + v10), 0.5f * (s1.y + v11));
        }
    }
}

// ======================= screened mask: K=64 partial-distance ===============
// partial64 = pq + pk - 2*c  (c = qn.kn over first 64 dims of the head).
// partial64 > 0.25  =>  |qn-kn|^2 > 0.2  =>  sim < 0.9  (rigorous rejection,
// 0.05 margin covers all bf16 error). Survivors -> exact fp32 check.
__global__ void __launch_bounds__(256) k_mask64() {
    extern __shared__ __nv_bfloat16 smp[];
    __shared__ float pkv[128];
    __shared__ float pqv[128];
    int tid = threadIdx.x, wid = tid >> 5, lane = tid & 31;
    int bn = blockIdx.x * 128, bm = blockIdx.y * 128, h = blockIdx.z;
    int wr = wid & 1, wc = wid >> 1;
    uint32_t s_base = smem_u32(smp);

#pragma unroll
    for (int i = 0; i < 4; i++) {
        int idx = tid + i * 256;
        int row = idx >> 3;
        int cg = idx & 7;
        uint32_t off = (uint32_t)(row * LDSROW + cg * 8) * 2;
        cp_async16(s_base + off,
                   g_Qb + (size_t)(bm + row) * DIM + h * HDIM + cg * 8);
        cp_async16(s_base + ASTAGE * 2 + off,
                   g_Kb + (size_t)(bn + row) * DIM + h * HDIM + cg * 8);
    }
    CP_COMMIT();

    if (tid < 128) {
        pqv[tid] = g_pq[h * KSEL + bm + tid];
        pkv[tid] = g_pk[h * KSEL + bn + tid];
    }

    float acc[4][4][4];
#pragma unroll
    for (int mi = 0; mi < 4; mi++)
#pragma unroll
        for (int ni = 0; ni < 4; ni++)
#pragma unroll
            for (int c = 0; c < 4; c++) acc[mi][ni][c] = 0.f;

    CP_WAIT(0);
    __syncthreads();
    warp_mma_block(s_base, s_base + ASTAGE * 2, wr, wc, lane, acc);  // K=64

#pragma unroll
    for (int mi = 0; mi < 4; mi++) {
        int r0l = wr * 64 + mi * 16 + (lane >> 2);
        int r1l = r0l + 8;
        float pq0 = pqv[r0l], pq1 = pqv[r1l];
#pragma unroll
        for (int ni = 0; ni < 4; ni++) {
            int cl = wc * 32 + ni * 8 + (lane & 3) * 2;
            float pk0 = pkv[cl], pk1 = pkv[cl + 1];
            int s00 = (pq0 + pk0 - 2.f * acc[mi][ni][0] <= 0.25f);
            int s01 = (pq0 + pk1 - 2.f * acc[mi][ni][1] <= 0.25f);
            int s10 = (pq1 + pk0 - 2.f * acc[mi][ni][2] <= 0.25f);
            int s11 = (pq1 + pk1 - 2.f * acc[mi][ni][3] <= 0.25f);
            if (__any_sync(0xffffffffu, s00 | s01 | s10 | s11)) {
                if (s00) { int p = atomicAdd(&g_npairs, 1);
                    if (p < PCAP) g_pairs[p] = (h << 22) | ((bm + r0l) << 11) | (bn + cl);
                    else g_anyvalid = 1; }
                if (s01) { int p = atomicAdd(&g_npairs, 1);
                    if (p < PCAP) g_pairs[p] = (h << 22) | ((bm + r0l) << 11) | (bn + cl + 1);
                    else g_anyvalid = 1; }
                if (s10) { int p = atomicAdd(&g_npairs, 1);
                    if (p < PCAP) g_pairs[p] = (h << 22) | ((bm + r1l) << 11) | (bn + cl);
                    else g_anyvalid = 1; }
                if (s11) { int p = atomicAdd(&g_npairs, 1);
                    if (p < PCAP) g_pairs[p] = (h << 22) | ((bm + r1l) << 11) | (bn + cl + 1);
                    else g_anyvalid = 1; }
            }
        }
    }
}

// exact fp32 check for survivor pairs
__global__ void k_maskcheck() {
    int np = g_npairs;
    if (np > PCAP) {
        if (blockIdx.x == 0 && threadIdx.x == 0) g_anyvalid = 1;
        np = PCAP;
    }
    int gw = (blockIdx.x * blockDim.x + threadIdx.x) >> 5;
    int lane = threadIdx.x & 31;
    int nw = (gridDim.x * blockDim.x) >> 5;
    for (int i = gw; i < np; i += nw) {
        int pk = g_pairs[i];
        int h = pk >> 22, qr = (pk >> 11) & 2047, kr = pk & 2047;
        const float4* q = (const float4*)(g_Q + (size_t)qr * DIM + h * HDIM);
        const float4* k = (const float4*)(g_K + (size_t)kr * DIM + h * HDIM);
        float4 qa = q[lane], ka = k[lane];
        float d = qa.x * ka.x + qa.y * ka.y + qa.z * ka.z + qa.w * ka.w;
#pragma unroll
        for (int o = 16; o; o >>= 1) d += __shfl_xor_sync(0xffffffffu, d, o);
        if (lane == 0) {
            float qn = g_qn[h * KSEL + qr] + 1e-6f;
            float kn = g_kn[h * KSEL + kr] + 1e-6f;
            if (d > 0.9f * qn * kn) atomicOr(&g_anyvalid, 1);
        }
    }
}

// ======================= fp32 SIMT GEMM (fallback only) =====================
#define BM 128
#define BN 128
#define BKK 16
#define SPAD 132
__global__ void __launch_bounds__(256) k_gemm(
    const float* __restrict__ A, int lda,
    const float* __restrict__ B, int ldb,
    const float* __restrict__ bias,
    float* __restrict__ C, int ldc,
    int M, int N, int Kd, int acc_flag, int chk)
{
    if (chk && g_anyvalid == 0) return;
    __shared__ float As[BKK * SPAD];
    __shared__ float Bs[BKK * SPAD];
    int tid = threadIdx.x;
    int bm = blockIdx.y * BM, bn = blockIdx.x * BN;
    int row0 = (tid >> 4) * 8, col0 = (tid & 15) * 8;
    float acc[8][8];
#pragma unroll
    for (int i = 0; i < 8; i++)
#pragma unroll
        for (int j = 0; j < 8; j++) acc[i][j] = 0.f;

    for (int k0 = 0; k0 < Kd; k0 += BKK) {
#pragma unroll
        for (int i = 0; i < 2; i++) {
            int f = tid + i * 256;
            int r = f >> 2;
            int kc = (f & 3) * 4;
            float4 av = *(const float4*)(A + (size_t)(bm + r) * lda + k0 + kc);
            As[(kc + 0) * SPAD + r] = av.x;
            As[(kc + 1) * SPAD + r] = av.y;
            As[(kc + 2) * SPAD + r] = av.z;
            As[(kc + 3) * SPAD + r] = av.w;
            float4 bv = *(const float4*)(B + (size_t)(bn + r) * ldb + k0 + kc);
            Bs[(kc + 0) * SPAD + r] = bv.x;
            Bs[(kc + 1) * SPAD + r] = bv.y;
            Bs[(kc + 2) * SPAD + r] = bv.z;
            Bs[(kc + 3) * SPAD + r] = bv.w;
        }
        __syncthreads();
#pragma unroll
        for (int k = 0; k < BKK; k++) {
            float a[8], b[8];
            *(float4*)&a[0] = *(const float4*)&As[k * SPAD + row0];
            *(float4*)&a[4] = *(const float4*)&As[k * SPAD + row0 + 4];
            *(float4*)&b[0] = *(const float4*)&Bs[k * SPAD + col0];
            *(float4*)&b[4] = *(const float4*)&Bs[k * SPAD + col0 + 4];
#pragma unroll
            for (int i = 0; i < 8; i++)
#pragma unroll
                for (int j = 0; j < 8; j++) acc[i][j] += a[i] * b[j];
        }
        __syncthreads();
    }
#pragma unroll
    for (int i = 0; i < 8; i++) {
        float* crow = C + (size_t)(bm + row0 + i) * ldc + bn + col0;
#pragma unroll
        for (int j = 0; j < 8; j++) {
            float v = acc[i][j];
            if (bias) v += bias[bn + col0 + j];
            if (acc_flag) v += crow[j];
            crow[j] = v;
        }
    }
}

// ======================= fp32 flash attention (fallback) ====================
#define AT_RS 68
#define AT_VS 132
#define ATTN_SMEM ((128 * AT_RS * 2 + 64 * AT_VS + 64 * AT_RS) * 4)

__global__ void __launch_bounds__(256) k_attn() {
    if (g_anyvalid == 0) return;
    extern __shared__ float smf[];
    float* QsT = smf;
    float* KsT = QsT + 128 * AT_RS;
    float* Vs  = KsT + 128 * AT_RS;
    float* Ps  = Vs + 64 * AT_VS;

    const int h = blockIdx.y;
    const int q0 = blockIdx.x * 64;
    const int tid = threadIdx.x;
    const int tx = tid & 15;
    const int ty = tid >> 4;
    const float scale = 0.088388347648318447f;

#pragma unroll
    for (int i = 0; i < 8; i++) {
        int f = tid + i * 256;
        int r = f >> 5;
        int dd = (f & 31) * 4;
        float4 v = *(const float4*)(g_Q + (size_t)(q0 + r) * DIM + h * HDIM + dd);
        QsT[(dd + 0) * AT_RS + r] = v.x;
        QsT[(dd + 1) * AT_RS + r] = v.y;
        QsT[(dd + 2) * AT_RS + r] = v.z;
        QsT[(dd + 3) * AT_RS + r] = v.w;
    }

    float qe[4];
#pragma unroll
    for (int i = 0; i < 4; i++)
        qe[i] = g_qn[h * KSEL + q0 + 4 * ty + i] + 1e-6f;

    float m[4], l[4], agg[4][8];
#pragma unroll
    for (int i = 0; i < 4; i++) {
        m[i] = -1e30f; l[i] = 0.f;
#pragma unroll
        for (int c = 0; c < 8; c++) agg[i][c] = 0.f;
    }

    for (int kt = 0; kt < KSEL / 64; kt++) {
        int k0 = kt * 64;
#pragma unroll
        for (int i = 0; i < 8; i++) {
            int f = tid + i * 256;
            int r = f >> 5;
            int dd = (f & 31) * 4;
            float4 v = *(const float4*)(g_K + (size_t)(k0 + r) * DIM + h * HDIM + dd);
            KsT[(dd + 0) * AT_RS + r] = v.x;
            KsT[(dd + 1) * AT_RS + r] = v.y;
            KsT[(dd + 2) * AT_RS + r] = v.z;
            KsT[(dd + 3) * AT_RS + r] = v.w;
            float4 vv = *(const float4*)(g_V + (size_t)(k0 + r) * DIM + h * HDIM + dd);
            *(float4*)&Vs[r * AT_VS + dd] = vv;
        }
        __syncthreads();

        float s[4][4];
#pragma unroll
        for (int i = 0; i < 4; i++)
#pragma unroll
            for (int j = 0; j < 4; j++) s[i][j] = 0.f;

#pragma unroll 4
        for (int dd = 0; dd < 128; dd++) {
            float4 qa = *(const float4*)&QsT[dd * AT_RS + 4 * ty];
            float4 kb = *(const float4*)&KsT[dd * AT_RS + 4 * tx];
            float a[4] = {qa.x, qa.y, qa.z, qa.w};
            float b[4] = {kb.x, kb.y, kb.z, kb.w};
#pragma unroll
            for (int i = 0; i < 4; i++)
#pragma unroll
                for (int j = 0; j < 4; j++) s[i][j] += a[i] * b[j];
        }

        float ke[4];
#pragma unroll
        for (int j = 0; j < 4; j++)
            ke[j] = g_kn[h * KSEL + k0 + 4 * tx + j] + 1e-6f;

        float w[4][4], tmax[4];
        int localany = 0;
#pragma unroll
        for (int i = 0; i < 4; i++) {
            float tm = -1e30f;
#pragma unroll
            for (int j = 0; j < 4; j++) {
                float sim = __fdividef(s[i][j], qe[i] * ke[j]);
                bool valid = sim > 0.9f;
                float lg = valid ? s[i][j] * scale : -1e30f;
                w[i][j] = lg;
                tm = fmaxf(tm, lg);
                localany |= (int)valid;
            }
#pragma unroll
            for (int o = 8; o; o >>= 1)
                tm = fmaxf(tm, __shfl_xor_sync(0xffffffffu, tm, o));
            tmax[i] = tm;
        }

        int anyv = __syncthreads_or(localany);
        if (anyv) {
#pragma unroll
            for (int i = 0; i < 4; i++) {
                float mn = fmaxf(m[i], tmax[i]);
                float f = __expf(m[i] - mn);
                float rs = 0.f;
#pragma unroll
                for (int j = 0; j < 4; j++) {
                    float e = (w[i][j] > -1e29f) ? __expf(w[i][j] - mn) : 0.f;
                    w[i][j] = e;
                    rs += e;
                }
#pragma unroll
                for (int o = 8; o; o >>= 1)
                    rs += __shfl_xor_sync(0xffffffffu, rs, o);
                l[i] = l[i] * f + rs;
                m[i] = mn;
#pragma unroll
                for (int c = 0; c < 8; c++) agg[i][c] *= f;
                *(float4*)&Ps[(4 * ty + i) * AT_RS + 4 * tx] =
                    make_float4(w[i][0], w[i][1], w[i][2], w[i][3]);
            }
            __syncthreads();
#pragma unroll 2
            for (int j = 0; j < 64; j++) {
                float4 v0 = *(const float4*)&Vs[j * AT_VS + 8 * tx];
                float4 v1 = *(const float4*)&Vs[j * AT_VS + 8 * tx + 4];
                float vv[8] = {v0.x, v0.y, v0.z, v0.w, v1.x, v1.y, v1.z, v1.w};
#pragma unroll
                for (int i = 0; i < 4; i++) {
                    float p = Ps[(4 * ty + i) * AT_RS + j];
#pragma unroll
                    for (int c = 0; c < 8; c++) agg[i][c] += p * vv[c];
                }
            }
        }
        __syncthreads();
    }

#pragma unroll
    for (int i = 0; i < 4; i++) {
        float inv = (l[i] > 0.f) ? __fdividef(1.f, l[i]) : 0.f;
        float4 o0, o1;
        o0.x = agg[i][0] * inv; o0.y = agg[i][1] * inv;
        o0.z = agg[i][2] * inv; o0.w = agg[i][3] * inv;
        o1.x = agg[i][4] * inv; o1.y = agg[i][5] * inv;
        o1.z = agg[i][6] * inv; o1.w = agg[i][7] * inv;
        float* dst = g_AGG + (size_t)(q0 + 4 * ty + i) * DIM + h * HDIM + 8 * tx;
        *(float4*)dst = o0;
        *(float4*)(dst + 4) = o1;
    }
}

// ======================= scatter (fallback only) ============================
__global__ void k_scatter(float* __restrict__ out) {
    if (g_anyvalid == 0) return;
    int r = blockIdx.x;
    int idx = g_topk[r];
    const float4* s = (const float4*)(g_S + (size_t)r * DIM);
    const float4* f = (const float4*)(g_FUSED + (size_t)r * DIM);
    float4 sv = s[threadIdx.x], fv = f[threadIdx.x];
    float4 o;
    o.x = 0.5f * (sv.x + fv.x);
    o.y = 0.5f * (sv.y + fv.y);
    o.z = 0.5f * (sv.z + fv.z);
    o.w = 0.5f * (sv.w + fv.w);
    ((float4*)(out + (size_t)idx * DIM))[threadIdx.x] = o;
}

// ======================= launch =============================================
extern "C" void kernel_launch(void* const* d_in, const int* in_sizes, int n_in,
                              void* d_out, int out_size) {
    const float* roi     = (const float*)d_in[0];
    const float* w_score = (const float*)d_in[1];
    const float* b_score = (const float*)d_in[2];
    const float* wq      = (const float*)d_in[3];
    const float* bq      = (const float*)d_in[4];
    const float* wk      = (const float*)d_in[5];
    const float* bk      = (const float*)d_in[6];
    const float* wv      = (const float*)d_in[7];
    const float* bv      = (const float*)d_in[8];
    const float* wo      = (const float*)d_in[9];
    const float* bo      = (const float*)d_in[10];
    float* out = (float*)d_out;

    float *pS, *pAGG, *pFUSED, *pV;
    cudaGetSymbolAddress((void**)&pS, g_S);
    cudaGetSymbolAddress((void**)&pAGG, g_AGG);
    cudaGetSymbolAddress((void**)&pFUSED, g_FUSED);
    cudaGetSymbolAddress((void**)&pV, g_V);

    cudaFuncSetAttribute(k_topk, cudaFuncAttributeMaxDynamicSharedMemorySize,
                         NROI * 4);
    cudaFuncSetAttribute(k_gemm3, cudaFuncAttributeMaxDynamicSharedMemorySize,
                         PIPE_SMEM);
    cudaFuncSetAttribute(k_gemm_fused, cudaFuncAttributeMaxDynamicSharedMemorySize,
                         PIPE_SMEM);
    cudaFuncSetAttribute(k_mask64, cudaFuncAttributeMaxDynamicSharedMemorySize,
                         MASK_SMEM);
    cudaFuncSetAttribute(k_attn, cudaFuncAttributeMaxDynamicSharedMemorySize,
                         ATTN_SMEM);

    cudaStream_t s1;
    cudaStreamCreateWithFlags(&s1, cudaStreamNonBlocking);
    cudaEvent_t ev0, evc, evg, evf;
    cudaEventCreateWithFlags(&ev0, cudaEventDisableTiming);
    cudaEventCreateWithFlags(&evc, cudaEventDisableTiming);
    cudaEventCreateWithFlags(&evg, cudaEventDisableTiming);
    cudaEventCreateWithFlags(&evf, cudaEventDisableTiming);

    // s1: weight cvt (fast, unblocks QK GEMM) then the bulk roi->out copy
    cudaEventRecord(ev0, 0);
    cudaStreamWaitEvent(s1, ev0, 0);
    k_cvt_all<<<dim3(DIM * DIM / 2048, 3), 256, 0, s1>>>(wq, wk, wo);
    cudaEventRecord(evc, s1);
    k_copy<<<NROI * DIM / 8 / 256, 256, 0, s1>>>((const float4*)roi, (float4*)out);

    // s0: score -> topk -> gather
    k_score<<<NROI / 8, 256>>>(roi, w_score, b_score);
    k_topk<<<1, 1024, NROI * 4>>>();
    k_gather<<<KSEL, 256>>>(roi);
    cudaEventRecord(evg, 0);

    // s1: FUSED projection (after cvt+copy on s1 and gather on s0);
    // copy-before-fused stream order makes the out[topk] writes race-free
    cudaStreamWaitEvent(s1, evg, 0);
    k_gemm_fused<<<dim3(DIM / 128, KSEL / 128), 256, PIPE_SMEM, s1>>>(bo, out);
    cudaEventRecord(evf, s1);

    // s0: Q/K projections, screened mask, exact survivor check
    cudaStreamWaitEvent(0, evc, 0);
    k_gemm3<<<dim3(DIM / 128, KSEL / 128, 2), 256, PIPE_SMEM>>>(bq, bk);
    k_mask64<<<dim3(KSEL / 128, KSEL / 128, NH), 256, MASK_SMEM>>>();
    k_maskcheck<<<32, 256>>>();

    // fallback path (guarded; normally no-ops)
    dim3 gg(DIM / BN, KSEL / BM);
    k_gemm<<<gg, 256>>>(pS, DIM, wv, DIM, bv, pV, DIM, KSEL, DIM, DIM, 0, 1);
    k_attn<<<dim3(KSEL / 64, NH), 256, ATTN_SMEM>>>();
    cudaStreamWaitEvent(0, evf, 0);
    k_gemm<<<gg, 256>>>(pAGG, DIM, wo, 2 * DIM, (const float*)nullptr,
                        pFUSED, DIM, KSEL, DIM, DIM, 1, 1);
    k_scatter<<<KSEL, 256>>>(out);
}

// round 11
// speedup vs baseline: 1.0827x; 1.0827x over previous
#include <cuda_runtime.h>
#include <cuda_bf16.h>
#include <math.h>
#include <stdint.h>

#define NROI 32768
#define DIM  1024
#define NH   8
#define HDIM 128
#define KSEL 2048
#define PCAP 32768

// ======================= PTX helpers (family-compatible) ====================
__device__ __forceinline__ uint32_t smem_u32(const void* p) {
    uint32_t a;
    asm("{ .reg .u64 t; cvta.to.shared.u64 t, %1; cvt.u32.u64 %0, t; }"
        : "=r"(a) : "l"(p));
    return a;
}
__device__ __forceinline__ void ldmatrix_x4(uint32_t* r, uint32_t addr) {
    asm volatile("ldmatrix.sync.aligned.m8n8.x4.shared.b16 {%0,%1,%2,%3}, [%4];"
        : "=r"(r[0]), "=r"(r[1]), "=r"(r[2]), "=r"(r[3]) : "r"(addr));
}
__device__ __forceinline__ void ldmatrix_x2(uint32_t* r, uint32_t addr) {
    asm volatile("ldmatrix.sync.aligned.m8n8.x2.shared.b16 {%0,%1}, [%2];"
        : "=r"(r[0]), "=r"(r[1]) : "r"(addr));
}
__device__ __forceinline__ void mma16816(float* d, const uint32_t* a,
                                         const uint32_t* b) {
    asm volatile(
        "mma.sync.aligned.m16n8k16.row.col.f32.bf16.bf16.f32 "
        "{%0,%1,%2,%3}, {%4,%5,%6,%7}, {%8,%9}, {%0,%1,%2,%3};"
        : "+f"(d[0]), "+f"(d[1]), "+f"(d[2]), "+f"(d[3])
        : "r"(a[0]), "r"(a[1]), "r"(a[2]), "r"(a[3]), "r"(b[0]), "r"(b[1]));
}
__device__ __forceinline__ void cp_async16(uint32_t smem_addr, const void* g) {
    asm volatile("cp.async.cg.shared.global [%0], [%1], 16;"
        :: "r"(smem_addr), "l"(g) : "memory");
}
#define CP_COMMIT() asm volatile("cp.async.commit_group;" ::: "memory")
#define CP_WAIT(n)  asm volatile("cp.async.wait_group %0;" :: "n"(n) : "memory")

// ======================= scratch device globals ==============================
__device__ unsigned int g_keys[NROI];
__device__ int          g_topk[KSEL];
__device__ int          g_eq[NROI];
__device__ int          g_anyvalid;
__device__ int          g_npairs;
__device__ int          g_pairs[PCAP];

__device__ float g_S[KSEL * DIM];
__device__ float g_Q[KSEL * DIM];
__device__ float g_K[KSEL * DIM];
__device__ float g_V[KSEL * DIM];
__device__ float g_AGG[KSEL * DIM];
__device__ float g_FUSED[KSEL * DIM];
__device__ float g_qn[NH * KSEL];   // |q| per head-row
__device__ float g_kn[NH * KSEL];
__device__ float g_pq[NH * KSEL];   // partial norm^2 of qn over first 64 dims
__device__ float g_pk[NH * KSEL];

__device__ __nv_bfloat16 g_Sh[KSEL * DIM];
__device__ __nv_bfloat16 g_Sl[KSEL * DIM];
__device__ __nv_bfloat16 g_Qb[KSEL * DIM];   // NORMALIZED qn (bf16)
__device__ __nv_bfloat16 g_Kb[KSEL * DIM];   // NORMALIZED kn (bf16)
__device__ __nv_bfloat16 g_Wqb[DIM * DIM];
__device__ __nv_bfloat16 g_Wkb[DIM * DIM];
__device__ __nv_bfloat16 g_Wo2h[DIM * DIM];
__device__ __nv_bfloat16 g_Wo2l[DIM * DIM];

// ======================= scores + full copy (one pass) ======================
__global__ void k_score_copy(const float* __restrict__ roi,
                             const float* __restrict__ w,
                             const float* __restrict__ b,
                             float* __restrict__ out) {
    int gw = (blockIdx.x * blockDim.x + threadIdx.x) >> 5;
    int lane = threadIdx.x & 31;
    if (gw >= NROI) return;
    const float4* r4 = (const float4*)(roi + (size_t)gw * DIM);
    const float4* w4 = (const float4*)w;
    float4* o4 = (float4*)(out + (size_t)gw * DIM);
    float acc = 0.f;
#pragma unroll
    for (int i = 0; i < 8; i++) {
        float4 rv = r4[lane + i * 32];
        float4 wv = w4[lane + i * 32];
        o4[lane + i * 32] = rv;
        acc += rv.x * wv.x + rv.y * wv.y + rv.z * wv.z + rv.w * wv.w;
    }
#pragma unroll
    for (int o = 16; o; o >>= 1) acc += __shfl_xor_sync(0xffffffffu, acc, o);
    if (lane == 0) {
        float s = acc + b[0];
        unsigned int kk = __float_as_uint(s);
        kk = (kk & 0x80000000u) ? ~kk : (kk | 0x80000000u);
        g_keys[gw] = kk;
    }
}

// ======================= single-kernel exact top-K ==========================
__global__ void __launch_bounds__(1024) k_topk() {
    extern __shared__ unsigned int sk[];
    __shared__ unsigned int hist[256];
    __shared__ unsigned int sprefix;
    __shared__ int skrem, scnt_gt, scnt_eq;
    int t = threadIdx.x;
    for (int i = t; i < NROI; i += 1024) sk[i] = g_keys[i];
    if (t == 0) {
        sprefix = 0; skrem = KSEL; scnt_gt = 0; scnt_eq = 0;
        g_anyvalid = 0; g_npairs = 0;
    }
    __syncthreads();

    for (int pass = 0; pass < 4; pass++) {
        if (t < 256) hist[t] = 0;
        __syncthreads();
        unsigned int pref = sprefix;
        unsigned int krem = (unsigned int)skrem;
        int shift = 24 - 8 * pass;
        for (int i = t; i < NROI; i += 1024) {
            unsigned int key = sk[i];
            if (pass == 0 || (key >> (shift + 8)) == pref)
                atomicAdd(&hist[(key >> shift) & 0xFFu], 1u);
        }
        __syncthreads();
#pragma unroll
        for (int o = 1; o < 256; o <<= 1) {
            unsigned int v = 0;
            if (t < 256 && t + o < 256) v = hist[t + o];
            __syncthreads();
            if (t < 256) hist[t] += v;
            __syncthreads();
        }
        if (t < 256) {
            unsigned int St = hist[t];
            unsigned int Sn = (t < 255) ? hist[t + 1] : 0u;
            if (St >= krem && Sn < krem) {
                sprefix = (pref << 8) | (unsigned int)t;
                skrem = (int)(krem - Sn);
            }
        }
        __syncthreads();
    }

    unsigned int thresh = sprefix;
    for (int i = t; i < NROI; i += 1024) {
        unsigned int key = sk[i];
        if (key > thresh) { int p = atomicAdd(&scnt_gt, 1); g_topk[p] = i; }
        else if (key == thresh) { int e = atomicAdd(&scnt_eq, 1); g_eq[e] = i; }
    }
    __syncthreads();
    int n = scnt_eq, need = skrem, base = scnt_gt;
    for (int i = t; i < n; i += 1024) {
        int idx = g_eq[i];
        int rank = 0;
        for (int j = 0; j < n; j++) rank += (g_eq[j] < idx);
        if (rank < need) g_topk[base + rank] = idx;
    }
}

// ======================= gather (+ bf16 split of S) =========================
__global__ void k_gather(const float* __restrict__ roi) {
    int r = blockIdx.x;
    int idx = g_topk[r];
    float4 v = ((const float4*)(roi + (size_t)idx * DIM))[threadIdx.x];
    ((float4*)(g_S + (size_t)r * DIM))[threadIdx.x] = v;
    int base = r * DIM + threadIdx.x * 4;
    float e[4] = {v.x, v.y, v.z, v.w};
    __nv_bfloat162 h01, h23, l01, l23;
    h01.x = __float2bfloat16(e[0]); h01.y = __float2bfloat16(e[1]);
    h23.x = __float2bfloat16(e[2]); h23.y = __float2bfloat16(e[3]);
    l01.x = __float2bfloat16(e[0] - __bfloat162float(h01.x));
    l01.y = __float2bfloat16(e[1] - __bfloat162float(h01.y));
    l23.x = __float2bfloat16(e[2] - __bfloat162float(h23.x));
    l23.y = __float2bfloat16(e[3] - __bfloat162float(h23.y));
    *(__nv_bfloat162*)(g_Sh + base) = h01;
    *(__nv_bfloat162*)(g_Sh + base + 2) = h23;
    *(__nv_bfloat162*)(g_Sl + base) = l01;
    *(__nv_bfloat162*)(g_Sl + base + 2) = l23;
}

// ======================= fused weight conversions (vectorized) ==============
__device__ __forceinline__ uint4 pack8(const float* e) {
    __nv_bfloat162 p[4];
#pragma unroll
    for (int c = 0; c < 4; c++) {
        p[c].x = __float2bfloat16(e[2 * c]);
        p[c].y = __float2bfloat16(e[2 * c + 1]);
    }
    uint4 u;
    u.x = *(uint32_t*)&p[0]; u.y = *(uint32_t*)&p[1];
    u.z = *(uint32_t*)&p[2]; u.w = *(uint32_t*)&p[3];
    return u;
}

__global__ void k_cvt_all(const float* __restrict__ wq,
                          const float* __restrict__ wk,
                          const float* __restrict__ wo) {
    int i = 8 * (blockIdx.x * blockDim.x + threadIdx.x);
    int which = blockIdx.y;
    if (which == 0) {
        float e[8];
        *(float4*)&e[0] = *(const float4*)(wq + i);
        *(float4*)&e[4] = *(const float4*)(wq + i + 4);
        *(uint4*)(g_Wqb + i) = pack8(e);
    } else if (which == 1) {
        float e[8];
        *(float4*)&e[0] = *(const float4*)(wk + i);
        *(float4*)&e[4] = *(const float4*)(wk + i + 4);
        *(uint4*)(g_Wkb + i) = pack8(e);
    } else {
        int j = i >> 10, k = i & 1023;
        float e[8];
        *(float4*)&e[0] = *(const float4*)(wo + (size_t)j * 2 * DIM + DIM + k);
        *(float4*)&e[4] = *(const float4*)(wo + (size_t)j * 2 * DIM + DIM + k + 4);
        uint4 h = pack8(e);
        *(uint4*)(g_Wo2h + i) = h;
        float r[8];
        const __nv_bfloat16* hb = (const __nv_bfloat16*)&h;
#pragma unroll
        for (int c = 0; c < 8; c++) r[c] = e[c] - __bfloat162float(hb[c]);
        *(uint4*)(g_Wo2l + i) = pack8(r);
    }
}

// ======================= pipelined bf16 HMMA GEMM ===========================
#define LDSROW 72
#define ASTAGE (128 * LDSROW)
#define STAGEB (2 * ASTAGE)
#define PIPE_SMEM (2 * STAGEB * 2)
#define MASK_SMEM (STAGEB * 2)

__device__ __forceinline__ void warp_mma_block(
    uint32_t a_base, uint32_t b_base, int wr, int wc, int lane,
    float acc[4][4][4]) {
#pragma unroll
    for (int ks = 0; ks < 4; ks++) {
        uint32_t af[4][4], bf[4][2];
#pragma unroll
        for (int mi = 0; mi < 4; mi++) {
            uint32_t addr = a_base +
                ((wr * 64 + mi * 16 + (lane & 15)) * LDSROW + ks * 16 + (lane >> 4) * 8) * 2;
            ldmatrix_x4(af[mi], addr);
        }
#pragma unroll
        for (int ni = 0; ni < 4; ni++) {
            uint32_t addr = b_base +
                ((wc * 32 + ni * 8 + (lane & 7)) * LDSROW + ks * 16 + ((lane >> 3) & 1) * 8) * 2;
            ldmatrix_x2(bf[ni], addr);
        }
#pragma unroll
        for (int mi = 0; mi < 4; mi++)
#pragma unroll
            for (int ni = 0; ni < 4; ni++)
                mma16816(acc[mi][ni], af[mi], bf[ni]);
    }
}

__device__ __forceinline__ void issue_stage(
    const __nv_bfloat16* __restrict__ A, int lda,
    const __nv_bfloat16* __restrict__ B, int ldb,
    uint32_t smem_stage_addr, int tid) {
#pragma unroll
    for (int i = 0; i < 4; i++) {
        int idx = tid + i * 256;
        int row = idx >> 3;
        int cg = idx & 7;
        uint32_t off = (uint32_t)(row * LDSROW + cg * 8) * 2;
        cp_async16(smem_stage_addr + off, A + (size_t)row * lda + cg * 8);
        cp_async16(smem_stage_addr + ASTAGE * 2 + off, B + (size_t)row * ldb + cg * 8);
    }
    CP_COMMIT();
}

// ----- Q/K projections: fp32 out + NORMALIZED bf16 + norms + partial norms --
__global__ void __launch_bounds__(256, 2) k_gemm3(
    const float* __restrict__ bq, const float* __restrict__ bk)
{
    extern __shared__ __nv_bfloat16 smp[];
    __shared__ float snorm[128];
    __shared__ float snorm64[128];
    int tid = threadIdx.x, wid = tid >> 5, lane = tid & 31;
    int bm = blockIdx.y * 128, bn = blockIdx.x * 128;
    int z = blockIdx.z;
    int wr = wid & 1, wc = wid >> 1;
    uint32_t s_base = smem_u32(smp);

    const __nv_bfloat16* B = z ? g_Wkb : g_Wqb;
    const float* bias = z ? bk : bq;
    float* C = z ? g_K : g_Q;
    __nv_bfloat16* Cb = z ? g_Kb : g_Qb;
    float* normOut = z ? g_kn : g_qn;
    float* pOut = z ? g_pk : g_pq;

    float acc[4][4][4];
#pragma unroll
    for (int mi = 0; mi < 4; mi++)
#pragma unroll
        for (int ni = 0; ni < 4; ni++)
#pragma unroll
            for (int c = 0; c < 4; c++) acc[mi][ni][c] = 0.f;

    const int nch = DIM >> 6;

    issue_stage(g_Sh + (size_t)bm * DIM, DIM, B + (size_t)bn * DIM, DIM,
                s_base, tid);

    for (int ch = 0; ch < nch; ch++) {
        int st = ch & 1;
        if (ch + 1 < nch) {
            int kc = (ch + 1) << 6;
            issue_stage(g_Sh + (size_t)bm * DIM + kc, DIM,
                        B + (size_t)bn * DIM + kc, DIM,
                        s_base + (st ^ 1) * STAGEB * 2, tid);
            CP_WAIT(1);
        } else {
            CP_WAIT(0);
        }
        __syncthreads();
        uint32_t a_b = s_base + st * STAGEB * 2;
        warp_mma_block(a_b, a_b + ASTAGE * 2, wr, wc, lane, acc);
        __syncthreads();
    }

    if (tid < 128) { snorm[tid] = 0.f; snorm64[tid] = 0.f; }
    __syncthreads();

    // pass 1: fp32 store + norm accumulation (full and first-64-dims partial)
#pragma unroll
    for (int mi = 0; mi < 4; mi++) {
        int row0 = bm + wr * 64 + mi * 16 + (lane >> 2);
        float ns0 = 0.f, ns1 = 0.f;
#pragma unroll
        for (int ni = 0; ni < 4; ni++) {
            int col = bn + wc * 32 + ni * 8 + (lane & 3) * 2;
            float b0 = bias[col], b1 = bias[col + 1];
            float v00 = acc[mi][ni][0] + b0, v01 = acc[mi][ni][1] + b1;
            float v10 = acc[mi][ni][2] + b0, v11 = acc[mi][ni][3] + b1;
            *(float2*)(C + (size_t)row0 * DIM + col) = make_float2(v00, v01);
            *(float2*)(C + (size_t)(row0 + 8) * DIM + col) = make_float2(v10, v11);
            ns0 += v00 * v00 + v01 * v01;
            ns1 += v10 * v10 + v11 * v11;
        }
        ns0 += __shfl_xor_sync(0xffffffffu, ns0, 1);
        ns0 += __shfl_xor_sync(0xffffffffu, ns0, 2);
        ns1 += __shfl_xor_sync(0xffffffffu, ns1, 1);
        ns1 += __shfl_xor_sync(0xffffffffu, ns1, 2);
        if ((lane & 3) == 0) {
            atomicAdd(&snorm[row0 - bm], ns0);
            atomicAdd(&snorm[row0 - bm + 8], ns1);
            if (wc < 2) {  // cols [bn, bn+64) = first 64 dims of this head
                atomicAdd(&snorm64[row0 - bm], ns0);
                atomicAdd(&snorm64[row0 - bm + 8], ns1);
            }
        }
    }
    __syncthreads();

    // pass 2: normalized bf16 store
#pragma unroll
    for (int mi = 0; mi < 4; mi++) {
        int row0 = bm + wr * 64 + mi * 16 + (lane >> 2);
        float rinv0 = __fdividef(1.f, sqrtf(snorm[row0 - bm]) + 1e-6f);
        float rinv1 = __fdividef(1.f, sqrtf(snorm[row0 - bm + 8]) + 1e-6f);
#pragma unroll
        for (int ni = 0; ni < 4; ni++) {
            int col = bn + wc * 32 + ni * 8 + (lane & 3) * 2;
            float b0 = bias[col], b1 = bias[col + 1];
            float v00 = acc[mi][ni][0] + b0, v01 = acc[mi][ni][1] + b1;
            float v10 = acc[mi][ni][2] + b0, v11 = acc[mi][ni][3] + b1;
            __nv_bfloat162 h0, h1;
            h0.x = __float2bfloat16(v00 * rinv0); h0.y = __float2bfloat16(v01 * rinv0);
            h1.x = __float2bfloat16(v10 * rinv1); h1.y = __float2bfloat16(v11 * rinv1);
            *(__nv_bfloat162*)(Cb + (size_t)row0 * DIM + col) = h0;
            *(__nv_bfloat162*)(Cb + (size_t)(row0 + 8) * DIM + col) = h1;
        }
    }
    if (tid < 128) {
        float ns = snorm[tid];
        float nrm = sqrtf(ns);
        float rinv = __fdividef(1.f, nrm + 1e-6f);
        normOut[blockIdx.x * KSEL + bm + tid] = nrm;
        pOut[blockIdx.x * KSEL + bm + tid] = snorm64[tid] * rinv * rinv;
    }
}

// ----- FUSED projection (3-segment split bf16) with direct output write -----
__global__ void __launch_bounds__(256, 2) k_gemm_fused(
    const float* __restrict__ bo, float* __restrict__ out)
{
    extern __shared__ __nv_bfloat16 smp[];
    int tid = threadIdx.x, wid = tid >> 5, lane = tid & 31;
    int bm = blockIdx.y * 128, bn = blockIdx.x * 128;
    int wr = wid & 1, wc = wid >> 1;
    uint32_t s_base = smem_u32(smp);

    const __nv_bfloat16* Aseg[3] = {g_Sh, g_Sh, g_Sl};
    const __nv_bfloat16* Bseg[3] = {g_Wo2h, g_Wo2l, g_Wo2h};

    float acc[4][4][4];
#pragma unroll
    for (int mi = 0; mi < 4; mi++)
#pragma unroll
        for (int ni = 0; ni < 4; ni++)
#pragma unroll
            for (int c = 0; c < 4; c++) acc[mi][ni][c] = 0.f;

    const int cps = DIM >> 6;
    const int nch = 3 * cps;

    issue_stage(Aseg[0] + (size_t)bm * DIM, DIM, Bseg[0] + (size_t)bn * DIM, DIM,
                s_base, tid);

    for (int ch = 0; ch < nch; ch++) {
        int st = ch & 1;
        if (ch + 1 < nch) {
            int seg = (ch + 1) / cps;
            int kc = ((ch + 1) - seg * cps) << 6;
            issue_stage(Aseg[seg] + (size_t)bm * DIM + kc, DIM,
                        Bseg[seg] + (size_t)bn * DIM + kc, DIM,
                        s_base + (st ^ 1) * STAGEB * 2, tid);
            CP_WAIT(1);
        } else {
            CP_WAIT(0);
        }
        __syncthreads();
        uint32_t a_b = s_base + st * STAGEB * 2;
        warp_mma_block(a_b, a_b + ASTAGE * 2, wr, wc, lane, acc);
        __syncthreads();
    }

#pragma unroll
    for (int mi = 0; mi < 4; mi++) {
        int r0 = bm + wr * 64 + mi * 16 + (lane >> 2);
        int r1 = r0 + 8;
        int t0 = g_topk[r0], t1 = g_topk[r1];
#pragma unroll
        for (int ni = 0; ni < 4; ni++) {
            int col = bn + wc * 32 + ni * 8 + (lane & 3) * 2;
            float b0 = bo[col], b1 = bo[col + 1];
            float v00 = acc[mi][ni][0] + b0, v01 = acc[mi][ni][1] + b1;
            float v10 = acc[mi][ni][2] + b0, v11 = acc[mi][ni][3] + b1;
            *(float2*)(g_FUSED + (size_t)r0 * DIM + col) = make_float2(v00, v01);
            *(float2*)(g_FUSED + (size_t)r1 * DIM + col) = make_float2(v10, v11);
            float2 s0 = *(const float2*)(g_S + (size_t)r0 * DIM + col);
            float2 s1 = *(const float2*)(g_S + (size_t)r1 * DIM + col);
            *(float2*)(out + (size_t)t0 * DIM + col) =
                make_float2(0.5f * (s0.x + v00), 0.5f * (s0.y + v01));
            *(float2*)(out + (size_t)t1 * DIM + col) =
                make_float2(0.5f * (s1.x + v10), 0.5f * (s1.y + v11));
        }
    }
}

// ======================= screened mask: K=64 partial-distance ===============
// partial64 = pq + pk - 2*c  (c = qn.kn over first 64 dims of the head).
// partial64 > 0.25  =>  |qn-kn|^2 > 0.2  =>  sim < 0.9  (rigorous rejection;
// 0.05 margin covers all bf16 error). Survivors -> exact fp32 check.
__global__ void __launch_bounds__(256) k_mask64() {
    extern __shared__ __nv_bfloat16 smp[];
    __shared__ float pkv[128];
    __shared__ float pqv[128];
    int tid = threadIdx.x, wid = tid >> 5, lane = tid & 31;
    int bn = blockIdx.x * 128, bm = blockIdx.y * 128, h = blockIdx.z;
    int wr = wid & 1, wc = wid >> 1;
    uint32_t s_base = smem_u32(smp);

#pragma unroll
    for (int i = 0; i < 4; i++) {
        int idx = tid + i * 256;
        int row = idx >> 3;
        int cg = idx & 7;
        uint32_t off = (uint32_t)(row * LDSROW + cg * 8) * 2;
        cp_async16(s_base + off,
                   g_Qb + (size_t)(bm + row) * DIM + h * HDIM + cg * 8);
        cp_async16(s_base + ASTAGE * 2 + off,
                   g_Kb + (size_t)(bn + row) * DIM + h * HDIM + cg * 8);
    }
    CP_COMMIT();

    if (tid < 128) {
        pqv[tid] = g_pq[h * KSEL + bm + tid];
        pkv[tid] = g_pk[h * KSEL + bn + tid];
    }

    float acc[4][4][4];
#pragma unroll
    for (int mi = 0; mi < 4; mi++)
#pragma unroll
        for (int ni = 0; ni < 4; ni++)
#pragma unroll
            for (int c = 0; c < 4; c++) acc[mi][ni][c] = 0.f;

    CP_WAIT(0);
    __syncthreads();
    warp_mma_block(s_base, s_base + ASTAGE * 2, wr, wc, lane, acc);  // K=64

#pragma unroll
    for (int mi = 0; mi < 4; mi++) {
        int r0l = wr * 64 + mi * 16 + (lane >> 2);
        int r1l = r0l + 8;
        float pq0 = pqv[r0l], pq1 = pqv[r1l];
#pragma unroll
        for (int ni = 0; ni < 4; ni++) {
            int cl = wc * 32 + ni * 8 + (lane & 3) * 2;
            float pk0 = pkv[cl], pk1 = pkv[cl + 1];
            int s00 = (pq0 + pk0 - 2.f * acc[mi][ni][0] <= 0.25f);
            int s01 = (pq0 + pk1 - 2.f * acc[mi][ni][1] <= 0.25f);
            int s10 = (pq1 + pk0 - 2.f * acc[mi][ni][2] <= 0.25f);
            int s11 = (pq1 + pk1 - 2.f * acc[mi][ni][3] <= 0.25f);
            if (__any_sync(0xffffffffu, s00 | s01 | s10 | s11)) {
                if (s00) { int p = atomicAdd(&g_npairs, 1);
                    if (p < PCAP) g_pairs[p] = (h << 22) | ((bm + r0l) << 11) | (bn + cl);
                    else g_anyvalid = 1; }
                if (s01) { int p = atomicAdd(&g_npairs, 1);
                    if (p < PCAP) g_pairs[p] = (h << 22) | ((bm + r0l) << 11) | (bn + cl + 1);
                    else g_anyvalid = 1; }
                if (s10) { int p = atomicAdd(&g_npairs, 1);
                    if (p < PCAP) g_pairs[p] = (h << 22) | ((bm + r1l) << 11) | (bn + cl);
                    else g_anyvalid = 1; }
                if (s11) { int p = atomicAdd(&g_npairs, 1);
                    if (p < PCAP) g_pairs[p] = (h << 22) | ((bm + r1l) << 11) | (bn + cl + 1);
                    else g_anyvalid = 1; }
            }
        }
    }
}

// exact fp32 check for survivor pairs
__global__ void k_maskcheck() {
    int np = g_npairs;
    if (np > PCAP) {
        if (blockIdx.x == 0 && threadIdx.x == 0) g_anyvalid = 1;
        np = PCAP;
    }
    int gw = (blockIdx.x * blockDim.x + threadIdx.x) >> 5;
    int lane = threadIdx.x & 31;
    int nw = (gridDim.x * blockDim.x) >> 5;
    for (int i = gw; i < np; i += nw) {
        int pk = g_pairs[i];
        int h = pk >> 22, qr = (pk >> 11) & 2047, kr = pk & 2047;
        const float4* q = (const float4*)(g_Q + (size_t)qr * DIM + h * HDIM);
        const float4* k = (const float4*)(g_K + (size_t)kr * DIM + h * HDIM);
        float4 qa = q[lane], ka = k[lane];
        float d = qa.x * ka.x + qa.y * ka.y + qa.z * ka.z + qa.w * ka.w;
#pragma unroll
        for (int o = 16; o; o >>= 1) d += __shfl_xor_sync(0xffffffffu, d, o);
        if (lane == 0) {
            float qn = g_qn[h * KSEL + qr] + 1e-6f;
            float kn = g_kn[h * KSEL + kr] + 1e-6f;
            if (d > 0.9f * qn * kn) atomicOr(&g_anyvalid, 1);
        }
    }
}

// ======================= fp32 SIMT GEMM (fallback only) =====================
#define BM 128
#define BN 128
#define BKK 16
#define SPAD 132
__global__ void __launch_bounds__(256) k_gemm(
    const float* __restrict__ A, int lda,
    const float* __restrict__ B, int ldb,
    const float* __restrict__ bias,
    float* __restrict__ C, int ldc,
    int M, int N, int Kd, int acc_flag, int chk)
{
    if (chk && g_anyvalid == 0) return;
    __shared__ float As[BKK * SPAD];
    __shared__ float Bs[BKK * SPAD];
    int tid = threadIdx.x;
    int bm = blockIdx.y * BM, bn = blockIdx.x * BN;
    int row0 = (tid >> 4) * 8, col0 = (tid & 15) * 8;
    float acc[8][8];
#pragma unroll
    for (int i = 0; i < 8; i++)
#pragma unroll
        for (int j = 0; j < 8; j++) acc[i][j] = 0.f;

    for (int k0 = 0; k0 < Kd; k0 += BKK) {
#pragma unroll
        for (int i = 0; i < 2; i++) {
            int f = tid + i * 256;
            int r = f >> 2;
            int kc = (f & 3) * 4;
            float4 av = *(const float4*)(A + (size_t)(bm + r) * lda + k0 + kc);
            As[(kc + 0) * SPAD + r] = av.x;
            As[(kc + 1) * SPAD + r] = av.y;
            As[(kc + 2) * SPAD + r] = av.z;
            As[(kc + 3) * SPAD + r] = av.w;
            float4 bv = *(const float4*)(B + (size_t)(bn + r) * ldb + k0 + kc);
            Bs[(kc + 0) * SPAD + r] = bv.x;
            Bs[(kc + 1) * SPAD + r] = bv.y;
            Bs[(kc + 2) * SPAD + r] = bv.z;
            Bs[(kc + 3) * SPAD + r] = bv.w;
        }
        __syncthreads();
#pragma unroll
        for (int k = 0; k < BKK; k++) {
            float a[8], b[8];
            *(float4*)&a[0] = *(const float4*)&As[k * SPAD + row0];
            *(float4*)&a[4] = *(const float4*)&As[k * SPAD + row0 + 4];
            *(float4*)&b[0] = *(const float4*)&Bs[k * SPAD + col0];
            *(float4*)&b[4] = *(const float4*)&Bs[k * SPAD + col0 + 4];
#pragma unroll
            for (int i = 0; i < 8; i++)
#pragma unroll
                for (int j = 0; j < 8; j++) acc[i][j] += a[i] * b[j];
        }
        __syncthreads();
    }
#pragma unroll
    for (int i = 0; i < 8; i++) {
        float* crow = C + (size_t)(bm + row0 + i) * ldc + bn + col0;
#pragma unroll
        for (int j = 0; j < 8; j++) {
            float v = acc[i][j];
            if (bias) v += bias[bn + col0 + j];
            if (acc_flag) v += crow[j];
            crow[j] = v;
        }
    }
}

// ======================= fp32 flash attention (fallback) ====================
#define AT_RS 68
#define AT_VS 132
#define ATTN_SMEM ((128 * AT_RS * 2 + 64 * AT_VS + 64 * AT_RS) * 4)

__global__ void __launch_bounds__(256) k_attn() {
    if (g_anyvalid == 0) return;
    extern __shared__ float smf[];
    float* QsT = smf;
    float* KsT = QsT + 128 * AT_RS;
    float* Vs  = KsT + 128 * AT_RS;
    float* Ps  = Vs + 64 * AT_VS;

    const int h = blockIdx.y;
    const int q0 = blockIdx.x * 64;
    const int tid = threadIdx.x;
    const int tx = tid & 15;
    const int ty = tid >> 4;
    const float scale = 0.088388347648318447f;

#pragma unroll
    for (int i = 0; i < 8; i++) {
        int f = tid + i * 256;
        int r = f >> 5;
        int dd = (f & 31) * 4;
        float4 v = *(const float4*)(g_Q + (size_t)(q0 + r) * DIM + h * HDIM + dd);
        QsT[(dd + 0) * AT_RS + r] = v.x;
        QsT[(dd + 1) * AT_RS + r] = v.y;
        QsT[(dd + 2) * AT_RS + r] = v.z;
        QsT[(dd + 3) * AT_RS + r] = v.w;
    }

    float qe[4];
#pragma unroll
    for (int i = 0; i < 4; i++)
        qe[i] = g_qn[h * KSEL + q0 + 4 * ty + i] + 1e-6f;

    float m[4], l[4], agg[4][8];
#pragma unroll
    for (int i = 0; i < 4; i++) {
        m[i] = -1e30f; l[i] = 0.f;
#pragma unroll
        for (int c = 0; c < 8; c++) agg[i][c] = 0.f;
    }

    for (int kt = 0; kt < KSEL / 64; kt++) {
        int k0 = kt * 64;
#pragma unroll
        for (int i = 0; i < 8; i++) {
            int f = tid + i * 256;
            int r = f >> 5;
            int dd = (f & 31) * 4;
            float4 v = *(const float4*)(g_K + (size_t)(k0 + r) * DIM + h * HDIM + dd);
            KsT[(dd + 0) * AT_RS + r] = v.x;
            KsT[(dd + 1) * AT_RS + r] = v.y;
            KsT[(dd + 2) * AT_RS + r] = v.z;
            KsT[(dd + 3) * AT_RS + r] = v.w;
            float4 vv = *(const float4*)(g_V + (size_t)(k0 + r) * DIM + h * HDIM + dd);
            *(float4*)&Vs[r * AT_VS + dd] = vv;
        }
        __syncthreads();

        float s[4][4];
#pragma unroll
        for (int i = 0; i < 4; i++)
#pragma unroll
            for (int j = 0; j < 4; j++) s[i][j] = 0.f;

#pragma unroll 4
        for (int dd = 0; dd < 128; dd++) {
            float4 qa = *(const float4*)&QsT[dd * AT_RS + 4 * ty];
            float4 kb = *(const float4*)&KsT[dd * AT_RS + 4 * tx];
            float a[4] = {qa.x, qa.y, qa.z, qa.w};
            float b[4] = {kb.x, kb.y, kb.z, kb.w};
#pragma unroll
            for (int i = 0; i < 4; i++)
#pragma unroll
                for (int j = 0; j < 4; j++) s[i][j] += a[i] * b[j];
        }

        float ke[4];
#pragma unroll
        for (int j = 0; j < 4; j++)
            ke[j] = g_kn[h * KSEL + k0 + 4 * tx + j] + 1e-6f;

        float w[4][4], tmax[4];
        int localany = 0;
#pragma unroll
        for (int i = 0; i < 4; i++) {
            float tm = -1e30f;
#pragma unroll
            for (int j = 0; j < 4; j++) {
                float sim = __fdividef(s[i][j], qe[i] * ke[j]);
                bool valid = sim > 0.9f;
                float lg = valid ? s[i][j] * scale : -1e30f;
                w[i][j] = lg;
                tm = fmaxf(tm, lg);
                localany |= (int)valid;
            }
#pragma unroll
            for (int o = 8; o; o >>= 1)
                tm = fmaxf(tm, __shfl_xor_sync(0xffffffffu, tm, o));
            tmax[i] = tm;
        }

        int anyv = __syncthreads_or(localany);
        if (anyv) {
#pragma unroll
            for (int i = 0; i < 4; i++) {
                float mn = fmaxf(m[i], tmax[i]);
                float f = __expf(m[i] - mn);
                float rs = 0.f;
#pragma unroll
                for (int j = 0; j < 4; j++) {
                    float e = (w[i][j] > -1e29f) ? __expf(w[i][j] - mn) : 0.f;
                    w[i][j] = e;
                    rs += e;
                }
#pragma unroll
                for (int o = 8; o; o >>= 1)
                    rs += __shfl_xor_sync(0xffffffffu, rs, o);
                l[i] = l[i] * f + rs;
                m[i] = mn;
#pragma unroll
                for (int c = 0; c < 8; c++) agg[i][c] *= f;
                *(float4*)&Ps[(4 * ty + i) * AT_RS + 4 * tx] =
                    make_float4(w[i][0], w[i][1], w[i][2], w[i][3]);
            }
            __syncthreads();
#pragma unroll 2
            for (int j = 0; j < 64; j++) {
                float4 v0 = *(const float4*)&Vs[j * AT_VS + 8 * tx];
                float4 v1 = *(const float4*)&Vs[j * AT_VS + 8 * tx + 4];
                float vv[8] = {v0.x, v0.y, v0.z, v0.w, v1.x, v1.y, v1.z, v1.w};
#pragma unroll
                for (int i = 0; i < 4; i++) {
                    float p = Ps[(4 * ty + i) * AT_RS + j];
#pragma unroll
                    for (int c = 0; c < 8; c++) agg[i][c] += p * vv[c];
                }
            }
        }
        __syncthreads();
    }

#pragma unroll
    for (int i = 0; i < 4; i++) {
        float inv = (l[i] > 0.f) ? __fdividef(1.f, l[i]) : 0.f;
        float4 o0, o1;
        o0.x = agg[i][0] * inv; o0.y = agg[i][1] * inv;
        o0.z = agg[i][2] * inv; o0.w = agg[i][3] * inv;
        o1.x = agg[i][4] * inv; o1.y = agg[i][5] * inv;
        o1.z = agg[i][6] * inv; o1.w = agg[i][7] * inv;
        float* dst = g_AGG + (size_t)(q0 + 4 * ty + i) * DIM + h * HDIM + 8 * tx;
        *(float4*)dst = o0;
        *(float4*)(dst + 4) = o1;
    }
}

// ======================= scatter (fallback only) ============================
__global__ void k_scatter(float* __restrict__ out) {
    if (g_anyvalid == 0) return;
    int r = blockIdx.x;
    int idx = g_topk[r];
    const float4* s = (const float4*)(g_S + (size_t)r * DIM);
    const float4* f = (const float4*)(g_FUSED + (size_t)r * DIM);
    float4 sv = s[threadIdx.x], fv = f[threadIdx.x];
    float4 o;
    o.x = 0.5f * (sv.x + fv.x);
    o.y = 0.5f * (sv.y + fv.y);
    o.z = 0.5f * (sv.z + fv.z);
    o.w = 0.5f * (sv.w + fv.w);
    ((float4*)(out + (size_t)idx * DIM))[threadIdx.x] = o;
}

// ======================= launch =============================================
extern "C" void kernel_launch(void* const* d_in, const int* in_sizes, int n_in,
                              void* d_out, int out_size) {
    const float* roi     = (const float*)d_in[0];
    const float* w_score = (const float*)d_in[1];
    const float* b_score = (const float*)d_in[2];
    const float* wq      = (const float*)d_in[3];
    const float* bq      = (const float*)d_in[4];
    const float* wk      = (const float*)d_in[5];
    const float* bk      = (const float*)d_in[6];
    const float* wv      = (const float*)d_in[7];
    const float* bv      = (const float*)d_in[8];
    const float* wo      = (const float*)d_in[9];
    const float* bo      = (const float*)d_in[10];
    float* out = (float*)d_out;

    float *pS, *pAGG, *pFUSED, *pV;
    cudaGetSymbolAddress((void**)&pS, g_S);
    cudaGetSymbolAddress((void**)&pAGG, g_AGG);
    cudaGetSymbolAddress((void**)&pFUSED, g_FUSED);
    cudaGetSymbolAddress((void**)&pV, g_V);

    cudaFuncSetAttribute(k_topk, cudaFuncAttributeMaxDynamicSharedMemorySize,
                         NROI * 4);
    cudaFuncSetAttribute(k_gemm3, cudaFuncAttributeMaxDynamicSharedMemorySize,
                         PIPE_SMEM);
    cudaFuncSetAttribute(k_gemm_fused, cudaFuncAttributeMaxDynamicSharedMemorySize,
                         PIPE_SMEM);
    cudaFuncSetAttribute(k_mask64, cudaFuncAttributeMaxDynamicSharedMemorySize,
                         MASK_SMEM);
    cudaFuncSetAttribute(k_attn, cudaFuncAttributeMaxDynamicSharedMemorySize,
                         ATTN_SMEM);

    cudaStream_t s1;
    cudaStreamCreateWithFlags(&s1, cudaStreamNonBlocking);
    cudaEvent_t ev0, evc, evg, evf;
    cudaEventCreateWithFlags(&ev0, cudaEventDisableTiming);
    cudaEventCreateWithFlags(&evc, cudaEventDisableTiming);
    cudaEventCreateWithFlags(&evg, cudaEventDisableTiming);
    cudaEventCreateWithFlags(&evf, cudaEventDisableTiming);

    // s1: weight cvt overlapping the score+copy pass on s0
    cudaEventRecord(ev0, 0);
    cudaStreamWaitEvent(s1, ev0, 0);
    k_cvt_all<<<dim3(DIM * DIM / 2048, 3), 256, 0, s1>>>(wq, wk, wo);
    cudaEventRecord(evc, s1);

    // s0: fused score+copy (single pass over roi) -> topk -> gather
    k_score_copy<<<NROI / 8, 256>>>(roi, w_score, b_score, out);
    k_topk<<<1, 1024, NROI * 4>>>();
    k_gather<<<KSEL, 256>>>(roi);
    cudaEventRecord(evg, 0);

    // s1: FUSED projection (after cvt on s1, gather+copy on s0 via evg)
    cudaStreamWaitEvent(s1, evg, 0);
    k_gemm_fused<<<dim3(DIM / 128, KSEL / 128), 256, PIPE_SMEM, s1>>>(bo, out);
    cudaEventRecord(evf, s1);

    // s0: Q/K projections, screened mask, exact survivor check
    cudaStreamWaitEvent(0, evc, 0);
    k_gemm3<<<dim3(DIM / 128, KSEL / 128, 2), 256, PIPE_SMEM>>>(bq, bk);
    k_mask64<<<dim3(KSEL / 128, KSEL / 128, NH), 256, MASK_SMEM>>>();
    k_maskcheck<<<32, 256>>>();

    // fallback path (guarded; normally no-ops)
    dim3 gg(DIM / BN, KSEL / BM);
    k_gemm<<<gg, 256>>>(pS, DIM, wv, DIM, bv, pV, DIM, KSEL, DIM, DIM, 0, 1);
    k_attn<<<dim3(KSEL / 64, NH), 256, ATTN_SMEM>>>();
    cudaStreamWaitEvent(0, evf, 0);
    k_gemm<<<gg, 256>>>(pAGG, DIM, wo, 2 * DIM, (const float*)nullptr,
                        pFUSED, DIM, KSEL, DIM, DIM, 1, 1);
    k_scatter<<<KSEL, 256>>>(out);
}

// round 12
// speedup vs baseline: 1.1089x; 1.0243x over previous
#include <cuda_runtime.h>
#include <cuda_bf16.h>
#include <math.h>
#include <stdint.h>

#define NROI 32768
#define DIM  1024
#define NH   8
#define HDIM 128
#define KSEL 2048
#define PCAP 32768

// ======================= PTX helpers (family-compatible) ====================
__device__ __forceinline__ uint32_t smem_u32(const void* p) {
    uint32_t a;
    asm("{ .reg .u64 t; cvta.to.shared.u64 t, %1; cvt.u32.u64 %0, t; }"
        : "=r"(a) : "l"(p));
    return a;
}
__device__ __forceinline__ void ldmatrix_x4(uint32_t* r, uint32_t addr) {
    asm volatile("ldmatrix.sync.aligned.m8n8.x4.shared.b16 {%0,%1,%2,%3}, [%4];"
        : "=r"(r[0]), "=r"(r[1]), "=r"(r[2]), "=r"(r[3]) : "r"(addr));
}
__device__ __forceinline__ void ldmatrix_x2(uint32_t* r, uint32_t addr) {
    asm volatile("ldmatrix.sync.aligned.m8n8.x2.shared.b16 {%0,%1}, [%2];"
        : "=r"(r[0]), "=r"(r[1]) : "r"(addr));
}
__device__ __forceinline__ void mma16816(float* d, const uint32_t* a,
                                         const uint32_t* b) {
    asm volatile(
        "mma.sync.aligned.m16n8k16.row.col.f32.bf16.bf16.f32 "
        "{%0,%1,%2,%3}, {%4,%5,%6,%7}, {%8,%9}, {%0,%1,%2,%3};"
        : "+f"(d[0]), "+f"(d[1]), "+f"(d[2]), "+f"(d[3])
        : "r"(a[0]), "r"(a[1]), "r"(a[2]), "r"(a[3]), "r"(b[0]), "r"(b[1]));
}
__device__ __forceinline__ void cp_async16(uint32_t smem_addr, const void* g) {
    asm volatile("cp.async.cg.shared.global [%0], [%1], 16;"
        :: "r"(smem_addr), "l"(g) : "memory");
}
#define CP_COMMIT() asm volatile("cp.async.commit_group;" ::: "memory")
#define CP_WAIT(n)  asm volatile("cp.async.wait_group %0;" :: "n"(n) : "memory")

// ======================= scratch device globals ==============================
__device__ unsigned int g_keys[NROI];
__device__ unsigned int g_hist[256];   // pass-0 histogram (zeroed by k_topk)
__device__ int          g_topk[KSEL];
__device__ int          g_eq[NROI];
__device__ int          g_anyvalid;
__device__ int          g_npairs;
__device__ int          g_pairs[PCAP];

__device__ float g_S[KSEL * DIM];
__device__ float g_Q[KSEL * DIM];
__device__ float g_K[KSEL * DIM];
__device__ float g_V[KSEL * DIM];
__device__ float g_AGG[KSEL * DIM];
__device__ float g_FUSED[KSEL * DIM];
__device__ float g_qn[NH * KSEL];   // |q| per head-row
__device__ float g_kn[NH * KSEL];
__device__ float g_pq[NH * KSEL];   // partial norm^2 of qn over first 64 dims
__device__ float g_pk[NH * KSEL];

__device__ __nv_bfloat16 g_Sh[KSEL * DIM];
__device__ __nv_bfloat16 g_Sl[KSEL * DIM];
__device__ __nv_bfloat16 g_Qb[KSEL * DIM];   // NORMALIZED qn (bf16)
__device__ __nv_bfloat16 g_Kb[KSEL * DIM];   // NORMALIZED kn (bf16)
__device__ __nv_bfloat16 g_Wqb[DIM * DIM];
__device__ __nv_bfloat16 g_Wkb[DIM * DIM];
__device__ __nv_bfloat16 g_Wo2h[DIM * DIM];
__device__ __nv_bfloat16 g_Wo2l[DIM * DIM];

// ======================= scores + full copy + pass-0 hist ===================
__global__ void k_score_copy(const float* __restrict__ roi,
                             const float* __restrict__ w,
                             const float* __restrict__ b,
                             float* __restrict__ out) {
    __shared__ unsigned int sh[256];
    sh[threadIdx.x] = 0;
    __syncthreads();
    int gw = (blockIdx.x * blockDim.x + threadIdx.x) >> 5;
    int lane = threadIdx.x & 31;
    const float4* r4 = (const float4*)(roi + (size_t)gw * DIM);
    const float4* w4 = (const float4*)w;
    float4* o4 = (float4*)(out + (size_t)gw * DIM);
    float acc = 0.f;
#pragma unroll
    for (int i = 0; i < 8; i++) {
        float4 rv = r4[lane + i * 32];
        float4 wv = w4[lane + i * 32];
        o4[lane + i * 32] = rv;
        acc += rv.x * wv.x + rv.y * wv.y + rv.z * wv.z + rv.w * wv.w;
    }
#pragma unroll
    for (int o = 16; o; o >>= 1) acc += __shfl_xor_sync(0xffffffffu, acc, o);
    if (lane == 0) {
        float s = acc + b[0];
        unsigned int kk = __float_as_uint(s);
        kk = (kk & 0x80000000u) ? ~kk : (kk | 0x80000000u);
        g_keys[gw] = kk;
        atomicAdd(&sh[kk >> 24], 1u);
    }
    __syncthreads();
    unsigned int c = sh[threadIdx.x];
    if (c) atomicAdd(&g_hist[threadIdx.x], c);
}

// ======================= single-kernel exact top-K (register keys) ==========
__global__ void __launch_bounds__(1024) k_topk() {
    __shared__ unsigned int hist[256];
    __shared__ unsigned int sprefix;
    __shared__ int skrem, scnt_gt, scnt_eq;
    int t = threadIdx.x;
    unsigned int keys[32];
#pragma unroll
    for (int j = 0; j < 32; j++) keys[j] = g_keys[t + j * 1024];
    if (t < 256) { hist[t] = g_hist[t]; g_hist[t] = 0; }  // consume + re-zero
    if (t == 0) {
        skrem = KSEL; scnt_gt = 0; scnt_eq = 0;
        g_anyvalid = 0; g_npairs = 0;
    }
    __syncthreads();

    // pass 0: bucket select from the precomputed histogram
#pragma unroll
    for (int o = 1; o < 256; o <<= 1) {
        unsigned int v = 0;
        if (t < 256 && t + o < 256) v = hist[t + o];
        __syncthreads();
        if (t < 256) hist[t] += v;
        __syncthreads();
    }
    if (t < 256) {
        unsigned int St = hist[t];
        unsigned int Sn = (t < 255) ? hist[t + 1] : 0u;
        if (St >= KSEL && Sn < KSEL) {
            sprefix = (unsigned int)t;
            skrem = (int)(KSEL - Sn);
        }
    }
    __syncthreads();

    // passes 1..3: only keys matching the running prefix (few) hit atomics
    for (int pass = 1; pass < 4; pass++) {
        if (t < 256) hist[t] = 0;
        __syncthreads();
        unsigned int pref = sprefix;
        unsigned int krem = (unsigned int)skrem;
        int shift = 24 - 8 * pass;
#pragma unroll
        for (int j = 0; j < 32; j++) {
            unsigned int key = keys[j];
            if ((key >> (shift + 8)) == pref)
                atomicAdd(&hist[(key >> shift) & 0xFFu], 1u);
        }
        __syncthreads();
#pragma unroll
        for (int o = 1; o < 256; o <<= 1) {
            unsigned int v = 0;
            if (t < 256 && t + o < 256) v = hist[t + o];
            __syncthreads();
            if (t < 256) hist[t] += v;
            __syncthreads();
        }
        if (t < 256) {
            unsigned int St = hist[t];
            unsigned int Sn = (t < 255) ? hist[t + 1] : 0u;
            if (St >= krem && Sn < krem) {
                sprefix = (pref << 8) | (unsigned int)t;
                skrem = (int)(krem - Sn);
            }
        }
        __syncthreads();
    }

    unsigned int thresh = sprefix;
#pragma unroll
    for (int j = 0; j < 32; j++) {
        unsigned int key = keys[j];
        int i = t + j * 1024;
        if (key > thresh) { int p = atomicAdd(&scnt_gt, 1); g_topk[p] = i; }
        else if (key == thresh) { int e = atomicAdd(&scnt_eq, 1); g_eq[e] = i; }
    }
    __syncthreads();
    int n = scnt_eq, need = skrem, base = scnt_gt;
    for (int i = t; i < n; i += 1024) {
        int idx = g_eq[i];
        int rank = 0;
        for (int jj = 0; jj < n; jj++) rank += (g_eq[jj] < idx);
        if (rank < need) g_topk[base + rank] = idx;
    }
}

// ======================= gather (+ bf16 split of S) =========================
__global__ void k_gather(const float* __restrict__ roi) {
    int r = blockIdx.x;
    int idx = g_topk[r];
    float4 v = ((const float4*)(roi + (size_t)idx * DIM))[threadIdx.x];
    ((float4*)(g_S + (size_t)r * DIM))[threadIdx.x] = v;
    int base = r * DIM + threadIdx.x * 4;
    float e[4] = {v.x, v.y, v.z, v.w};
    __nv_bfloat162 h01, h23, l01, l23;
    h01.x = __float2bfloat16(e[0]); h01.y = __float2bfloat16(e[1]);
    h23.x = __float2bfloat16(e[2]); h23.y = __float2bfloat16(e[3]);
    l01.x = __float2bfloat16(e[0] - __bfloat162float(h01.x));
    l01.y = __float2bfloat16(e[1] - __bfloat162float(h01.y));
    l23.x = __float2bfloat16(e[2] - __bfloat162float(h23.x));
    l23.y = __float2bfloat16(e[3] - __bfloat162float(h23.y));
    *(__nv_bfloat162*)(g_Sh + base) = h01;
    *(__nv_bfloat162*)(g_Sh + base + 2) = h23;
    *(__nv_bfloat162*)(g_Sl + base) = l01;
    *(__nv_bfloat162*)(g_Sl + base + 2) = l23;
}

// ======================= fused weight conversions (vectorized) ==============
__device__ __forceinline__ uint4 pack8(const float* e) {
    __nv_bfloat162 p[4];
#pragma unroll
    for (int c = 0; c < 4; c++) {
        p[c].x = __float2bfloat16(e[2 * c]);
        p[c].y = __float2bfloat16(e[2 * c + 1]);
    }
    uint4 u;
    u.x = *(uint32_t*)&p[0]; u.y = *(uint32_t*)&p[1];
    u.z = *(uint32_t*)&p[2]; u.w = *(uint32_t*)&p[3];
    return u;
}

__global__ void k_cvt_all(const float* __restrict__ wq,
                          const float* __restrict__ wk,
                          const float* __restrict__ wo) {
    int i = 8 * (blockIdx.x * blockDim.x + threadIdx.x);
    int which = blockIdx.y;
    if (which == 0) {
        float e[8];
        *(float4*)&e[0] = *(const float4*)(wq + i);
        *(float4*)&e[4] = *(const float4*)(wq + i + 4);
        *(uint4*)(g_Wqb + i) = pack8(e);
    } else if (which == 1) {
        float e[8];
        *(float4*)&e[0] = *(const float4*)(wk + i);
        *(float4*)&e[4] = *(const float4*)(wk + i + 4);
        *(uint4*)(g_Wkb + i) = pack8(e);
    } else {
        int j = i >> 10, k = i & 1023;
        float e[8];
        *(float4*)&e[0] = *(const float4*)(wo + (size_t)j * 2 * DIM + DIM + k);
        *(float4*)&e[4] = *(const float4*)(wo + (size_t)j * 2 * DIM + DIM + k + 4);
        uint4 h = pack8(e);
        *(uint4*)(g_Wo2h + i) = h;
        float r[8];
        const __nv_bfloat16* hb = (const __nv_bfloat16*)&h;
#pragma unroll
        for (int c = 0; c < 8; c++) r[c] = e[c] - __bfloat162float(hb[c]);
        *(uint4*)(g_Wo2l + i) = pack8(r);
    }
}

// ======================= pipelined bf16 HMMA GEMM ===========================
#define LDSROW 72
#define ASTAGE (128 * LDSROW)
#define STAGEB (2 * ASTAGE)
#define PIPE_SMEM (2 * STAGEB * 2)
#define MASK_SMEM (STAGEB * 2)

__device__ __forceinline__ void warp_mma_block(
    uint32_t a_base, uint32_t b_base, int wr, int wc, int lane,
    float acc[4][4][4]) {
#pragma unroll
    for (int ks = 0; ks < 4; ks++) {
        uint32_t af[4][4], bf[4][2];
#pragma unroll
        for (int mi = 0; mi < 4; mi++) {
            uint32_t addr = a_base +
                ((wr * 64 + mi * 16 + (lane & 15)) * LDSROW + ks * 16 + (lane >> 4) * 8) * 2;
            ldmatrix_x4(af[mi], addr);
        }
#pragma unroll
        for (int ni = 0; ni < 4; ni++) {
            uint32_t addr = b_base +
                ((wc * 32 + ni * 8 + (lane & 7)) * LDSROW + ks * 16 + ((lane >> 3) & 1) * 8) * 2;
            ldmatrix_x2(bf[ni], addr);
        }
#pragma unroll
        for (int mi = 0; mi < 4; mi++)
#pragma unroll
            for (int ni = 0; ni < 4; ni++)
                mma16816(acc[mi][ni], af[mi], bf[ni]);
    }
}

__device__ __forceinline__ void issue_stage(
    const __nv_bfloat16* __restrict__ A, int lda,
    const __nv_bfloat16* __restrict__ B, int ldb,
    uint32_t smem_stage_addr, int tid) {
#pragma unroll
    for (int i = 0; i < 4; i++) {
        int idx = tid + i * 256;
        int row = idx >> 3;
        int cg = idx & 7;
        uint32_t off = (uint32_t)(row * LDSROW + cg * 8) * 2;
        cp_async16(smem_stage_addr + off, A + (size_t)row * lda + cg * 8);
        cp_async16(smem_stage_addr + ASTAGE * 2 + off, B + (size_t)row * ldb + cg * 8);
    }
    CP_COMMIT();
}

// ----- Q/K projections: fp32 out + NORMALIZED bf16 + norms + partial norms --
__global__ void __launch_bounds__(256, 2) k_gemm3(
    const float* __restrict__ bq, const float* __restrict__ bk)
{
    extern __shared__ __nv_bfloat16 smp[];
    __shared__ float snorm[128];
    __shared__ float snorm64[128];
    int tid = threadIdx.x, wid = tid >> 5, lane = tid & 31;
    int bm = blockIdx.y * 128, bn = blockIdx.x * 128;
    int z = blockIdx.z;
    int wr = wid & 1, wc = wid >> 1;
    uint32_t s_base = smem_u32(smp);

    const __nv_bfloat16* B = z ? g_Wkb : g_Wqb;
    const float* bias = z ? bk : bq;
    float* C = z ? g_K : g_Q;
    __nv_bfloat16* Cb = z ? g_Kb : g_Qb;
    float* normOut = z ? g_kn : g_qn;
    float* pOut = z ? g_pk : g_pq;

    float acc[4][4][4];
#pragma unroll
    for (int mi = 0; mi < 4; mi++)
#pragma unroll
        for (int ni = 0; ni < 4; ni++)
#pragma unroll
            for (int c = 0; c < 4; c++) acc[mi][ni][c] = 0.f;

    const int nch = DIM >> 6;

    issue_stage(g_Sh + (size_t)bm * DIM, DIM, B + (size_t)bn * DIM, DIM,
                s_base, tid);

    for (int ch = 0; ch < nch; ch++) {
        int st = ch & 1;
        if (ch + 1 < nch) {
            int kc = (ch + 1) << 6;
            issue_stage(g_Sh + (size_t)bm * DIM + kc, DIM,
                        B + (size_t)bn * DIM + kc, DIM,
                        s_base + (st ^ 1) * STAGEB * 2, tid);
            CP_WAIT(1);
        } else {
            CP_WAIT(0);
        }
        __syncthreads();
        uint32_t a_b = s_base + st * STAGEB * 2;
        warp_mma_block(a_b, a_b + ASTAGE * 2, wr, wc, lane, acc);
        __syncthreads();
    }

    if (tid < 128) { snorm[tid] = 0.f; snorm64[tid] = 0.f; }
    __syncthreads();

    // pass 1: fp32 store + norm accumulation (full and first-64-dims partial)
#pragma unroll
    for (int mi = 0; mi < 4; mi++) {
        int row0 = bm + wr * 64 + mi * 16 + (lane >> 2);
        float ns0 = 0.f, ns1 = 0.f;
#pragma unroll
        for (int ni = 0; ni < 4; ni++) {
            int col = bn + wc * 32 + ni * 8 + (lane & 3) * 2;
            float b0 = bias[col], b1 = bias[col + 1];
            float v00 = acc[mi][ni][0] + b0, v01 = acc[mi][ni][1] + b1;
            float v10 = acc[mi][ni][2] + b0, v11 = acc[mi][ni][3] + b1;
            *(float2*)(C + (size_t)row0 * DIM + col) = make_float2(v00, v01);
            *(float2*)(C + (size_t)(row0 + 8) * DIM + col) = make_float2(v10, v11);
            ns0 += v00 * v00 + v01 * v01;
            ns1 += v10 * v10 + v11 * v11;
        }
        ns0 += __shfl_xor_sync(0xffffffffu, ns0, 1);
        ns0 += __shfl_xor_sync(0xffffffffu, ns0, 2);
        ns1 += __shfl_xor_sync(0xffffffffu, ns1, 1);
        ns1 += __shfl_xor_sync(0xffffffffu, ns1, 2);
        if ((lane & 3) == 0) {
            atomicAdd(&snorm[row0 - bm], ns0);
            atomicAdd(&snorm[row0 - bm + 8], ns1);
            if (wc < 2) {  // cols [bn, bn+64) = first 64 dims of this head
                atomicAdd(&snorm64[row0 - bm], ns0);
                atomicAdd(&snorm64[row0 - bm + 8], ns1);
            }
        }
    }
    __syncthreads();

    // pass 2: normalized bf16 store
#pragma unroll
    for (int mi = 0; mi < 4; mi++) {
        int row0 = bm + wr * 64 + mi * 16 + (lane >> 2);
        float rinv0 = __fdividef(1.f, sqrtf(snorm[row0 - bm]) + 1e-6f);
        float rinv1 = __fdividef(1.f, sqrtf(snorm[row0 - bm + 8]) + 1e-6f);
#pragma unroll
        for (int ni = 0; ni < 4; ni++) {
            int col = bn + wc * 32 + ni * 8 + (lane & 3) * 2;
            float b0 = bias[col], b1 = bias[col + 1];
            float v00 = acc[mi][ni][0] + b0, v01 = acc[mi][ni][1] + b1;
            float v10 = acc[mi][ni][2] + b0, v11 = acc[mi][ni][3] + b1;
            __nv_bfloat162 h0, h1;
            h0.x = __float2bfloat16(v00 * rinv0); h0.y = __float2bfloat16(v01 * rinv0);
            h1.x = __float2bfloat16(v10 * rinv1); h1.y = __float2bfloat16(v11 * rinv1);
            *(__nv_bfloat162*)(Cb + (size_t)row0 * DIM + col) = h0;
            *(__nv_bfloat162*)(Cb + (size_t)(row0 + 8) * DIM + col) = h1;
        }
    }
    if (tid < 128) {
        float ns = snorm[tid];
        float nrm = sqrtf(ns);
        float rinv = __fdividef(1.f, nrm + 1e-6f);
        normOut[blockIdx.x * KSEL + bm + tid] = nrm;
        pOut[blockIdx.x * KSEL + bm + tid] = snorm64[tid] * rinv * rinv;
    }
}

// ----- FUSED projection (3-segment split bf16) with direct output write -----
__global__ void __launch_bounds__(256, 2) k_gemm_fused(
    const float* __restrict__ bo, float* __restrict__ out)
{
    extern __shared__ __nv_bfloat16 smp[];
    int tid = threadIdx.x, wid = tid >> 5, lane = tid & 31;
    int bm = blockIdx.y * 128, bn = blockIdx.x * 128;
    int wr = wid & 1, wc = wid >> 1;
    uint32_t s_base = smem_u32(smp);

    const __nv_bfloat16* Aseg[3] = {g_Sh, g_Sh, g_Sl};
    const __nv_bfloat16* Bseg[3] = {g_Wo2h, g_Wo2l, g_Wo2h};

    float acc[4][4][4];
#pragma unroll
    for (int mi = 0; mi < 4; mi++)
#pragma unroll
        for (int ni = 0; ni < 4; ni++)
#pragma unroll
            for (int c = 0; c < 4; c++) acc[mi][ni][c] = 0.f;

    const int cps = DIM >> 6;
    const int nch = 3 * cps;

    issue_stage(Aseg[0] + (size_t)bm * DIM, DIM, Bseg[0] + (size_t)bn * DIM, DIM,
                s_base, tid);

    for (int ch = 0; ch < nch; ch++) {
        int st = ch & 1;
        if (ch + 1 < nch) {
            int seg = (ch + 1) / cps;
            int kc = ((ch + 1) - seg * cps) << 6;
            issue_stage(Aseg[seg] + (size_t)bm * DIM + kc, DIM,
                        Bseg[seg] + (size_t)bn * DIM + kc, DIM,
                        s_base + (st ^ 1) * STAGEB * 2, tid);
            CP_WAIT(1);
        } else {
            CP_WAIT(0);
        }
        __syncthreads();
        uint32_t a_b = s_base + st * STAGEB * 2;
        warp_mma_block(a_b, a_b + ASTAGE * 2, wr, wc, lane, acc);
        __syncthreads();
    }

#pragma unroll
    for (int mi = 0; mi < 4; mi++) {
        int r0 = bm + wr * 64 + mi * 16 + (lane >> 2);
        int r1 = r0 + 8;
        int t0 = g_topk[r0], t1 = g_topk[r1];
#pragma unroll
        for (int ni = 0; ni < 4; ni++) {
            int col = bn + wc * 32 + ni * 8 + (lane & 3) * 2;
            float b0 = bo[col], b1 = bo[col + 1];
            float v00 = acc[mi][ni][0] + b0, v01 = acc[mi][ni][1] + b1;
            float v10 = acc[mi][ni][2] + b0, v11 = acc[mi][ni][3] + b1;
            *(float2*)(g_FUSED + (size_t)r0 * DIM + col) = make_float2(v00, v01);
            *(float2*)(g_FUSED + (size_t)r1 * DIM + col) = make_float2(v10, v11);
            float2 s0 = *(const float2*)(g_S + (size_t)r0 * DIM + col);
            float2 s1 = *(const float2*)(g_S + (size_t)r1 * DIM + col);
            *(float2*)(out + (size_t)t0 * DIM + col) =
                make_float2(0.5f * (s0.x + v00), 0.5f * (s0.y + v01));
            *(float2*)(out + (size_t)t1 * DIM + col) =
                make_float2(0.5f * (s1.x + v10), 0.5f * (s1.y + v11));
        }
    }
}

// ======================= screened mask: K=64 partial-distance ===============
// partial64 = pq + pk - 2*c  (c = qn.kn over first 64 dims of the head).
// partial64 > 0.25  =>  |qn-kn|^2 > 0.2  =>  sim < 0.9  (rigorous rejection;
// 0.05 margin covers all bf16 error). Survivors -> exact fp32 check.
__global__ void __launch_bounds__(256) k_mask64() {
    extern __shared__ __nv_bfloat16 smp[];
    __shared__ float pkv[128];
    __shared__ float pqv[128];
    int tid = threadIdx.x, wid = tid >> 5, lane = tid & 31;
    int bn = blockIdx.x * 128, bm = blockIdx.y * 128, h = blockIdx.z;
    int wr = wid & 1, wc = wid >> 1;
    uint32_t s_base = smem_u32(smp);

#pragma unroll
    for (int i = 0; i < 4; i++) {
        int idx = tid + i * 256;
        int row = idx >> 3;
        int cg = idx & 7;
        uint32_t off = (uint32_t)(row * LDSROW + cg * 8) * 2;
        cp_async16(s_base + off,
                   g_Qb + (size_t)(bm + row) * DIM + h * HDIM + cg * 8);
        cp_async16(s_base + ASTAGE * 2 + off,
                   g_Kb + (size_t)(bn + row) * DIM + h * HDIM + cg * 8);
    }
    CP_COMMIT();

    if (tid < 128) {
        pqv[tid] = g_pq[h * KSEL + bm + tid];
        pkv[tid] = g_pk[h * KSEL + bn + tid];
    }

    float acc[4][4][4];
#pragma unroll
    for (int mi = 0; mi < 4; mi++)
#pragma unroll
        for (int ni = 0; ni < 4; ni++)
#pragma unroll
            for (int c = 0; c < 4; c++) acc[mi][ni][c] = 0.f;

    CP_WAIT(0);
    __syncthreads();
    warp_mma_block(s_base, s_base + ASTAGE * 2, wr, wc, lane, acc);  // K=64

#pragma unroll
    for (int mi = 0; mi < 4; mi++) {
        int r0l = wr * 64 + mi * 16 + (lane >> 2);
        int r1l = r0l + 8;
        float pq0 = pqv[r0l], pq1 = pqv[r1l];
#pragma unroll
        for (int ni = 0; ni < 4; ni++) {
            int cl = wc * 32 + ni * 8 + (lane & 3) * 2;
            float pk0 = pkv[cl], pk1 = pkv[cl + 1];
            int s00 = (pq0 + pk0 - 2.f * acc[mi][ni][0] <= 0.25f);
            int s01 = (pq0 + pk1 - 2.f * acc[mi][ni][1] <= 0.25f);
            int s10 = (pq1 + pk0 - 2.f * acc[mi][ni][2] <= 0.25f);
            int s11 = (pq1 + pk1 - 2.f * acc[mi][ni][3] <= 0.25f);
            if (__any_sync(0xffffffffu, s00 | s01 | s10 | s11)) {
                if (s00) { int p = atomicAdd(&g_npairs, 1);
                    if (p < PCAP) g_pairs[p] = (h << 22) | ((bm + r0l) << 11) | (bn + cl);
                    else g_anyvalid = 1; }
                if (s01) { int p = atomicAdd(&g_npairs, 1);
                    if (p < PCAP) g_pairs[p] = (h << 22) | ((bm + r0l) << 11) | (bn + cl + 1);
                    else g_anyvalid = 1; }
                if (s10) { int p = atomicAdd(&g_npairs, 1);
                    if (p < PCAP) g_pairs[p] = (h << 22) | ((bm + r1l) << 11) | (bn + cl);
                    else g_anyvalid = 1; }
                if (s11) { int p = atomicAdd(&g_npairs, 1);
                    if (p < PCAP) g_pairs[p] = (h << 22) | ((bm + r1l) << 11) | (bn + cl + 1);
                    else g_anyvalid = 1; }
            }
        }
    }
}

// exact fp32 check for survivor pairs
__global__ void k_maskcheck() {
    int np = g_npairs;
    if (np > PCAP) {
        if (blockIdx.x == 0 && threadIdx.x == 0) g_anyvalid = 1;
        np = PCAP;
    }
    int gw = (blockIdx.x * blockDim.x + threadIdx.x) >> 5;
    int lane = threadIdx.x & 31;
    int nw = (gridDim.x * blockDim.x) >> 5;
    for (int i = gw; i < np; i += nw) {
        int pk = g_pairs[i];
        int h = pk >> 22, qr = (pk >> 11) & 2047, kr = pk & 2047;
        const float4* q = (const float4*)(g_Q + (size_t)qr * DIM + h * HDIM);
        const float4* k = (const float4*)(g_K + (size_t)kr * DIM + h * HDIM);
        float4 qa = q[lane], ka = k[lane];
        float d = qa.x * ka.x + qa.y * ka.y + qa.z * ka.z + qa.w * ka.w;
#pragma unroll
        for (int o = 16; o; o >>= 1) d += __shfl_xor_sync(0xffffffffu, d, o);
        if (lane == 0) {
            float qn = g_qn[h * KSEL + qr] + 1e-6f;
            float kn = g_kn[h * KSEL + kr] + 1e-6f;
            if (d > 0.9f * qn * kn) atomicOr(&g_anyvalid, 1);
        }
    }
}

// ======================= fp32 SIMT GEMM (fallback only) =====================
#define BM 128
#define BN 128
#define BKK 16
#define SPAD 132
__global__ void __launch_bounds__(256) k_gemm(
    const float* __restrict__ A, int lda,
    const float* __restrict__ B, int ldb,
    const float* __restrict__ bias,
    float* __restrict__ C, int ldc,
    int M, int N, int Kd, int acc_flag, int chk)
{
    if (chk && g_anyvalid == 0) return;
    __shared__ float As[BKK * SPAD];
    __shared__ float Bs[BKK * SPAD];
    int tid = threadIdx.x;
    int bm = blockIdx.y * BM, bn = blockIdx.x * BN;
    int row0 = (tid >> 4) * 8, col0 = (tid & 15) * 8;
    float acc[8][8];
#pragma unroll
    for (int i = 0; i < 8; i++)
#pragma unroll
        for (int j = 0; j < 8; j++) acc[i][j] = 0.f;

    for (int k0 = 0; k0 < Kd; k0 += BKK) {
#pragma unroll
        for (int i = 0; i < 2; i++) {
            int f = tid + i * 256;
            int r = f >> 2;
            int kc = (f & 3) * 4;
            float4 av = *(const float4*)(A + (size_t)(bm + r) * lda + k0 + kc);
            As[(kc + 0) * SPAD + r] = av.x;
            As[(kc + 1) * SPAD + r] = av.y;
            As[(kc + 2) * SPAD + r] = av.z;
            As[(kc + 3) * SPAD + r] = av.w;
            float4 bv = *(const float4*)(B + (size_t)(bn + r) * ldb + k0 + kc);
            Bs[(kc + 0) * SPAD + r] = bv.x;
            Bs[(kc + 1) * SPAD + r] = bv.y;
            Bs[(kc + 2) * SPAD + r] = bv.z;
            Bs[(kc + 3) * SPAD + r] = bv.w;
        }
        __syncthreads();
#pragma unroll
        for (int k = 0; k < BKK; k++) {
            float a[8], b[8];
            *(float4*)&a[0] = *(const float4*)&As[k * SPAD + row0];
            *(float4*)&a[4] = *(const float4*)&As[k * SPAD + row0 + 4];
            *(float4*)&b[0] = *(const float4*)&Bs[k * SPAD + col0];
            *(float4*)&b[4] = *(const float4*)&Bs[k * SPAD + col0 + 4];
#pragma unroll
            for (int i = 0; i < 8; i++)
#pragma unroll
                for (int j = 0; j < 8; j++) acc[i][j] += a[i] * b[j];
        }
        __syncthreads();
    }
#pragma unroll
    for (int i = 0; i < 8; i++) {
        float* crow = C + (size_t)(bm + row0 + i) * ldc + bn + col0;
#pragma unroll
        for (int j = 0; j < 8; j++) {
            float v = acc[i][j];
            if (bias) v += bias[bn + col0 + j];
            if (acc_flag) v += crow[j];
            crow[j] = v;
        }
    }
}

// ======================= fp32 flash attention (fallback) ====================
#define AT_RS 68
#define AT_VS 132
#define ATTN_SMEM ((128 * AT_RS * 2 + 64 * AT_VS + 64 * AT_RS) * 4)

__global__ void __launch_bounds__(256) k_attn() {
    if (g_anyvalid == 0) return;
    extern __shared__ float smf[];
    float* QsT = smf;
    float* KsT = QsT + 128 * AT_RS;
    float* Vs  = KsT + 128 * AT_RS;
    float* Ps  = Vs + 64 * AT_VS;

    const int h = blockIdx.y;
    const int q0 = blockIdx.x * 64;
    const int tid = threadIdx.x;
    const int tx = tid & 15;
    const int ty = tid >> 4;
    const float scale = 0.088388347648318447f;

#pragma unroll
    for (int i = 0; i < 8; i++) {
        int f = tid + i * 256;
        int r = f >> 5;
        int dd = (f & 31) * 4;
        float4 v = *(const float4*)(g_Q + (size_t)(q0 + r) * DIM + h * HDIM + dd);
        QsT[(dd + 0) * AT_RS + r] = v.x;
        QsT[(dd + 1) * AT_RS + r] = v.y;
        QsT[(dd + 2) * AT_RS + r] = v.z;
        QsT[(dd + 3) * AT_RS + r] = v.w;
    }

    float qe[4];
#pragma unroll
    for (int i = 0; i < 4; i++)
        qe[i] = g_qn[h * KSEL + q0 + 4 * ty + i] + 1e-6f;

    float m[4], l[4], agg[4][8];
#pragma unroll
    for (int i = 0; i < 4; i++) {
        m[i] = -1e30f; l[i] = 0.f;
#pragma unroll
        for (int c = 0; c < 8; c++) agg[i][c] = 0.f;
    }

    for (int kt = 0; kt < KSEL / 64; kt++) {
        int k0 = kt * 64;
#pragma unroll
        for (int i = 0; i < 8; i++) {
            int f = tid + i * 256;
            int r = f >> 5;
            int dd = (f & 31) * 4;
            float4 v = *(const float4*)(g_K + (size_t)(k0 + r) * DIM + h * HDIM + dd);
            KsT[(dd + 0) * AT_RS + r] = v.x;
            KsT[(dd + 1) * AT_RS + r] = v.y;
            KsT[(dd + 2) * AT_RS + r] = v.z;
            KsT[(dd + 3) * AT_RS + r] = v.w;
            float4 vv = *(const float4*)(g_V + (size_t)(k0 + r) * DIM + h * HDIM + dd);
            *(float4*)&Vs[r * AT_VS + dd] = vv;
        }
        __syncthreads();

        float s[4][4];
#pragma unroll
        for (int i = 0; i < 4; i++)
#pragma unroll
            for (int j = 0; j < 4; j++) s[i][j] = 0.f;

#pragma unroll 4
        for (int dd = 0; dd < 128; dd++) {
            float4 qa = *(const float4*)&QsT[dd * AT_RS + 4 * ty];
            float4 kb = *(const float4*)&KsT[dd * AT_RS + 4 * tx];
            float a[4] = {qa.x, qa.y, qa.z, qa.w};
            float b[4] = {kb.x, kb.y, kb.z, kb.w};
#pragma unroll
            for (int i = 0; i < 4; i++)
#pragma unroll
                for (int j = 0; j < 4; j++) s[i][j] += a[i] * b[j];
        }

        float ke[4];
#pragma unroll
        for (int j = 0; j < 4; j++)
            ke[j] = g_kn[h * KSEL + k0 + 4 * tx + j] + 1e-6f;

        float w[4][4], tmax[4];
        int localany = 0;
#pragma unroll
        for (int i = 0; i < 4; i++) {
            float tm = -1e30f;
#pragma unroll
            for (int j = 0; j < 4; j++) {
                float sim = __fdividef(s[i][j], qe[i] * ke[j]);
                bool valid = sim > 0.9f;
                float lg = valid ? s[i][j] * scale : -1e30f;
                w[i][j] = lg;
                tm = fmaxf(tm, lg);
                localany |= (int)valid;
            }
#pragma unroll
            for (int o = 8; o; o >>= 1)
                tm = fmaxf(tm, __shfl_xor_sync(0xffffffffu, tm, o));
            tmax[i] = tm;
        }

        int anyv = __syncthreads_or(localany);
        if (anyv) {
#pragma unroll
            for (int i = 0; i < 4; i++) {
                float mn = fmaxf(m[i], tmax[i]);
                float f = __expf(m[i] - mn);
                float rs = 0.f;
#pragma unroll
                for (int j = 0; j < 4; j++) {
                    float e = (w[i][j] > -1e29f) ? __expf(w[i][j] - mn) : 0.f;
                    w[i][j] = e;
                    rs += e;
                }
#pragma unroll
                for (int o = 8; o; o >>= 1)
                    rs += __shfl_xor_sync(0xffffffffu, rs, o);
                l[i] = l[i] * f + rs;
                m[i] = mn;
#pragma unroll
                for (int c = 0; c < 8; c++) agg[i][c] *= f;
                *(float4*)&Ps[(4 * ty + i) * AT_RS + 4 * tx] =
                    make_float4(w[i][0], w[i][1], w[i][2], w[i][3]);
            }
            __syncthreads();
#pragma unroll 2
            for (int j = 0; j < 64; j++) {
                float4 v0 = *(const float4*)&Vs[j * AT_VS + 8 * tx];
                float4 v1 = *(const float4*)&Vs[j * AT_VS + 8 * tx + 4];
                float vv[8] = {v0.x, v0.y, v0.z, v0.w, v1.x, v1.y, v1.z, v1.w};
#pragma unroll
                for (int i = 0; i < 4; i++) {
                    float p = Ps[(4 * ty + i) * AT_RS + j];
#pragma unroll
                    for (int c = 0; c < 8; c++) agg[i][c] += p * vv[c];
                }
            }
        }
        __syncthreads();
    }

#pragma unroll
    for (int i = 0; i < 4; i++) {
        float inv = (l[i] > 0.f) ? __fdividef(1.f, l[i]) : 0.f;
        float4 o0, o1;
        o0.x = agg[i][0] * inv; o0.y = agg[i][1] * inv;
        o0.z = agg[i][2] * inv; o0.w = agg[i][3] * inv;
        o1.x = agg[i][4] * inv; o1.y = agg[i][5] * inv;
        o1.z = agg[i][6] * inv; o1.w = agg[i][7] * inv;
        float* dst = g_AGG + (size_t)(q0 + 4 * ty + i) * DIM + h * HDIM + 8 * tx;
        *(float4*)dst = o0;
        *(float4*)(dst + 4) = o1;
    }
}

// ======================= scatter (fallback only) ============================
__global__ void k_scatter(float* __restrict__ out) {
    if (g_anyvalid == 0) return;
    int r = blockIdx.x;
    int idx = g_topk[r];
    const float4* s = (const float4*)(g_S + (size_t)r * DIM);
    const float4* f = (const float4*)(g_FUSED + (size_t)r * DIM);
    float4 sv = s[threadIdx.x], fv = f[threadIdx.x];
    float4 o;
    o.x = 0.5f * (sv.x + fv.x);
    o.y = 0.5f * (sv.y + fv.y);
    o.z = 0.5f * (sv.z + fv.z);
    o.w = 0.5f * (sv.w + fv.w);
    ((float4*)(out + (size_t)idx * DIM))[threadIdx.x] = o;
}

// ======================= launch =============================================
extern "C" void kernel_launch(void* const* d_in, const int* in_sizes, int n_in,
                              void* d_out, int out_size) {
    const float* roi     = (const float*)d_in[0];
    const float* w_score = (const float*)d_in[1];
    const float* b_score = (const float*)d_in[2];
    const float* wq      = (const float*)d_in[3];
    const float* bq      = (const float*)d_in[4];
    const float* wk      = (const float*)d_in[5];
    const float* bk      = (const float*)d_in[6];
    const float* wv      = (const float*)d_in[7];
    const float* bv      = (const float*)d_in[8];
    const float* wo      = (const float*)d_in[9];
    const float* bo      = (const float*)d_in[10];
    float* out = (float*)d_out;

    float *pS, *pAGG, *pFUSED, *pV;
    cudaGetSymbolAddress((void**)&pS, g_S);
    cudaGetSymbolAddress((void**)&pAGG, g_AGG);
    cudaGetSymbolAddress((void**)&pFUSED, g_FUSED);
    cudaGetSymbolAddress((void**)&pV, g_V);

    cudaFuncSetAttribute(k_gemm3, cudaFuncAttributeMaxDynamicSharedMemorySize,
                         PIPE_SMEM);
    cudaFuncSetAttribute(k_gemm_fused, cudaFuncAttributeMaxDynamicSharedMemorySize,
                         PIPE_SMEM);
    cudaFuncSetAttribute(k_mask64, cudaFuncAttributeMaxDynamicSharedMemorySize,
                         MASK_SMEM);
    cudaFuncSetAttribute(k_attn, cudaFuncAttributeMaxDynamicSharedMemorySize,
                         ATTN_SMEM);

    cudaStream_t s1;
    cudaStreamCreateWithFlags(&s1, cudaStreamNonBlocking);
    cudaEvent_t ev0, evc, evg, evf;
    cudaEventCreateWithFlags(&ev0, cudaEventDisableTiming);
    cudaEventCreateWithFlags(&evc, cudaEventDisableTiming);
    cudaEventCreateWithFlags(&evg, cudaEventDisableTiming);
    cudaEventCreateWithFlags(&evf, cudaEventDisableTiming);

    // s1: weight cvt overlapping the score+copy pass on s0
    cudaEventRecord(ev0, 0);
    cudaStreamWaitEvent(s1, ev0, 0);
    k_cvt_all<<<dim3(DIM * DIM / 2048, 3), 256, 0, s1>>>(wq, wk, wo);
    cudaEventRecord(evc, s1);

    // s0: fused score+copy+hist (single pass over roi) -> topk -> gather
    k_score_copy<<<NROI / 8, 256>>>(roi, w_score, b_score, out);
    k_topk<<<1, 1024>>>();
    k_gather<<<KSEL, 256>>>(roi);
    cudaEventRecord(evg, 0);

    // s1: FUSED projection (after cvt on s1, gather+copy on s0 via evg)
    cudaStreamWaitEvent(s1, evg, 0);
    k_gemm_fused<<<dim3(DIM / 128, KSEL / 128), 256, PIPE_SMEM, s1>>>(bo, out);
    cudaEventRecord(evf, s1);

    // s0: Q/K projections, screened mask, exact survivor check
    cudaStreamWaitEvent(0, evc, 0);
    k_gemm3<<<dim3(DIM / 128, KSEL / 128, 2), 256, PIPE_SMEM>>>(bq, bk);
    k_mask64<<<dim3(KSEL / 128, KSEL / 128, NH), 256, MASK_SMEM>>>();
    k_maskcheck<<<32, 256>>>();

    // fallback path (guarded; normally no-ops)
    dim3 gg(DIM / BN, KSEL / BM);
    k_gemm<<<gg, 256>>>(pS, DIM, wv, DIM, bv, pV, DIM, KSEL, DIM, DIM, 0, 1);
    k_attn<<<dim3(KSEL / 64, NH), 256, ATTN_SMEM>>>();
    cudaStreamWaitEvent(0, evf, 0);
    k_gemm<<<gg, 256>>>(pAGG, DIM, wo, 2 * DIM, (const float*)nullptr,
                        pFUSED, DIM, KSEL, DIM, DIM, 1, 1);
    k_scatter<<<KSEL, 256>>>(out);
}

// round 14
// speedup vs baseline: 1.1732x; 1.0580x over previous
#include <cuda_runtime.h>
#include <cuda_bf16.h>
#include <math.h>
#include <stdint.h>

#define NROI 32768
#define DIM  1024
#define NH   8
#define HDIM 128
#define KSEL 2048
#define PCAP 32768

// ======================= PTX helpers (family-compatible) ====================
__device__ __forceinline__ uint32_t smem_u32(const void* p) {
    uint32_t a;
    asm("{ .reg .u64 t; cvta.to.shared.u64 t, %1; cvt.u32.u64 %0, t; }"
        : "=r"(a) : "l"(p));
    return a;
}
__device__ __forceinline__ void ldmatrix_x4(uint32_t* r, uint32_t addr) {
    asm volatile("ldmatrix.sync.aligned.m8n8.x4.shared.b16 {%0,%1,%2,%3}, [%4];"
        : "=r"(r[0]), "=r"(r[1]), "=r"(r[2]), "=r"(r[3]) : "r"(addr));
}
__device__ __forceinline__ void ldmatrix_x2(uint32_t* r, uint32_t addr) {
    asm volatile("ldmatrix.sync.aligned.m8n8.x2.shared.b16 {%0,%1}, [%2];"
        : "=r"(r[0]), "=r"(r[1]) : "r"(addr));
}
__device__ __forceinline__ void mma16816(float* d, const uint32_t* a,
                                         const uint32_t* b) {
    asm volatile(
        "mma.sync.aligned.m16n8k16.row.col.f32.bf16.bf16.f32 "
        "{%0,%1,%2,%3}, {%4,%5,%6,%7}, {%8,%9}, {%0,%1,%2,%3};"
        : "+f"(d[0]), "+f"(d[1]), "+f"(d[2]), "+f"(d[3])
        : "r"(a[0]), "r"(a[1]), "r"(a[2]), "r"(a[3]), "r"(b[0]), "r"(b[1]));
}
__device__ __forceinline__ void cp_async16(uint32_t smem_addr, const void* g) {
    asm volatile("cp.async.cg.shared.global [%0], [%1], 16;"
        :: "r"(smem_addr), "l"(g) : "memory");
}
#define CP_COMMIT() asm volatile("cp.async.commit_group;" ::: "memory")
#define CP_WAIT(n)  asm volatile("cp.async.wait_group %0;" :: "n"(n) : "memory")

// ======================= scratch device globals ==============================
__device__ unsigned int g_keys[NROI];
__device__ unsigned int g_hist[256];   // pass-0 histogram (zeroed by k_topk)
__device__ int          g_topk[KSEL];
__device__ int          g_eq[NROI];
__device__ int          g_anyvalid;
__device__ int          g_npairs;
__device__ int          g_pairs[PCAP];

__device__ float g_S[KSEL * DIM];
__device__ float g_Q[KSEL * DIM];
__device__ float g_K[KSEL * DIM];
__device__ float g_V[KSEL * DIM];
__device__ float g_AGG[KSEL * DIM];
__device__ float g_FUSED[KSEL * DIM];
__device__ float g_qn[NH * KSEL];   // |q| per head-row
__device__ float g_kn[NH * KSEL];
__device__ float g_pq[NH * KSEL];   // partial norm^2 of qn over first 64 dims
__device__ float g_pk[NH * KSEL];

__device__ __nv_bfloat16 g_Sh[KSEL * DIM];
__device__ __nv_bfloat16 g_Sl[KSEL * DIM];
__device__ __nv_bfloat16 g_Qb[KSEL * DIM];   // NORMALIZED qn (bf16)
__device__ __nv_bfloat16 g_Kb[KSEL * DIM];   // NORMALIZED kn (bf16)
__device__ __nv_bfloat16 g_Wqb[DIM * DIM];
__device__ __nv_bfloat16 g_Wkb[DIM * DIM];
__device__ __nv_bfloat16 g_Wo2h[DIM * DIM];
__device__ __nv_bfloat16 g_Wo2l[DIM * DIM];

// ======================= scores + pass-0 hist (no copy) =====================
__global__ void k_score(const float* __restrict__ roi,
                        const float* __restrict__ w,
                        const float* __restrict__ b) {
    __shared__ unsigned int sh[256];
    sh[threadIdx.x] = 0;
    __syncthreads();
    int gw = (blockIdx.x * blockDim.x + threadIdx.x) >> 5;
    int lane = threadIdx.x & 31;
    const float4* r4 = (const float4*)(roi + (size_t)gw * DIM);
    const float4* w4 = (const float4*)w;
    float acc = 0.f;
#pragma unroll
    for (int i = 0; i < 8; i++) {
        float4 rv = r4[lane + i * 32];
        float4 wv = w4[lane + i * 32];
        acc += rv.x * wv.x + rv.y * wv.y + rv.z * wv.z + rv.w * wv.w;
    }
#pragma unroll
    for (int o = 16; o; o >>= 1) acc += __shfl_xor_sync(0xffffffffu, acc, o);
    if (lane == 0) {
        float s = acc + b[0];
        unsigned int kk = __float_as_uint(s);
        kk = (kk & 0x80000000u) ? ~kk : (kk | 0x80000000u);
        g_keys[gw] = kk;
        atomicAdd(&sh[kk >> 24], 1u);
    }
    __syncthreads();
    unsigned int c = sh[threadIdx.x];
    if (c) atomicAdd(&g_hist[threadIdx.x], c);
}

// ======================= flat copy roi -> out (overlaps GEMM phase) =========
__global__ void k_copy(const float4* __restrict__ roi, float4* __restrict__ out) {
    int i = blockIdx.x * blockDim.x + threadIdx.x;
    out[i] = roi[i];
    out[i + (NROI * DIM / 8)] = roi[i + (NROI * DIM / 8)];
}

// ======================= single-kernel exact top-K (register keys) ==========
__global__ void __launch_bounds__(1024) k_topk() {
    __shared__ unsigned int hist[256];
    __shared__ unsigned int sprefix;
    __shared__ int skrem, scnt_gt, scnt_eq;
    int t = threadIdx.x;
    unsigned int keys[32];
#pragma unroll
    for (int j = 0; j < 32; j++) keys[j] = g_keys[t + j * 1024];
    if (t < 256) { hist[t] = g_hist[t]; g_hist[t] = 0; }  // consume + re-zero
    if (t == 0) {
        skrem = KSEL; scnt_gt = 0; scnt_eq = 0;
        g_anyvalid = 0; g_npairs = 0;
    }
    __syncthreads();

    // pass 0: bucket select from the precomputed histogram
#pragma unroll
    for (int o = 1; o < 256; o <<= 1) {
        unsigned int v = 0;
        if (t < 256 && t + o < 256) v = hist[t + o];
        __syncthreads();
        if (t < 256) hist[t] += v;
        __syncthreads();
    }
    if (t < 256) {
        unsigned int St = hist[t];
        unsigned int Sn = (t < 255) ? hist[t + 1] : 0u;
        if (St >= KSEL && Sn < KSEL) {
            sprefix = (unsigned int)t;
            skrem = (int)(KSEL - Sn);
        }
    }
    __syncthreads();

    // passes 1..3: only keys matching the running prefix (few) hit atomics
    for (int pass = 1; pass < 4; pass++) {
        if (t < 256) hist[t] = 0;
        __syncthreads();
        unsigned int pref = sprefix;
        unsigned int krem = (unsigned int)skrem;
        int shift = 24 - 8 * pass;
#pragma unroll
        for (int j = 0; j < 32; j++) {
            unsigned int key = keys[j];
            if ((key >> (shift + 8)) == pref)
                atomicAdd(&hist[(key >> shift) & 0xFFu], 1u);
        }
        __syncthreads();
#pragma unroll
        for (int o = 1; o < 256; o <<= 1) {
            unsigned int v = 0;
            if (t < 256 && t + o < 256) v = hist[t + o];
            __syncthreads();
            if (t < 256) hist[t] += v;
            __syncthreads();
        }
        if (t < 256) {
            unsigned int St = hist[t];
            unsigned int Sn = (t < 255) ? hist[t + 1] : 0u;
            if (St >= krem && Sn < krem) {
                sprefix = (pref << 8) | (unsigned int)t;
                skrem = (int)(krem - Sn);
            }
        }
        __syncthreads();
    }

    unsigned int thresh = sprefix;
#pragma unroll
    for (int j = 0; j < 32; j++) {
        unsigned int key = keys[j];
        int i = t + j * 1024;
        if (key > thresh) { int p = atomicAdd(&scnt_gt, 1); g_topk[p] = i; }
        else if (key == thresh) { int e = atomicAdd(&scnt_eq, 1); g_eq[e] = i; }
    }
    __syncthreads();
    int n = scnt_eq, need = skrem, base = scnt_gt;
    for (int i = t; i < n; i += 1024) {
        int idx = g_eq[i];
        int rank = 0;
        for (int jj = 0; jj < n; jj++) rank += (g_eq[jj] < idx);
        if (rank < need) g_topk[base + rank] = idx;
    }
}

// ======================= gather (+ bf16 split of S) =========================
__global__ void k_gather(const float* __restrict__ roi) {
    int r = blockIdx.x;
    int idx = g_topk[r];
    float4 v = ((const float4*)(roi + (size_t)idx * DIM))[threadIdx.x];
    ((float4*)(g_S + (size_t)r * DIM))[threadIdx.x] = v;
    int base = r * DIM + threadIdx.x * 4;
    float e[4] = {v.x, v.y, v.z, v.w};
    __nv_bfloat162 h01, h23, l01, l23;
    h01.x = __float2bfloat16(e[0]); h01.y = __float2bfloat16(e[1]);
    h23.x = __float2bfloat16(e[2]); h23.y = __float2bfloat16(e[3]);
    l01.x = __float2bfloat16(e[0] - __bfloat162float(h01.x));
    l01.y = __float2bfloat16(e[1] - __bfloat162float(h01.y));
    l23.x = __float2bfloat16(e[2] - __bfloat162float(h23.x));
    l23.y = __float2bfloat16(e[3] - __bfloat162float(h23.y));
    *(__nv_bfloat162*)(g_Sh + base) = h01;
    *(__nv_bfloat162*)(g_Sh + base + 2) = h23;
    *(__nv_bfloat162*)(g_Sl + base) = l01;
    *(__nv_bfloat162*)(g_Sl + base + 2) = l23;
}

// ======================= fused weight conversions (vectorized) ==============
__device__ __forceinline__ uint4 pack8(const float* e) {
    __nv_bfloat162 p[4];
#pragma unroll
    for (int c = 0; c < 4; c++) {
        p[c].x = __float2bfloat16(e[2 * c]);
        p[c].y = __float2bfloat16(e[2 * c + 1]);
    }
    uint4 u;
    u.x = *(uint32_t*)&p[0]; u.y = *(uint32_t*)&p[1];
    u.z = *(uint32_t*)&p[2]; u.w = *(uint32_t*)&p[3];
    return u;
}

__global__ void k_cvt_all(const float* __restrict__ wq,
                          const float* __restrict__ wk,
                          const float* __restrict__ wo) {
    int i = 8 * (blockIdx.x * blockDim.x + threadIdx.x);
    int which = blockIdx.y;
    if (which == 0) {
        float e[8];
        *(float4*)&e[0] = *(const float4*)(wq + i);
        *(float4*)&e[4] = *(const float4*)(wq + i + 4);
        *(uint4*)(g_Wqb + i) = pack8(e);
    } else if (which == 1) {
        float e[8];
        *(float4*)&e[0] = *(const float4*)(wk + i);
        *(float4*)&e[4] = *(const float4*)(wk + i + 4);
        *(uint4*)(g_Wkb + i) = pack8(e);
    } else {
        int j = i >> 10, k = i & 1023;
        float e[8];
        *(float4*)&e[0] = *(const float4*)(wo + (size_t)j * 2 * DIM + DIM + k);
        *(float4*)&e[4] = *(const float4*)(wo + (size_t)j * 2 * DIM + DIM + k + 4);
        uint4 h = pack8(e);
        *(uint4*)(g_Wo2h + i) = h;
        float r[8];
        const __nv_bfloat16* hb = (const __nv_bfloat16*)&h;
#pragma unroll
        for (int c = 0; c < 8; c++) r[c] = e[c] - __bfloat162float(hb[c]);
        *(uint4*)(g_Wo2l + i) = pack8(r);
    }
}

// ======================= pipelined bf16 HMMA GEMM ===========================
#define LDSROW 72
#define ASTAGE (128 * LDSROW)
#define STAGEB (2 * ASTAGE)
#define PIPE_SMEM (2 * STAGEB * 2)
#define MASK_SMEM (STAGEB * 2)

__device__ __forceinline__ void warp_mma_block(
    uint32_t a_base, uint32_t b_base, int wr, int wc, int lane,
    float acc[4][4][4]) {
#pragma unroll
    for (int ks = 0; ks < 4; ks++) {
        uint32_t af[4][4], bf[4][2];
#pragma unroll
        for (int mi = 0; mi < 4; mi++) {
            uint32_t addr = a_base +
                ((wr * 64 + mi * 16 + (lane & 15)) * LDSROW + ks * 16 + (lane >> 4) * 8) * 2;
            ldmatrix_x4(af[mi], addr);
        }
#pragma unroll
        for (int ni = 0; ni < 4; ni++) {
            uint32_t addr = b_base +
                ((wc * 32 + ni * 8 + (lane & 7)) * LDSROW + ks * 16 + ((lane >> 3) & 1) * 8) * 2;
            ldmatrix_x2(bf[ni], addr);
        }
#pragma unroll
        for (int mi = 0; mi < 4; mi++)
#pragma unroll
            for (int ni = 0; ni < 4; ni++)
                mma16816(acc[mi][ni], af[mi], bf[ni]);
    }
}

__device__ __forceinline__ void issue_stage(
    const __nv_bfloat16* __restrict__ A, int lda,
    const __nv_bfloat16* __restrict__ B, int ldb,
    uint32_t smem_stage_addr, int tid) {
#pragma unroll
    for (int i = 0; i < 4; i++) {
        int idx = tid + i * 256;
        int row = idx >> 3;
        int cg = idx & 7;
        uint32_t off = (uint32_t)(row * LDSROW + cg * 8) * 2;
        cp_async16(smem_stage_addr + off, A + (size_t)row * lda + cg * 8);
        cp_async16(smem_stage_addr + ASTAGE * 2 + off, B + (size_t)row * ldb + cg * 8);
    }
    CP_COMMIT();
}

// ----- Q/K projections: fp32 out + NORMALIZED bf16 + norms + partial norms --
__global__ void __launch_bounds__(256, 2) k_gemm3(
    const float* __restrict__ bq, const float* __restrict__ bk)
{
    extern __shared__ __nv_bfloat16 smp[];
    __shared__ float snorm[128];
    __shared__ float snorm64[128];
    int tid = threadIdx.x, wid = tid >> 5, lane = tid & 31;
    int bm = blockIdx.y * 128, bn = blockIdx.x * 128;
    int z = blockIdx.z;
    int wr = wid & 1, wc = wid >> 1;
    uint32_t s_base = smem_u32(smp);

    const __nv_bfloat16* B = z ? g_Wkb : g_Wqb;
    const float* bias = z ? bk : bq;
    float* C = z ? g_K : g_Q;
    __nv_bfloat16* Cb = z ? g_Kb : g_Qb;
    float* normOut = z ? g_kn : g_qn;
    float* pOut = z ? g_pk : g_pq;

    float acc[4][4][4];
#pragma unroll
    for (int mi = 0; mi < 4; mi++)
#pragma unroll
        for (int ni = 0; ni < 4; ni++)
#pragma unroll
            for (int c = 0; c < 4; c++) acc[mi][ni][c] = 0.f;

    const int nch = DIM >> 6;

    issue_stage(g_Sh + (size_t)bm * DIM, DIM, B + (size_t)bn * DIM, DIM,
                s_base, tid);

    for (int ch = 0; ch < nch; ch++) {
        int st = ch & 1;
        if (ch + 1 < nch) {
            int kc = (ch + 1) << 6;
            issue_stage(g_Sh + (size_t)bm * DIM + kc, DIM,
                        B + (size_t)bn * DIM + kc, DIM,
                        s_base + (st ^ 1) * STAGEB * 2, tid);
            CP_WAIT(1);
        } else {
            CP_WAIT(0);
        }
        __syncthreads();
        uint32_t a_b = s_base + st * STAGEB * 2;
        warp_mma_block(a_b, a_b + ASTAGE * 2, wr, wc, lane, acc);
        __syncthreads();
    }

    if (tid < 128) { snorm[tid] = 0.f; snorm64[tid] = 0.f; }
    __syncthreads();

    // pass 1: fp32 store + norm accumulation (full and first-64-dims partial)
#pragma unroll
    for (int mi = 0; mi < 4; mi++) {
        int row0 = bm + wr * 64 + mi * 16 + (lane >> 2);
        float ns0 = 0.f, ns1 = 0.f;
#pragma unroll
        for (int ni = 0; ni < 4; ni++) {
            int col = bn + wc * 32 + ni * 8 + (lane & 3) * 2;
            float b0 = bias[col], b1 = bias[col + 1];
            float v00 = acc[mi][ni][0] + b0, v01 = acc[mi][ni][1] + b1;
            float v10 = acc[mi][ni][2] + b0, v11 = acc[mi][ni][3] + b1;
            *(float2*)(C + (size_t)row0 * DIM + col) = make_float2(v00, v01);
            *(float2*)(C + (size_t)(row0 + 8) * DIM + col) = make_float2(v10, v11);
            ns0 += v00 * v00 + v01 * v01;
            ns1 += v10 * v10 + v11 * v11;
        }
        ns0 += __shfl_xor_sync(0xffffffffu, ns0, 1);
        ns0 += __shfl_xor_sync(0xffffffffu, ns0, 2);
        ns1 += __shfl_xor_sync(0xffffffffu, ns1, 1);
        ns1 += __shfl_xor_sync(0xffffffffu, ns1, 2);
        if ((lane & 3) == 0) {
            atomicAdd(&snorm[row0 - bm], ns0);
            atomicAdd(&snorm[row0 - bm + 8], ns1);
            if (wc < 2) {  // cols [bn, bn+64) = first 64 dims of this head
                atomicAdd(&snorm64[row0 - bm], ns0);
                atomicAdd(&snorm64[row0 - bm + 8], ns1);
            }
        }
    }
    __syncthreads();

    // pass 2: normalized bf16 store
#pragma unroll
    for (int mi = 0; mi < 4; mi++) {
        int row0 = bm + wr * 64 + mi * 16 + (lane >> 2);
        float rinv0 = __fdividef(1.f, sqrtf(snorm[row0 - bm]) + 1e-6f);
        float rinv1 = __fdividef(1.f, sqrtf(snorm[row0 - bm + 8]) + 1e-6f);
#pragma unroll
        for (int ni = 0; ni < 4; ni++) {
            int col = bn + wc * 32 + ni * 8 + (lane & 3) * 2;
            float b0 = bias[col], b1 = bias[col + 1];
            float v00 = acc[mi][ni][0] + b0, v01 = acc[mi][ni][1] + b1;
            float v10 = acc[mi][ni][2] + b0, v11 = acc[mi][ni][3] + b1;
            __nv_bfloat162 h0, h1;
            h0.x = __float2bfloat16(v00 * rinv0); h0.y = __float2bfloat16(v01 * rinv0);
            h1.x = __float2bfloat16(v10 * rinv1); h1.y = __float2bfloat16(v11 * rinv1);
            *(__nv_bfloat162*)(Cb + (size_t)row0 * DIM + col) = h0;
            *(__nv_bfloat162*)(Cb + (size_t)(row0 + 8) * DIM + col) = h1;
        }
    }
    if (tid < 128) {
        float ns = snorm[tid];
        float nrm = sqrtf(ns);
        float rinv = __fdividef(1.f, nrm + 1e-6f);
        normOut[blockIdx.x * KSEL + bm + tid] = nrm;
        pOut[blockIdx.x * KSEL + bm + tid] = snorm64[tid] * rinv * rinv;
    }
}

// ----- FUSED projection (3-segment split bf16), writes g_FUSED only --------
__global__ void __launch_bounds__(256, 2) k_gemm_fused(
    const float* __restrict__ bo)
{
    extern __shared__ __nv_bfloat16 smp[];
    int tid = threadIdx.x, wid = tid >> 5, lane = tid & 31;
    int bm = blockIdx.y * 128, bn = blockIdx.x * 128;
    int wr = wid & 1, wc = wid >> 1;
    uint32_t s_base = smem_u32(smp);

    const __nv_bfloat16* Aseg[3] = {g_Sh, g_Sh, g_Sl};
    const __nv_bfloat16* Bseg[3] = {g_Wo2h, g_Wo2l, g_Wo2h};

    float acc[4][4][4];
#pragma unroll
    for (int mi = 0; mi < 4; mi++)
#pragma unroll
        for (int ni = 0; ni < 4; ni++)
#pragma unroll
            for (int c = 0; c < 4; c++) acc[mi][ni][c] = 0.f;

    const int cps = DIM >> 6;
    const int nch = 3 * cps;

    issue_stage(Aseg[0] + (size_t)bm * DIM, DIM, Bseg[0] + (size_t)bn * DIM, DIM,
                s_base, tid);

    for (int ch = 0; ch < nch; ch++) {
        int st = ch & 1;
        if (ch + 1 < nch) {
            int seg = (ch + 1) / cps;
            int kc = ((ch + 1) - seg * cps) << 6;
            issue_stage(Aseg[seg] + (size_t)bm * DIM + kc, DIM,
                        Bseg[seg] + (size_t)bn * DIM + kc, DIM,
                        s_base + (st ^ 1) * STAGEB * 2, tid);
            CP_WAIT(1);
        } else {
            CP_WAIT(0);
        }
        __syncthreads();
        uint32_t a_b = s_base + st * STAGEB * 2;
        warp_mma_block(a_b, a_b + ASTAGE * 2, wr, wc, lane, acc);
        __syncthreads();
    }

#pragma unroll
    for (int mi = 0; mi < 4; mi++) {
        int r0 = bm + wr * 64 + mi * 16 + (lane >> 2);
        int r1 = r0 + 8;
#pragma unroll
        for (int ni = 0; ni < 4; ni++) {
            int col = bn + wc * 32 + ni * 8 + (lane & 3) * 2;
            float b0 = bo[col], b1 = bo[col + 1];
            *(float2*)(g_FUSED + (size_t)r0 * DIM + col) =
                make_float2(acc[mi][ni][0] + b0, acc[mi][ni][1] + b1);
            *(float2*)(g_FUSED + (size_t)r1 * DIM + col) =
                make_float2(acc[mi][ni][2] + b0, acc[mi][ni][3] + b1);
        }
    }
}

// ======================= screened mask: K=64 partial-distance ===============
// partial64 = pq + pk - 2*c  (c = qn.kn over first 64 dims of the head).
// partial64 > 0.25  =>  |qn-kn|^2 > 0.2  =>  sim < 0.9  (rigorous rejection;
// 0.05 margin covers all bf16 error). Survivors -> exact fp32 check.
__global__ void __launch_bounds__(256) k_mask64() {
    extern __shared__ __nv_bfloat16 smp[];
    __shared__ float pkv[128];
    __shared__ float pqv[128];
    int tid = threadIdx.x, wid = tid >> 5, lane = tid & 31;
    int bn = blockIdx.x * 128, bm = blockIdx.y * 128, h = blockIdx.z;
    int wr = wid & 1, wc = wid >> 1;
    uint32_t s_base = smem_u32(smp);

#pragma unroll
    for (int i = 0; i < 4; i++) {
        int idx = tid + i * 256;
        int row = idx >> 3;
        int cg = idx & 7;
        uint32_t off = (uint32_t)(row * LDSROW + cg * 8) * 2;
        cp_async16(s_base + off,
                   g_Qb + (size_t)(bm + row) * DIM + h * HDIM + cg * 8);
        cp_async16(s_base + ASTAGE * 2 + off,
                   g_Kb + (size_t)(bn + row) * DIM + h * HDIM + cg * 8);
    }
    CP_COMMIT();

    if (tid < 128) {
        pqv[tid] = g_pq[h * KSEL + bm + tid];
        pkv[tid] = g_pk[h * KSEL + bn + tid];
    }

    float acc[4][4][4];
#pragma unroll
    for (int mi = 0; mi < 4; mi++)
#pragma unroll
        for (int ni = 0; ni < 4; ni++)
#pragma unroll
            for (int c = 0; c < 4; c++) acc[mi][ni][c] = 0.f;

    CP_WAIT(0);
    __syncthreads();
    warp_mma_block(s_base, s_base + ASTAGE * 2, wr, wc, lane, acc);  // K=64

#pragma unroll
    for (int mi = 0; mi < 4; mi++) {
        int r0l = wr * 64 + mi * 16 + (lane >> 2);
        int r1l = r0l + 8;
        float pq0 = pqv[r0l], pq1 = pqv[r1l];
#pragma unroll
        for (int ni = 0; ni < 4; ni++) {
            int cl = wc * 32 + ni * 8 + (lane & 3) * 2;
            float pk0 = pkv[cl], pk1 = pkv[cl + 1];
            int s00 = (pq0 + pk0 - 2.f * acc[mi][ni][0] <= 0.25f);
            int s01 = (pq0 + pk1 - 2.f * acc[mi][ni][1] <= 0.25f);
            int s10 = (pq1 + pk0 - 2.f * acc[mi][ni][2] <= 0.25f);
            int s11 = (pq1 + pk1 - 2.f * acc[mi][ni][3] <= 0.25f);
            if (__any_sync(0xffffffffu, s00 | s01 | s10 | s11)) {
                if (s00) { int p = atomicAdd(&g_npairs, 1);
                    if (p < PCAP) g_pairs[p] = (h << 22) | ((bm + r0l) << 11) | (bn + cl);
                    else g_anyvalid = 1; }
                if (s01) { int p = atomicAdd(&g_npairs, 1);
                    if (p < PCAP) g_pairs[p] = (h << 22) | ((bm + r0l) << 11) | (bn + cl + 1);
                    else g_anyvalid = 1; }
                if (s10) { int p = atomicAdd(&g_npairs, 1);
                    if (p < PCAP) g_pairs[p] = (h << 22) | ((bm + r1l) << 11) | (bn + cl);
                    else g_anyvalid = 1; }
                if (s11) { int p = atomicAdd(&g_npairs, 1);
                    if (p < PCAP) g_pairs[p] = (h << 22) | ((bm + r1l) << 11) | (bn + cl + 1);
                    else g_anyvalid = 1; }
            }
        }
    }
}

// exact fp32 check for survivor pairs
__global__ void k_maskcheck() {
    int np = g_npairs;
    if (np > PCAP) {
        if (blockIdx.x == 0 && threadIdx.x == 0) g_anyvalid = 1;
        np = PCAP;
    }
    int gw = (blockIdx.x * blockDim.x + threadIdx.x) >> 5;
    int lane = threadIdx.x & 31;
    int nw = (gridDim.x * blockDim.x) >> 5;
    for (int i = gw; i < np; i += nw) {
        int pk = g_pairs[i];
        int h = pk >> 22, qr = (pk >> 11) & 2047, kr = pk & 2047;
        const float4* q = (const float4*)(g_Q + (size_t)qr * DIM + h * HDIM);
        const float4* k = (const float4*)(g_K + (size_t)kr * DIM + h * HDIM);
        float4 qa = q[lane], ka = k[lane];
        float d = qa.x * ka.x + qa.y * ka.y + qa.z * ka.z + qa.w * ka.w;
#pragma unroll
        for (int o = 16; o; o >>= 1) d += __shfl_xor_sync(0xffffffffu, d, o);
        if (lane == 0) {
            float qn = g_qn[h * KSEL + qr] + 1e-6f;
            float kn = g_kn[h * KSEL + kr] + 1e-6f;
            if (d > 0.9f * qn * kn) atomicOr(&g_anyvalid, 1);
        }
    }
}

// ======================= fp32 SIMT GEMM (fallback only) =====================
#define BM 128
#define BN 128
#define BKK 16
#define SPAD 132
__global__ void __launch_bounds__(256) k_gemm(
    const float* __restrict__ A, int lda,
    const float* __restrict__ B, int ldb,
    const float* __restrict__ bias,
    float* __restrict__ C, int ldc,
    int M, int N, int Kd, int acc_flag, int chk)
{
    if (chk && g_anyvalid == 0) return;
    __shared__ float As[BKK * SPAD];
    __shared__ float Bs[BKK * SPAD];
    int tid = threadIdx.x;
    int bm = blockIdx.y * BM, bn = blockIdx.x * BN;
    int row0 = (tid >> 4) * 8, col0 = (tid & 15) * 8;
    float acc[8][8];
#pragma unroll
    for (int i = 0; i < 8; i++)
#pragma unroll
        for (int j = 0; j < 8; j++) acc[i][j] = 0.f;

    for (int k0 = 0; k0 < Kd; k0 += BKK) {
#pragma unroll
        for (int i = 0; i < 2; i++) {
            int f = tid + i * 256;
            int r = f >> 2;
            int kc = (f & 3) * 4;
            float4 av = *(const float4*)(A + (size_t)(bm + r) * lda + k0 + kc);
            As[(kc + 0) * SPAD + r] = av.x;
            As[(kc + 1) * SPAD + r] = av.y;
            As[(kc + 2) * SPAD + r] = av.z;
            As[(kc + 3) * SPAD + r] = av.w;
            float4 bv = *(const float4*)(B + (size_t)(bn + r) * ldb + k0 + kc);
            Bs[(kc + 0) * SPAD + r] = bv.x;
            Bs[(kc + 1) * SPAD + r] = bv.y;
            Bs[(kc + 2) * SPAD + r] = bv.z;
            Bs[(kc + 3) * SPAD + r] = bv.w;
        }
        __syncthreads();
#pragma unroll
        for (int k = 0; k < BKK; k++) {
            float a[8], b[8];
            *(float4*)&a[0] = *(const float4*)&As[k * SPAD + row0];
            *(float4*)&a[4] = *(const float4*)&As[k * SPAD + row0 + 4];
            *(float4*)&b[0] = *(const float4*)&Bs[k * SPAD + col0];
            *(float4*)&b[4] = *(const float4*)&Bs[k * SPAD + col0 + 4];
#pragma unroll
            for (int i = 0; i < 8; i++)
#pragma unroll
                for (int j = 0; j < 8; j++) acc[i][j] += a[i] * b[j];
        }
        __syncthreads();
    }
#pragma unroll
    for (int i = 0; i < 8; i++) {
        float* crow = C + (size_t)(bm + row0 + i) * ldc + bn + col0;
#pragma unroll
        for (int j = 0; j < 8; j++) {
            float v = acc[i][j];
            if (bias) v += bias[bn + col0 + j];
            if (acc_flag) v += crow[j];
            crow[j] = v;
        }
    }
}

// ======================= fp32 flash attention (fallback) ====================
#define AT_RS 68
#define AT_VS 132
#define ATTN_SMEM ((128 * AT_RS * 2 + 64 * AT_VS + 64 * AT_RS) * 4)

__global__ void __launch_bounds__(256) k_attn() {
    if (g_anyvalid == 0) return;
    extern __shared__ float smf[];
    float* QsT = smf;
    float* KsT = QsT + 128 * AT_RS;
    float* Vs  = KsT + 128 * AT_RS;
    float* Ps  = Vs + 64 * AT_VS;

    const int h = blockIdx.y;
    const int q0 = blockIdx.x * 64;
    const int tid = threadIdx.x;
    const int tx = tid & 15;
    const int ty = tid >> 4;
    const float scale = 0.088388347648318447f;

#pragma unroll
    for (int i = 0; i < 8; i++) {
        int f = tid + i * 256;
        int r = f >> 5;
        int dd = (f & 31) * 4;
        float4 v = *(const float4*)(g_Q + (size_t)(q0 + r) * DIM + h * HDIM + dd);
        QsT[(dd + 0) * AT_RS + r] = v.x;
        QsT[(dd + 1) * AT_RS + r] = v.y;
        QsT[(dd + 2) * AT_RS + r] = v.z;
        QsT[(dd + 3) * AT_RS + r] = v.w;
    }

    float qe[4];
#pragma unroll
    for (int i = 0; i < 4; i++)
        qe[i] = g_qn[h * KSEL + q0 + 4 * ty + i] + 1e-6f;

    float m[4], l[4], agg[4][8];
#pragma unroll
    for (int i = 0; i < 4; i++) {
        m[i] = -1e30f; l[i] = 0.f;
#pragma unroll
        for (int c = 0; c < 8; c++) agg[i][c] = 0.f;
    }

    for (int kt = 0; kt < KSEL / 64; kt++) {
        int k0 = kt * 64;
#pragma unroll
        for (int i = 0; i < 8; i++) {
            int f = tid + i * 256;
            int r = f >> 5;
            int dd = (f & 31) * 4;
            float4 v = *(const float4*)(g_K + (size_t)(k0 + r) * DIM + h * HDIM + dd);
            KsT[(dd + 0) * AT_RS + r] = v.x;
            KsT[(dd + 1) * AT_RS + r] = v.y;
            KsT[(dd + 2) * AT_RS + r] = v.z;
            KsT[(dd + 3) * AT_RS + r] = v.w;
            float4 vv = *(const float4*)(g_V + (size_t)(k0 + r) * DIM + h * HDIM + dd);
            *(float4*)&Vs[r * AT_VS + dd] = vv;
        }
        __syncthreads();

        float s[4][4];
#pragma unroll
        for (int i = 0; i < 4; i++)
#pragma unroll
            for (int j = 0; j < 4; j++) s[i][j] = 0.f;

#pragma unroll 4
        for (int dd = 0; dd < 128; dd++) {
            float4 qa = *(const float4*)&QsT[dd * AT_RS + 4 * ty];
            float4 kb = *(const float4*)&KsT[dd * AT_RS + 4 * tx];
            float a[4] = {qa.x, qa.y, qa.z, qa.w};
            float b[4] = {kb.x, kb.y, kb.z, kb.w};
#pragma unroll
            for (int i = 0; i < 4; i++)
#pragma unroll
                for (int j = 0; j < 4; j++) s[i][j] += a[i] * b[j];
        }

        float ke[4];
#pragma unroll
        for (int j = 0; j < 4; j++)
            ke[j] = g_kn[h * KSEL + k0 + 4 * tx + j] + 1e-6f;

        float w[4][4], tmax[4];
        int localany = 0;
#pragma unroll
        for (int i = 0; i < 4; i++) {
            float tm = -1e30f;
#pragma unroll
            for (int j = 0; j < 4; j++) {
                float sim = __fdividef(s[i][j], qe[i] * ke[j]);
                bool valid = sim > 0.9f;
                float lg = valid ? s[i][j] * scale : -1e30f;
                w[i][j] = lg;
                tm = fmaxf(tm, lg);
                localany |= (int)valid;
            }
#pragma unroll
            for (int o = 8; o; o >>= 1)
                tm = fmaxf(tm, __shfl_xor_sync(0xffffffffu, tm, o));
            tmax[i] = tm;
        }

        int anyv = __syncthreads_or(localany);
        if (anyv) {
#pragma unroll
            for (int i = 0; i < 4; i++) {
                float mn = fmaxf(m[i], tmax[i]);
                float f = __expf(m[i] - mn);
                float rs = 0.f;
#pragma unroll
                for (int j = 0; j < 4; j++) {
                    float e = (w[i][j] > -1e29f) ? __expf(w[i][j] - mn) : 0.f;
                    w[i][j] = e;
                    rs += e;
                }
#pragma unroll
                for (int o = 8; o; o >>= 1)
                    rs += __shfl_xor_sync(0xffffffffu, rs, o);
                l[i] = l[i] * f + rs;
                m[i] = mn;
#pragma unroll
                for (int c = 0; c < 8; c++) agg[i][c] *= f;
                *(float4*)&Ps[(4 * ty + i) * AT_RS + 4 * tx] =
                    make_float4(w[i][0], w[i][1], w[i][2], w[i][3]);
            }
            __syncthreads();
#pragma unroll 2
            for (int j = 0; j < 64; j++) {
                float4 v0 = *(const float4*)&Vs[j * AT_VS + 8 * tx];
                float4 v1 = *(const float4*)&Vs[j * AT_VS + 8 * tx + 4];
                float vv[8] = {v0.x, v0.y, v0.z, v0.w, v1.x, v1.y, v1.z, v1.w};
#pragma unroll
                for (int i = 0; i < 4; i++) {
                    float p = Ps[(4 * ty + i) * AT_RS + j];
#pragma unroll
                    for (int c = 0; c < 8; c++) agg[i][c] += p * vv[c];
                }
            }
        }
        __syncthreads();
    }

#pragma unroll
    for (int i = 0; i < 4; i++) {
        float inv = (l[i] > 0.f) ? __fdividef(1.f, l[i]) : 0.f;
        float4 o0, o1;
        o0.x = agg[i][0] * inv; o0.y = agg[i][1] * inv;
        o0.z = agg[i][2] * inv; o0.w = agg[i][3] * inv;
        o1.x = agg[i][4] * inv; o1.y = agg[i][5] * inv;
        o1.z = agg[i][6] * inv; o1.w = agg[i][7] * inv;
        float* dst = g_AGG + (size_t)(q0 + 4 * ty + i) * DIM + h * HDIM + 8 * tx;
        *(float4*)dst = o0;
        *(float4*)(dst + 4) = o1;
    }
}

// ======================= blend: out[topk[r]] = 0.5*(S + FUSED) ==============
__global__ void k_blend(float* __restrict__ out) {
    int r = blockIdx.x;
    int idx = g_topk[r];
    const float4* s = (const float4*)(g_S + (size_t)r * DIM);
    const float4* f = (const float4*)(g_FUSED + (size_t)r * DIM);
    float4 sv = s[threadIdx.x], fv = f[threadIdx.x];
    float4 o;
    o.x = 0.5f * (sv.x + fv.x);
    o.y = 0.5f * (sv.y + fv.y);
    o.z = 0.5f * (sv.z + fv.z);
    o.w = 0.5f * (sv.w + fv.w);
    ((float4*)(out + (size_t)idx * DIM))[threadIdx.x] = o;
}

// ======================= launch =============================================
extern "C" void kernel_launch(void* const* d_in, const int* in_sizes, int n_in,
                              void* d_out, int out_size) {
    const float* roi     = (const float*)d_in[0];
    const float* w_score = (const float*)d_in[1];
    const float* b_score = (const float*)d_in[2];
    const float* wq      = (const float*)d_in[3];
    const float* bq      = (const float*)d_in[4];
    const float* wk      = (const float*)d_in[5];
    const float* bk      = (const float*)d_in[6];
    const float* wv      = (const float*)d_in[7];
    const float* bv      = (const float*)d_in[8];
    const float* wo      = (const float*)d_in[9];
    const float* bo      = (const float*)d_in[10];
    float* out = (float*)d_out;

    float *pS, *pAGG, *pFUSED, *pV;
    cudaGetSymbolAddress((void**)&pS, g_S);
    cudaGetSymbolAddress((void**)&pAGG, g_AGG);
    cudaGetSymbolAddress((void**)&pFUSED, g_FUSED);
    cudaGetSymbolAddress((void**)&pV, g_V);

    // One-time setup: streams/events/attrs created on the FIRST call (the
    // correctness run, pre-capture) and cached. The capture call then makes
    // NO allocations — keeps the graph-teardown memory checkpoint clean.
    static cudaStream_t s1 = nullptr, s2 = nullptr;
    static cudaEvent_t ev0, evc, evg, evf, evcp;
    if (!s1) {
        cudaStreamCreateWithFlags(&s1, cudaStreamNonBlocking);
        cudaStreamCreateWithFlags(&s2, cudaStreamNonBlocking);
        cudaEventCreateWithFlags(&ev0, cudaEventDisableTiming);
        cudaEventCreateWithFlags(&evc, cudaEventDisableTiming);
        cudaEventCreateWithFlags(&evg, cudaEventDisableTiming);
        cudaEventCreateWithFlags(&evf, cudaEventDisableTiming);
        cudaEventCreateWithFlags(&evcp, cudaEventDisableTiming);
        cudaFuncSetAttribute(k_gemm3, cudaFuncAttributeMaxDynamicSharedMemorySize,
                             PIPE_SMEM);
        cudaFuncSetAttribute(k_gemm_fused,
                             cudaFuncAttributeMaxDynamicSharedMemorySize, PIPE_SMEM);
        cudaFuncSetAttribute(k_mask64, cudaFuncAttributeMaxDynamicSharedMemorySize,
                             MASK_SMEM);
        cudaFuncSetAttribute(k_attn, cudaFuncAttributeMaxDynamicSharedMemorySize,
                             ATTN_SMEM);
    }

    // s1: weight cvt first (overlaps score), then the bulk copy AFTER gather
    // so it runs inside the GEMM phase's idle HBM bandwidth.
    cudaEventRecord(ev0, 0);
    cudaStreamWaitEvent(s1, ev0, 0);
    k_cvt_all<<<dim3(DIM * DIM / 2048, 3), 256, 0, s1>>>(wq, wk, wo);
    cudaEventRecord(evc, s1);

    // s0: score (read-only pass) -> topk -> gather
    k_score<<<NROI / 8, 256>>>(roi, w_score, b_score);
    k_topk<<<1, 1024>>>();
    k_gather<<<KSEL, 256>>>(roi);
    cudaEventRecord(evg, 0);

    // s1: bulk roi->out copy, overlapping the GEMM phase
    cudaStreamWaitEvent(s1, evg, 0);
    k_copy<<<NROI * DIM / 8 / 256, 256, 0, s1>>>((const float4*)roi, (float4*)out);
    cudaEventRecord(evcp, s1);

    // s2: FUSED projection (needs cvt + gather), concurrent with Q/K + mask
    cudaStreamWaitEvent(s2, evg, 0);
    cudaStreamWaitEvent(s2, evc, 0);
    k_gemm_fused<<<dim3(DIM / 128, KSEL / 128), 256, PIPE_SMEM, s2>>>(bo);
    cudaEventRecord(evf, s2);

    // s0: Q/K projections, screened mask, exact survivor check
    cudaStreamWaitEvent(0, evc, 0);
    k_gemm3<<<dim3(DIM / 128, KSEL / 128, 2), 256, PIPE_SMEM>>>(bq, bk);
    k_mask64<<<dim3(KSEL / 128, KSEL / 128, NH), 256, MASK_SMEM>>>();
    k_maskcheck<<<32, 256>>>();

    // fallback path (guarded; normally no-ops)
    dim3 gg(DIM / BN, KSEL / BM);
    k_gemm<<<gg, 256>>>(pS, DIM, wv, DIM, bv, pV, DIM, KSEL, DIM, DIM, 0, 1);
    k_attn<<<dim3(KSEL / 64, NH), 256, ATTN_SMEM>>>();
    cudaStreamWaitEvent(0, evf, 0);
    k_gemm<<<gg, 256>>>(pAGG, DIM, wo, 2 * DIM, (const float*)nullptr,
                        pFUSED, DIM, KSEL, DIM, DIM, 1, 1);

    // final blend (always runs; waits for copy + fused (+ accum in fallback))
    cudaStreamWaitEvent(0, evcp, 0);
    k_blend<<<KSEL, 256>>>(out);
}

// round 15
// speedup vs baseline: 1.2796x; 1.0906x over previous
#include <cuda_runtime.h>
#include <cuda_bf16.h>
#include <math.h>
#include <stdint.h>

#define NROI 32768
#define DIM  1024
#define NH   8
#define HDIM 128
#define KSEL 2048
#define PCAP 32768

// ======================= PTX helpers (family-compatible) ====================
__device__ __forceinline__ uint32_t smem_u32(const void* p) {
    uint32_t a;
    asm("{ .reg .u64 t; cvta.to.shared.u64 t, %1; cvt.u32.u64 %0, t; }"
        : "=r"(a) : "l"(p));
    return a;
}
__device__ __forceinline__ void ldmatrix_x4(uint32_t* r, uint32_t addr) {
    asm volatile("ldmatrix.sync.aligned.m8n8.x4.shared.b16 {%0,%1,%2,%3}, [%4];"
        : "=r"(r[0]), "=r"(r[1]), "=r"(r[2]), "=r"(r[3]) : "r"(addr));
}
__device__ __forceinline__ void ldmatrix_x2(uint32_t* r, uint32_t addr) {
    asm volatile("ldmatrix.sync.aligned.m8n8.x2.shared.b16 {%0,%1}, [%2];"
        : "=r"(r[0]), "=r"(r[1]) : "r"(addr));
}
__device__ __forceinline__ void mma16816(float* d, const uint32_t* a,
                                         const uint32_t* b) {
    asm volatile(
        "mma.sync.aligned.m16n8k16.row.col.f32.bf16.bf16.f32 "
        "{%0,%1,%2,%3}, {%4,%5,%6,%7}, {%8,%9}, {%0,%1,%2,%3};"
        : "+f"(d[0]), "+f"(d[1]), "+f"(d[2]), "+f"(d[3])
        : "r"(a[0]), "r"(a[1]), "r"(a[2]), "r"(a[3]), "r"(b[0]), "r"(b[1]));
}
__device__ __forceinline__ void cp_async16(uint32_t smem_addr, const void* g) {
    asm volatile("cp.async.cg.shared.global [%0], [%1], 16;"
        :: "r"(smem_addr), "l"(g) : "memory");
}
#define CP_COMMIT() asm volatile("cp.async.commit_group;" ::: "memory")
#define CP_WAIT(n)  asm volatile("cp.async.wait_group %0;" :: "n"(n) : "memory")

// ======================= scratch device globals ==============================
__device__ unsigned int g_keys[NROI];
__device__ unsigned int g_hist[256];   // pass-0 histogram (zeroed by k_topk)
__device__ int          g_topk[KSEL];
__device__ int          g_eq[NROI];
__device__ int          g_anyvalid;
__device__ int          g_npairs;
__device__ int          g_pairs[PCAP];

__device__ float g_S[KSEL * DIM];
__device__ float g_Q[KSEL * DIM];
__device__ float g_K[KSEL * DIM];
__device__ float g_V[KSEL * DIM];
__device__ float g_AGG[KSEL * DIM];
__device__ float g_FUSED[KSEL * DIM];
__device__ float g_qn[NH * KSEL];   // |q| per head-row
__device__ float g_kn[NH * KSEL];
__device__ float g_pq[NH * KSEL];   // partial norm^2 of qn over first 64 dims
__device__ float g_pk[NH * KSEL];

__device__ __nv_bfloat16 g_Sh[KSEL * DIM];
__device__ __nv_bfloat16 g_Qb[KSEL * DIM];   // NORMALIZED qn (bf16)
__device__ __nv_bfloat16 g_Kb[KSEL * DIM];   // NORMALIZED kn (bf16)
__device__ __nv_bfloat16 g_Wqb[DIM * DIM];
__device__ __nv_bfloat16 g_Wkb[DIM * DIM];
__device__ __nv_bfloat16 g_Wo2h[DIM * DIM];

// ======================= scores + pass-0 hist (no copy) =====================
__global__ void k_score(const float* __restrict__ roi,
                        const float* __restrict__ w,
                        const float* __restrict__ b) {
    __shared__ unsigned int sh[256];
    sh[threadIdx.x] = 0;
    __syncthreads();
    int gw = (blockIdx.x * blockDim.x + threadIdx.x) >> 5;
    int lane = threadIdx.x & 31;
    const float4* r4 = (const float4*)(roi + (size_t)gw * DIM);
    const float4* w4 = (const float4*)w;
    float acc = 0.f;
#pragma unroll
    for (int i = 0; i < 8; i++) {
        float4 rv = r4[lane + i * 32];
        float4 wv = w4[lane + i * 32];
        acc += rv.x * wv.x + rv.y * wv.y + rv.z * wv.z + rv.w * wv.w;
    }
#pragma unroll
    for (int o = 16; o; o >>= 1) acc += __shfl_xor_sync(0xffffffffu, acc, o);
    if (lane == 0) {
        float s = acc + b[0];
        unsigned int kk = __float_as_uint(s);
        kk = (kk & 0x80000000u) ? ~kk : (kk | 0x80000000u);
        g_keys[gw] = kk;
        atomicAdd(&sh[kk >> 24], 1u);
    }
    __syncthreads();
    unsigned int c = sh[threadIdx.x];
    if (c) atomicAdd(&g_hist[threadIdx.x], c);
}

// ======================= flat copy roi -> out (overlaps GEMM phase) =========
__global__ void k_copy(const float4* __restrict__ roi, float4* __restrict__ out) {
    int i = blockIdx.x * blockDim.x + threadIdx.x;
    out[i] = roi[i];
    out[i + (NROI * DIM / 8)] = roi[i + (NROI * DIM / 8)];
}

// ======================= single-kernel exact top-K (register keys) ==========
__global__ void __launch_bounds__(1024) k_topk() {
    __shared__ unsigned int hist[256];
    __shared__ unsigned int sprefix;
    __shared__ int skrem, scnt_gt, scnt_eq;
    int t = threadIdx.x;
    unsigned int keys[32];
#pragma unroll
    for (int j = 0; j < 32; j++) keys[j] = g_keys[t + j * 1024];
    if (t < 256) { hist[t] = g_hist[t]; g_hist[t] = 0; }  // consume + re-zero
    if (t == 0) {
        skrem = KSEL; scnt_gt = 0; scnt_eq = 0;
        g_anyvalid = 0; g_npairs = 0;
    }
    __syncthreads();

    // pass 0: bucket select from the precomputed histogram
#pragma unroll
    for (int o = 1; o < 256; o <<= 1) {
        unsigned int v = 0;
        if (t < 256 && t + o < 256) v = hist[t + o];
        __syncthreads();
        if (t < 256) hist[t] += v;
        __syncthreads();
    }
    if (t < 256) {
        unsigned int St = hist[t];
        unsigned int Sn = (t < 255) ? hist[t + 1] : 0u;
        if (St >= KSEL && Sn < KSEL) {
            sprefix = (unsigned int)t;
            skrem = (int)(KSEL - Sn);
        }
    }
    __syncthreads();

    // passes 1..3: only keys matching the running prefix (few) hit atomics
    for (int pass = 1; pass < 4; pass++) {
        if (t < 256) hist[t] = 0;
        __syncthreads();
        unsigned int pref = sprefix;
        unsigned int krem = (unsigned int)skrem;
        int shift = 24 - 8 * pass;
#pragma unroll
        for (int j = 0; j < 32; j++) {
            unsigned int key = keys[j];
            if ((key >> (shift + 8)) == pref)
                atomicAdd(&hist[(key >> shift) & 0xFFu], 1u);
        }
        __syncthreads();
#pragma unroll
        for (int o = 1; o < 256; o <<= 1) {
            unsigned int v = 0;
            if (t < 256 && t + o < 256) v = hist[t + o];
            __syncthreads();
            if (t < 256) hist[t] += v;
            __syncthreads();
        }
        if (t < 256) {
            unsigned int St = hist[t];
            unsigned int Sn = (t < 255) ? hist[t + 1] : 0u;
            if (St >= krem && Sn < krem) {
                sprefix = (pref << 8) | (unsigned int)t;
                skrem = (int)(krem - Sn);
            }
        }
        __syncthreads();
    }

    unsigned int thresh = sprefix;
#pragma unroll
    for (int j = 0; j < 32; j++) {
        unsigned int key = keys[j];
        int i = t + j * 1024;
        if (key > thresh) { int p = atomicAdd(&scnt_gt, 1); g_topk[p] = i; }
        else if (key == thresh) { int e = atomicAdd(&scnt_eq, 1); g_eq[e] = i; }
    }
    __syncthreads();
    int n = scnt_eq, need = skrem, base = scnt_gt;
    for (int i = t; i < n; i += 1024) {
        int idx = g_eq[i];
        int rank = 0;
        for (int jj = 0; jj < n; jj++) rank += (g_eq[jj] < idx);
        if (rank < need) g_topk[base + rank] = idx;
    }
}

// ======================= gather (+ bf16 copy of S) ==========================
__global__ void k_gather(const float* __restrict__ roi) {
    int r = blockIdx.x;
    int idx = g_topk[r];
    float4 v = ((const float4*)(roi + (size_t)idx * DIM))[threadIdx.x];
    ((float4*)(g_S + (size_t)r * DIM))[threadIdx.x] = v;
    int base = r * DIM + threadIdx.x * 4;
    __nv_bfloat162 h01, h23;
    h01.x = __float2bfloat16(v.x); h01.y = __float2bfloat16(v.y);
    h23.x = __float2bfloat16(v.z); h23.y = __float2bfloat16(v.w);
    *(__nv_bfloat162*)(g_Sh + base) = h01;
    *(__nv_bfloat162*)(g_Sh + base + 2) = h23;
}

// ======================= fused weight conversions (vectorized) ==============
__device__ __forceinline__ uint4 pack8(const float* e) {
    __nv_bfloat162 p[4];
#pragma unroll
    for (int c = 0; c < 4; c++) {
        p[c].x = __float2bfloat16(e[2 * c]);
        p[c].y = __float2bfloat16(e[2 * c + 1]);
    }
    uint4 u;
    u.x = *(uint32_t*)&p[0]; u.y = *(uint32_t*)&p[1];
    u.z = *(uint32_t*)&p[2]; u.w = *(uint32_t*)&p[3];
    return u;
}

__global__ void k_cvt_all(const float* __restrict__ wq,
                          const float* __restrict__ wk,
                          const float* __restrict__ wo) {
    int i = 8 * (blockIdx.x * blockDim.x + threadIdx.x);
    int which = blockIdx.y;
    if (which == 0) {
        float e[8];
        *(float4*)&e[0] = *(const float4*)(wq + i);
        *(float4*)&e[4] = *(const float4*)(wq + i + 4);
        *(uint4*)(g_Wqb + i) = pack8(e);
    } else if (which == 1) {
        float e[8];
        *(float4*)&e[0] = *(const float4*)(wk + i);
        *(float4*)&e[4] = *(const float4*)(wk + i + 4);
        *(uint4*)(g_Wkb + i) = pack8(e);
    } else {
        int j = i >> 10, k = i & 1023;
        float e[8];
        *(float4*)&e[0] = *(const float4*)(wo + (size_t)j * 2 * DIM + DIM + k);
        *(float4*)&e[4] = *(const float4*)(wo + (size_t)j * 2 * DIM + DIM + k + 4);
        *(uint4*)(g_Wo2h + i) = pack8(e);
    }
}

// ======================= pipelined bf16 HMMA GEMM ===========================
#define LDSROW 72
#define ASTAGE (128 * LDSROW)
#define STAGEB (2 * ASTAGE)
#define PIPE_SMEM (2 * STAGEB * 2)
#define MASK_SMEM (STAGEB * 2)

__device__ __forceinline__ void warp_mma_block(
    uint32_t a_base, uint32_t b_base, int wr, int wc, int lane,
    float acc[4][4][4]) {
#pragma unroll
    for (int ks = 0; ks < 4; ks++) {
        uint32_t af[4][4], bf[4][2];
#pragma unroll
        for (int mi = 0; mi < 4; mi++) {
            uint32_t addr = a_base +
                ((wr * 64 + mi * 16 + (lane & 15)) * LDSROW + ks * 16 + (lane >> 4) * 8) * 2;
            ldmatrix_x4(af[mi], addr);
        }
#pragma unroll
        for (int ni = 0; ni < 4; ni++) {
            uint32_t addr = b_base +
                ((wc * 32 + ni * 8 + (lane & 7)) * LDSROW + ks * 16 + ((lane >> 3) & 1) * 8) * 2;
            ldmatrix_x2(bf[ni], addr);
        }
#pragma unroll
        for (int mi = 0; mi < 4; mi++)
#pragma unroll
            for (int ni = 0; ni < 4; ni++)
                mma16816(acc[mi][ni], af[mi], bf[ni]);
    }
}

__device__ __forceinline__ void issue_stage(
    const __nv_bfloat16* __restrict__ A, int lda,
    const __nv_bfloat16* __restrict__ B, int ldb,
    uint32_t smem_stage_addr, int tid) {
#pragma unroll
    for (int i = 0; i < 4; i++) {
        int idx = tid + i * 256;
        int row = idx >> 3;
        int cg = idx & 7;
        uint32_t off = (uint32_t)(row * LDSROW + cg * 8) * 2;
        cp_async16(smem_stage_addr + off, A + (size_t)row * lda + cg * 8);
        cp_async16(smem_stage_addr + ASTAGE * 2 + off, B + (size_t)row * ldb + cg * 8);
    }
    CP_COMMIT();
}

// ----- projections: z=0 Q, z=1 K (w/ norms + normalized bf16), z=2 FUSED ----
__global__ void __launch_bounds__(256, 2) k_gemm3(
    const float* __restrict__ bq, const float* __restrict__ bk,
    const float* __restrict__ bo)
{
    extern __shared__ __nv_bfloat16 smp[];
    __shared__ float snorm[128];
    __shared__ float snorm64[128];
    int tid = threadIdx.x, wid = tid >> 5, lane = tid & 31;
    int bm = blockIdx.y * 128, bn = blockIdx.x * 128;
    int z = blockIdx.z;
    int wr = wid & 1, wc = wid >> 1;
    uint32_t s_base = smem_u32(smp);

    const __nv_bfloat16* B = (z == 0) ? g_Wqb : (z == 1) ? g_Wkb : g_Wo2h;
    const float* bias = (z == 0) ? bq : (z == 1) ? bk : bo;
    float* C = (z == 0) ? g_Q : (z == 1) ? g_K : g_FUSED;
    __nv_bfloat16* Cb = (z == 0) ? g_Qb : (z == 1) ? g_Kb : nullptr;
    float* normOut = (z == 0) ? g_qn : (z == 1) ? g_kn : nullptr;
    float* pOut = (z == 0) ? g_pq : g_pk;

    float acc[4][4][4];
#pragma unroll
    for (int mi = 0; mi < 4; mi++)
#pragma unroll
        for (int ni = 0; ni < 4; ni++)
#pragma unroll
            for (int c = 0; c < 4; c++) acc[mi][ni][c] = 0.f;

    const int nch = DIM >> 6;

    issue_stage(g_Sh + (size_t)bm * DIM, DIM, B + (size_t)bn * DIM, DIM,
                s_base, tid);

    for (int ch = 0; ch < nch; ch++) {
        int st = ch & 1;
        if (ch + 1 < nch) {
            int kc = (ch + 1) << 6;
            issue_stage(g_Sh + (size_t)bm * DIM + kc, DIM,
                        B + (size_t)bn * DIM + kc, DIM,
                        s_base + (st ^ 1) * STAGEB * 2, tid);
            CP_WAIT(1);
        } else {
            CP_WAIT(0);
        }
        __syncthreads();
        uint32_t a_b = s_base + st * STAGEB * 2;
        warp_mma_block(a_b, a_b + ASTAGE * 2, wr, wc, lane, acc);
        __syncthreads();
    }

    if (normOut) {
        if (tid < 128) { snorm[tid] = 0.f; snorm64[tid] = 0.f; }
        __syncthreads();
    }

    // pass 1: fp32 store (+ norm accumulation for Q/K)
#pragma unroll
    for (int mi = 0; mi < 4; mi++) {
        int row0 = bm + wr * 64 + mi * 16 + (lane >> 2);
        float ns0 = 0.f, ns1 = 0.f;
#pragma unroll
        for (int ni = 0; ni < 4; ni++) {
            int col = bn + wc * 32 + ni * 8 + (lane & 3) * 2;
            float b0 = bias[col], b1 = bias[col + 1];
            float v00 = acc[mi][ni][0] + b0, v01 = acc[mi][ni][1] + b1;
            float v10 = acc[mi][ni][2] + b0, v11 = acc[mi][ni][3] + b1;
            *(float2*)(C + (size_t)row0 * DIM + col) = make_float2(v00, v01);
            *(float2*)(C + (size_t)(row0 + 8) * DIM + col) = make_float2(v10, v11);
            ns0 += v00 * v00 + v01 * v01;
            ns1 += v10 * v10 + v11 * v11;
        }
        if (normOut) {
            ns0 += __shfl_xor_sync(0xffffffffu, ns0, 1);
            ns0 += __shfl_xor_sync(0xffffffffu, ns0, 2);
            ns1 += __shfl_xor_sync(0xffffffffu, ns1, 1);
            ns1 += __shfl_xor_sync(0xffffffffu, ns1, 2);
            if ((lane & 3) == 0) {
                atomicAdd(&snorm[row0 - bm], ns0);
                atomicAdd(&snorm[row0 - bm + 8], ns1);
                if (wc < 2) {  // cols [bn, bn+64) = first 64 dims of this head
                    atomicAdd(&snorm64[row0 - bm], ns0);
                    atomicAdd(&snorm64[row0 - bm + 8], ns1);
                }
            }
        }
    }
    if (!normOut) return;
    __syncthreads();

    // pass 2 (Q/K only): normalized bf16 store
#pragma unroll
    for (int mi = 0; mi < 4; mi++) {
        int row0 = bm + wr * 64 + mi * 16 + (lane >> 2);
        float rinv0 = __fdividef(1.f, sqrtf(snorm[row0 - bm]) + 1e-6f);
        float rinv1 = __fdividef(1.f, sqrtf(snorm[row0 - bm + 8]) + 1e-6f);
#pragma unroll
        for (int ni = 0; ni < 4; ni++) {
            int col = bn + wc * 32 + ni * 8 + (lane & 3) * 2;
            float b0 = bias[col], b1 = bias[col + 1];
            float v00 = acc[mi][ni][0] + b0, v01 = acc[mi][ni][1] + b1;
            float v10 = acc[mi][ni][2] + b0, v11 = acc[mi][ni][3] + b1;
            __nv_bfloat162 h0, h1;
            h0.x = __float2bfloat16(v00 * rinv0); h0.y = __float2bfloat16(v01 * rinv0);
            h1.x = __float2bfloat16(v10 * rinv1); h1.y = __float2bfloat16(v11 * rinv1);
            *(__nv_bfloat162*)(Cb + (size_t)row0 * DIM + col) = h0;
            *(__nv_bfloat162*)(Cb + (size_t)(row0 + 8) * DIM + col) = h1;
        }
    }
    if (tid < 128) {
        float ns = snorm[tid];
        float nrm = sqrtf(ns);
        float rinv = __fdividef(1.f, nrm + 1e-6f);
        normOut[blockIdx.x * KSEL + bm + tid] = nrm;
        pOut[blockIdx.x * KSEL + bm + tid] = snorm64[tid] * rinv * rinv;
    }
}

// ======================= screened mask: K=64 partial-distance ===============
// partial64 = pq + pk - 2*c  (c = qn.kn over first 64 dims of the head).
// partial64 > 0.25  =>  |qn-kn|^2 > 0.2  =>  sim < 0.9  (rigorous rejection;
// 0.05 margin covers all bf16 error). Survivors -> exact fp32 check.
__global__ void __launch_bounds__(256) k_mask64() {
    extern __shared__ __nv_bfloat16 smp[];
    __shared__ float pkv[128];
    __shared__ float pqv[128];
    int tid = threadIdx.x, wid = tid >> 5, lane = tid & 31;
    int bn = blockIdx.x * 128, bm = blockIdx.y * 128, h = blockIdx.z;
    int wr = wid & 1, wc = wid >> 1;
    uint32_t s_base = smem_u32(smp);

#pragma unroll
    for (int i = 0; i < 4; i++) {
        int idx = tid + i * 256;
        int row = idx >> 3;
        int cg = idx & 7;
        uint32_t off = (uint32_t)(row * LDSROW + cg * 8) * 2;
        cp_async16(s_base + off,
                   g_Qb + (size_t)(bm + row) * DIM + h * HDIM + cg * 8);
        cp_async16(s_base + ASTAGE * 2 + off,
                   g_Kb + (size_t)(bn + row) * DIM + h * HDIM + cg * 8);
    }
    CP_COMMIT();

    if (tid < 128) {
        pqv[tid] = g_pq[h * KSEL + bm + tid];
        pkv[tid] = g_pk[h * KSEL + bn + tid];
    }

    float acc[4][4][4];
#pragma unroll
    for (int mi = 0; mi < 4; mi++)
#pragma unroll
        for (int ni = 0; ni < 4; ni++)
#pragma unroll
            for (int c = 0; c < 4; c++) acc[mi][ni][c] = 0.f;

    CP_WAIT(0);
    __syncthreads();
    warp_mma_block(s_base, s_base + ASTAGE * 2, wr, wc, lane, acc);  // K=64

#pragma unroll
    for (int mi = 0; mi < 4; mi++) {
        int r0l = wr * 64 + mi * 16 + (lane >> 2);
        int r1l = r0l + 8;
        float pq0 = pqv[r0l], pq1 = pqv[r1l];
#pragma unroll
        for (int ni = 0; ni < 4; ni++) {
            int cl = wc * 32 + ni * 8 + (lane & 3) * 2;
            float pk0 = pkv[cl], pk1 = pkv[cl + 1];
            int s00 = (pq0 + pk0 - 2.f * acc[mi][ni][0] <= 0.25f);
            int s01 = (pq0 + pk1 - 2.f * acc[mi][ni][1] <= 0.25f);
            int s10 = (pq1 + pk0 - 2.f * acc[mi][ni][2] <= 0.25f);
            int s11 = (pq1 + pk1 - 2.f * acc[mi][ni][3] <= 0.25f);
            if (__any_sync(0xffffffffu, s00 | s01 | s10 | s11)) {
                if (s00) { int p = atomicAdd(&g_npairs, 1);
                    if (p < PCAP) g_pairs[p] = (h << 22) | ((bm + r0l) << 11) | (bn + cl);
                    else g_anyvalid = 1; }
                if (s01) { int p = atomicAdd(&g_npairs, 1);
                    if (p < PCAP) g_pairs[p] = (h << 22) | ((bm + r0l) << 11) | (bn + cl + 1);
                    else g_anyvalid = 1; }
                if (s10) { int p = atomicAdd(&g_npairs, 1);
                    if (p < PCAP) g_pairs[p] = (h << 22) | ((bm + r1l) << 11) | (bn + cl);
                    else g_anyvalid = 1; }
                if (s11) { int p = atomicAdd(&g_npairs, 1);
                    if (p < PCAP) g_pairs[p] = (h << 22) | ((bm + r1l) << 11) | (bn + cl + 1);
                    else g_anyvalid = 1; }
            }
        }
    }
}

// exact fp32 check for survivor pairs
__global__ void k_maskcheck() {
    int np = g_npairs;
    if (np > PCAP) {
        if (blockIdx.x == 0 && threadIdx.x == 0) g_anyvalid = 1;
        np = PCAP;
    }
    int gw = (blockIdx.x * blockDim.x + threadIdx.x) >> 5;
    int lane = threadIdx.x & 31;
    int nw = (gridDim.x * blockDim.x) >> 5;
    for (int i = gw; i < np; i += nw) {
        int pk = g_pairs[i];
        int h = pk >> 22, qr = (pk >> 11) & 2047, kr = pk & 2047;
        const float4* q = (const float4*)(g_Q + (size_t)qr * DIM + h * HDIM);
        const float4* k = (const float4*)(g_K + (size_t)kr * DIM + h * HDIM);
        float4 qa = q[lane], ka = k[lane];
        float d = qa.x * ka.x + qa.y * ka.y + qa.z * ka.z + qa.w * ka.w;
#pragma unroll
        for (int o = 16; o; o >>= 1) d += __shfl_xor_sync(0xffffffffu, d, o);
        if (lane == 0) {
            float qn = g_qn[h * KSEL + qr] + 1e-6f;
            float kn = g_kn[h * KSEL + kr] + 1e-6f;
            if (d > 0.9f * qn * kn) atomicOr(&g_anyvalid, 1);
        }
    }
}

// ======================= fp32 SIMT GEMM (fallback only) =====================
#define BM 128
#define BN 128
#define BKK 16
#define SPAD 132
__global__ void __launch_bounds__(256) k_gemm(
    const float* __restrict__ A, int lda,
    const float* __restrict__ B, int ldb,
    const float* __restrict__ bias,
    float* __restrict__ C, int ldc,
    int M, int N, int Kd, int acc_flag, int chk)
{
    if (chk && g_anyvalid == 0) return;
    __shared__ float As[BKK * SPAD];
    __shared__ float Bs[BKK * SPAD];
    int tid = threadIdx.x;
    int bm = blockIdx.y * BM, bn = blockIdx.x * BN;
    int row0 = (tid >> 4) * 8, col0 = (tid & 15) * 8;
    float acc[8][8];
#pragma unroll
    for (int i = 0; i < 8; i++)
#pragma unroll
        for (int j = 0; j < 8; j++) acc[i][j] = 0.f;

    for (int k0 = 0; k0 < Kd; k0 += BKK) {
#pragma unroll
        for (int i = 0; i < 2; i++) {
            int f = tid + i * 256;
            int r = f >> 2;
            int kc = (f & 3) * 4;
            float4 av = *(const float4*)(A + (size_t)(bm + r) * lda + k0 + kc);
            As[(kc + 0) * SPAD + r] = av.x;
            As[(kc + 1) * SPAD + r] = av.y;
            As[(kc + 2) * SPAD + r] = av.z;
            As[(kc + 3) * SPAD + r] = av.w;
            float4 bv = *(const float4*)(B + (size_t)(bn + r) * ldb + k0 + kc);
            Bs[(kc + 0) * SPAD + r] = bv.x;
            Bs[(kc + 1) * SPAD + r] = bv.y;
            Bs[(kc + 2) * SPAD + r] = bv.z;
            Bs[(kc + 3) * SPAD + r] = bv.w;
        }
        __syncthreads();
#pragma unroll
        for (int k = 0; k < BKK; k++) {
            float a[8], b[8];
            *(float4*)&a[0] = *(const float4*)&As[k * SPAD + row0];
            *(float4*)&a[4] = *(const float4*)&As[k * SPAD + row0 + 4];
            *(float4*)&b[0] = *(const float4*)&Bs[k * SPAD + col0];
            *(float4*)&b[4] = *(const float4*)&Bs[k * SPAD + col0 + 4];
#pragma unroll
            for (int i = 0; i < 8; i++)
#pragma unroll
                for (int j = 0; j < 8; j++) acc[i][j] += a[i] * b[j];
        }
        __syncthreads();
    }
#pragma unroll
    for (int i = 0; i < 8; i++) {
        float* crow = C + (size_t)(bm + row0 + i) * ldc + bn + col0;
#pragma unroll
        for (int j = 0; j < 8; j++) {
            float v = acc[i][j];
            if (bias) v += bias[bn + col0 + j];
            if (acc_flag) v += crow[j];
            crow[j] = v;
        }
    }
}

// ======================= fp32 flash attention (fallback) ====================
#define AT_RS 68
#define AT_VS 132
#define ATTN_SMEM ((128 * AT_RS * 2 + 64 * AT_VS + 64 * AT_RS) * 4)

__global__ void __launch_bounds__(256) k_attn() {
    if (g_anyvalid == 0) return;
    extern __shared__ float smf[];
    float* QsT = smf;
    float* KsT = QsT + 128 * AT_RS;
    float* Vs  = KsT + 128 * AT_RS;
    float* Ps  = Vs + 64 * AT_VS;

    const int h = blockIdx.y;
    const int q0 = blockIdx.x * 64;
    const int tid = threadIdx.x;
    const int tx = tid & 15;
    const int ty = tid >> 4;
    const float scale = 0.088388347648318447f;

#pragma unroll
    for (int i = 0; i < 8; i++) {
        int f = tid + i * 256;
        int r = f >> 5;
        int dd = (f & 31) * 4;
        float4 v = *(const float4*)(g_Q + (size_t)(q0 + r) * DIM + h * HDIM + dd);
        QsT[(dd + 0) * AT_RS + r] = v.x;
        QsT[(dd + 1) * AT_RS + r] = v.y;
        QsT[(dd + 2) * AT_RS + r] = v.z;
        QsT[(dd + 3) * AT_RS + r] = v.w;
    }

    float qe[4];
#pragma unroll
    for (int i = 0; i < 4; i++)
        qe[i] = g_qn[h * KSEL + q0 + 4 * ty + i] + 1e-6f;

    float m[4], l[4], agg[4][8];
#pragma unroll
    for (int i = 0; i < 4; i++) {
        m[i] = -1e30f; l[i] = 0.f;
#pragma unroll
        for (int c = 0; c < 8; c++) agg[i][c] = 0.f;
    }

    for (int kt = 0; kt < KSEL / 64; kt++) {
        int k0 = kt * 64;
#pragma unroll
        for (int i = 0; i < 8; i++) {
            int f = tid + i * 256;
            int r = f >> 5;
            int dd = (f & 31) * 4;
            float4 v = *(const float4*)(g_K + (size_t)(k0 + r) * DIM + h * HDIM + dd);
            KsT[(dd + 0) * AT_RS + r] = v.x;
            KsT[(dd + 1) * AT_RS + r] = v.y;
            KsT[(dd + 2) * AT_RS + r] = v.z;
            KsT[(dd + 3) * AT_RS + r] = v.w;
            float4 vv = *(const float4*)(g_V + (size_t)(k0 + r) * DIM + h * HDIM + dd);
            *(float4*)&Vs[r * AT_VS + dd] = vv;
        }
        __syncthreads();

        float s[4][4];
#pragma unroll
        for (int i = 0; i < 4; i++)
#pragma unroll
            for (int j = 0; j < 4; j++) s[i][j] = 0.f;

#pragma unroll 4
        for (int dd = 0; dd < 128; dd++) {
            float4 qa = *(const float4*)&QsT[dd * AT_RS + 4 * ty];
            float4 kb = *(const float4*)&KsT[dd * AT_RS + 4 * tx];
            float a[4] = {qa.x, qa.y, qa.z, qa.w};
            float b[4] = {kb.x, kb.y, kb.z, kb.w};
#pragma unroll
            for (int i = 0; i < 4; i++)
#pragma unroll
                for (int j = 0; j < 4; j++) s[i][j] += a[i] * b[j];
        }

        float ke[4];
#pragma unroll
        for (int j = 0; j < 4; j++)
            ke[j] = g_kn[h * KSEL + k0 + 4 * tx + j] + 1e-6f;

        float w[4][4], tmax[4];
        int localany = 0;
#pragma unroll
        for (int i = 0; i < 4; i++) {
            float tm = -1e30f;
#pragma unroll
            for (int j = 0; j < 4; j++) {
                float sim = __fdividef(s[i][j], qe[i] * ke[j]);
                bool valid = sim > 0.9f;
                float lg = valid ? s[i][j] * scale : -1e30f;
                w[i][j] = lg;
                tm = fmaxf(tm, lg);
                localany |= (int)valid;
            }
#pragma unroll
            for (int o = 8; o; o >>= 1)
                tm = fmaxf(tm, __shfl_xor_sync(0xffffffffu, tm, o));
            tmax[i] = tm;
        }

        int anyv = __syncthreads_or(localany);
        if (anyv) {
#pragma unroll
            for (int i = 0; i < 4; i++) {
                float mn = fmaxf(m[i], tmax[i]);
                float f = __expf(m[i] - mn);
                float rs = 0.f;
#pragma unroll
                for (int j = 0; j < 4; j++) {
                    float e = (w[i][j] > -1e29f) ? __expf(w[i][j] - mn) : 0.f;
                    w[i][j] = e;
                    rs += e;
                }
#pragma unroll
                for (int o = 8; o; o >>= 1)
                    rs += __shfl_xor_sync(0xffffffffu, rs, o);
                l[i] = l[i] * f + rs;
                m[i] = mn;
#pragma unroll
                for (int c = 0; c < 8; c++) agg[i][c] *= f;
                *(float4*)&Ps[(4 * ty + i) * AT_RS + 4 * tx] =
                    make_float4(w[i][0], w[i][1], w[i][2], w[i][3]);
            }
            __syncthreads();
#pragma unroll 2
            for (int j = 0; j < 64; j++) {
                float4 v0 = *(const float4*)&Vs[j * AT_VS + 8 * tx];
                float4 v1 = *(const float4*)&Vs[j * AT_VS + 8 * tx + 4];
                float vv[8] = {v0.x, v0.y, v0.z, v0.w, v1.x, v1.y, v1.z, v1.w};
#pragma unroll
                for (int i = 0; i < 4; i++) {
                    float p = Ps[(4 * ty + i) * AT_RS + j];
#pragma unroll
                    for (int c = 0; c < 8; c++) agg[i][c] += p * vv[c];
                }
            }
        }
        __syncthreads();
    }

#pragma unroll
    for (int i = 0; i < 4; i++) {
        float inv = (l[i] > 0.f) ? __fdividef(1.f, l[i]) : 0.f;
        float4 o0, o1;
        o0.x = agg[i][0] * inv; o0.y = agg[i][1] * inv;
        o0.z = agg[i][2] * inv; o0.w = agg[i][3] * inv;
        o1.x = agg[i][4] * inv; o1.y = agg[i][5] * inv;
        o1.z = agg[i][6] * inv; o1.w = agg[i][7] * inv;
        float* dst = g_AGG + (size_t)(q0 + 4 * ty + i) * DIM + h * HDIM + 8 * tx;
        *(float4*)dst = o0;
        *(float4*)(dst + 4) = o1;
    }
}

// ======================= blend: out[topk[r]] = 0.5*(S + FUSED) ==============
__global__ void k_blend(float* __restrict__ out) {
    int r = blockIdx.x;
    int idx = g_topk[r];
    const float4* s = (const float4*)(g_S + (size_t)r * DIM);
    const float4* f = (const float4*)(g_FUSED + (size_t)r * DIM);
    float4 sv = s[threadIdx.x], fv = f[threadIdx.x];
    float4 o;
    o.x = 0.5f * (sv.x + fv.x);
    o.y = 0.5f * (sv.y + fv.y);
    o.z = 0.5f * (sv.z + fv.z);
    o.w = 0.5f * (sv.w + fv.w);
    ((float4*)(out + (size_t)idx * DIM))[threadIdx.x] = o;
}

// ======================= launch =============================================
extern "C" void kernel_launch(void* const* d_in, const int* in_sizes, int n_in,
                              void* d_out, int out_size) {
    const float* roi     = (const float*)d_in[0];
    const float* w_score = (const float*)d_in[1];
    const float* b_score = (const float*)d_in[2];
    const float* wq      = (const float*)d_in[3];
    const float* bq      = (const float*)d_in[4];
    const float* wk      = (const float*)d_in[5];
    const float* bk      = (const float*)d_in[6];
    const float* wv      = (const float*)d_in[7];
    const float* bv      = (const float*)d_in[8];
    const float* wo      = (const float*)d_in[9];
    const float* bo      = (const float*)d_in[10];
    float* out = (float*)d_out;

    float *pS, *pAGG, *pFUSED, *pV;
    cudaGetSymbolAddress((void**)&pS, g_S);
    cudaGetSymbolAddress((void**)&pAGG, g_AGG);
    cudaGetSymbolAddress((void**)&pFUSED, g_FUSED);
    cudaGetSymbolAddress((void**)&pV, g_V);

    // One-time setup: streams/events/attrs created on the FIRST call (the
    // correctness run, pre-capture) and cached. The capture call then makes
    // NO allocations — keeps the graph-teardown memory checkpoint clean.
    static cudaStream_t s1 = nullptr;
    static cudaEvent_t ev0, evc, evg, evcp;
    if (!s1) {
        cudaStreamCreateWithFlags(&s1, cudaStreamNonBlocking);
        cudaEventCreateWithFlags(&ev0, cudaEventDisableTiming);
        cudaEventCreateWithFlags(&evc, cudaEventDisableTiming);
        cudaEventCreateWithFlags(&evg, cudaEventDisableTiming);
        cudaEventCreateWithFlags(&evcp, cudaEventDisableTiming);
        cudaFuncSetAttribute(k_gemm3, cudaFuncAttributeMaxDynamicSharedMemorySize,
                             PIPE_SMEM);
        cudaFuncSetAttribute(k_mask64, cudaFuncAttributeMaxDynamicSharedMemorySize,
                             MASK_SMEM);
        cudaFuncSetAttribute(k_attn, cudaFuncAttributeMaxDynamicSharedMemorySize,
                             ATTN_SMEM);
    }

    // s1: weight cvt (overlaps score), then the bulk copy AFTER gather so it
    // runs inside the GEMM phase's idle HBM bandwidth.
    cudaEventRecord(ev0, 0);
    cudaStreamWaitEvent(s1, ev0, 0);
    k_cvt_all<<<dim3(DIM * DIM / 2048, 3), 256, 0, s1>>>(wq, wk, wo);
    cudaEventRecord(evc, s1);

    // s0: score (read-only pass) -> topk -> gather
    k_score<<<NROI / 8, 256>>>(roi, w_score, b_score);
    k_topk<<<1, 1024>>>();
    k_gather<<<KSEL, 256>>>(roi);
    cudaEventRecord(evg, 0);

    // s1: bulk roi->out copy, overlapping the GEMM phase
    cudaStreamWaitEvent(s1, evg, 0);
    k_copy<<<NROI * DIM / 8 / 256, 256, 0, s1>>>((const float4*)roi, (float4*)out);
    cudaEventRecord(evcp, s1);

    // s0: all three projections (Q, K, FUSED), screened mask, survivor check
    cudaStreamWaitEvent(0, evc, 0);
    k_gemm3<<<dim3(DIM / 128, KSEL / 128, 3), 256, PIPE_SMEM>>>(bq, bk, bo);
    k_mask64<<<dim3(KSEL / 128, KSEL / 128, NH), 256, MASK_SMEM>>>();
    k_maskcheck<<<32, 256>>>();

    // fallback path (guarded; normally no-ops)
    dim3 gg(DIM / BN, KSEL / BM);
    k_gemm<<<gg, 256>>>(pS, DIM, wv, DIM, bv, pV, DIM, KSEL, DIM, DIM, 0, 1);
    k_attn<<<dim3(KSEL / 64, NH), 256, ATTN_SMEM>>>();
    k_gemm<<<gg, 256>>>(pAGG, DIM, wo, 2 * DIM, (const float*)nullptr,
                        pFUSED, DIM, KSEL, DIM, DIM, 1, 1);

    // final blend (waits for the copy; fused/fallback ordered by s0)
    cudaStreamWaitEvent(0, evcp, 0);
    k_blend<<<KSEL, 256>>>(out);
}